// round 1
// baseline (speedup 1.0000x reference)
#include <cuda_runtime.h>
#include <math.h>
#include <stdint.h>

// ---------------- problem constants ----------------
#define BB    16
#define TT    256
#define MELN  1024
#define DD    512
#define HH    8
#define DHD   64
#define LLAY  4
#define INTERN 2048
#define OUTC  80

// ---------------- scratch (device globals; no allocation allowed) ----------
__device__ float g_x   [(size_t)BB*MELN*DD];         // activations (max S=MEL)
__device__ float g_qkv [(size_t)BB*MELN*3*DD];       // qkv
__device__ float g_ctx [(size_t)BB*MELN*DD];         // attn ctx / LN1 output (Y)
__device__ float g_t1  [(size_t)BB*MELN*DD];         // wo output / final proj
__device__ float g_h   [(size_t)BB*MELN*INTERN];     // conv1 intermediate
__device__ float g_h2  [(size_t)BB*MELN*DD];         // conv2 output
__device__ float g_scores[(size_t)BB*HH*MELN*MELN];  // attention scores
__device__ float g_enc [(size_t)BB*TT*DD];           // encoder output copy
__device__ float g_am  [BB*TT];
__device__ float g_am2 [BB*MELN];
__device__ int   g_cums[BB*TT];

// ---------------- embed + positional (note: reference adds pos[b], not pos[t]) ----
__global__ __launch_bounds__(256) void embed_kernel(const int* __restrict__ tokens,
                                                    const float* __restrict__ emb,
                                                    float* __restrict__ x)
{
    int i = blockIdx.x * 256 + threadIdx.x;
    if (i >= BB*TT*DD) return;
    int d  = i & (DD-1);
    int bt = i / DD;
    int b  = bt / TT;
    int tok = tokens[bt];
    int half = d >> 1;
    float den = __expf(-(float)(2*half) * (logf(10000.f) / (float)DD));
    float ang = (float)b * den;
    float posv = (d & 1) ? cosf(ang) : sinf(ang);
    x[i] = 2.f * emb[(size_t)tok*DD + d] + posv;
}

__global__ __launch_bounds__(256) void mask_kernel(const int* __restrict__ lens,
                                                   float* __restrict__ am, int S)
{
    int i = blockIdx.x*256 + threadIdx.x;
    if (i >= BB*S) return;
    int b = i / S, t = i % S;
    am[i] = (t > lens[b]) ? -INFINITY : 0.f;
}

// ---------------- generic tiled SGEMM with conv-shift + accumulate + relu ----
// C[M,N] = op( A_shifted[M,Kd] @ W[Kd,N] (+bias | +C) ), row r -> batch b=r/S, l=r%S,
// source row = l+shift (zero if out of [0,S)).
__global__ __launch_bounds__(256) void gemm_kernel(const float* __restrict__ A,
                                                   const float* __restrict__ W,
                                                   const float* __restrict__ bias,
                                                   float* __restrict__ C,
                                                   int M, int N, int Kd, int S,
                                                   int shift, int accumulate, int relu)
{
    __shared__ float As[16][65];
    __shared__ float Bs[16][64];
    int tx = threadIdx.x, ty = threadIdx.y;
    int tid = ty*16 + tx;
    int bm = blockIdx.y * 64, bn = blockIdx.x * 64;

    float acc[4][4];
#pragma unroll
    for (int i = 0; i < 4; i++)
#pragma unroll
        for (int j = 0; j < 4; j++) acc[i][j] = 0.f;

    for (int k0 = 0; k0 < Kd; k0 += 16) {
        // A tile: 64 rows x 16 k
#pragma unroll
        for (int i = 0; i < 4; i++) {
            int idx = tid + i*256;
            int m = idx >> 4, kk = idx & 15;
            int gm = bm + m;
            float v = 0.f;
            if (gm < M) {
                int b = gm / S, l = gm % S;
                int src = l + shift;
                if (src >= 0 && src < S)
                    v = A[(size_t)(b*S + src)*Kd + k0 + kk];
            }
            As[kk][m] = v;
        }
        // B tile: 16 k x 64 n
#pragma unroll
        for (int i = 0; i < 4; i++) {
            int idx = tid + i*256;
            int kk = idx >> 6, n = idx & 63;
            int gn = bn + n;
            float v = 0.f;
            if (gn < N) v = W[(size_t)(k0 + kk)*N + gn];
            Bs[kk][n] = v;
        }
        __syncthreads();
#pragma unroll
        for (int kk = 0; kk < 16; kk++) {
            float a[4], bf[4];
#pragma unroll
            for (int i = 0; i < 4; i++) a[i]  = As[kk][ty + 16*i];
#pragma unroll
            for (int j = 0; j < 4; j++) bf[j] = Bs[kk][tx + 16*j];
#pragma unroll
            for (int i = 0; i < 4; i++)
#pragma unroll
                for (int j = 0; j < 4; j++)
                    acc[i][j] += a[i] * bf[j];
        }
        __syncthreads();
    }
#pragma unroll
    for (int i = 0; i < 4; i++) {
        int gm = bm + ty + 16*i;
        if (gm >= M) continue;
#pragma unroll
        for (int j = 0; j < 4; j++) {
            int gn = bn + tx + 16*j;
            if (gn >= N) continue;
            float v = acc[i][j];
            size_t off = (size_t)gm*N + gn;
            if (accumulate) v += C[off];
            else if (bias)  v += bias[gn];
            if (relu) v = fmaxf(v, 0.f);
            C[off] = v;
        }
    }
}

// ---------------- attention: scores = Q K^T / 8 + am[b, k] ----------------
__global__ __launch_bounds__(256) void attn_scores_kernel(const float* __restrict__ qkv,
                                                          const float* __restrict__ am,
                                                          float* __restrict__ scores, int S)
{
    int bh = blockIdx.z;
    int b = bh / HH, h = bh % HH;
    int q0 = blockIdx.y * 32, k0 = blockIdx.x * 32;
    __shared__ float Qs[32][65], Ks[32][65];
    int tx = threadIdx.x, ty = threadIdx.y;
    int tid = ty*16 + tx;
    for (int i = tid; i < 32*64; i += 256) {
        int r = i >> 6, d = i & 63;
        Qs[r][d] = qkv[(size_t)(b*S + q0 + r)*(3*DD) + h*DHD + d];
        Ks[r][d] = qkv[(size_t)(b*S + k0 + r)*(3*DD) + DD + h*DHD + d];
    }
    __syncthreads();
    float acc[2][2] = {{0,0},{0,0}};
#pragma unroll 8
    for (int d = 0; d < 64; d++) {
        float a0 = Qs[ty][d],    a1 = Qs[ty+16][d];
        float b0 = Ks[tx][d],    b1 = Ks[tx+16][d];
        acc[0][0] += a0*b0; acc[0][1] += a0*b1;
        acc[1][0] += a1*b0; acc[1][1] += a1*b1;
    }
#pragma unroll
    for (int i = 0; i < 2; i++)
#pragma unroll
        for (int j = 0; j < 2; j++) {
            int q = q0 + ty + 16*i, k = k0 + tx + 16*j;
            scores[((size_t)bh*S + q)*S + k] = acc[i][j]*0.125f + am[b*S + k];
        }
}

__global__ __launch_bounds__(256) void softmax_kernel(float* __restrict__ scores, int S)
{
    size_t row = blockIdx.x;
    float* p = scores + row*S;
    __shared__ float red[256];
    int t = threadIdx.x;
    float m = -INFINITY;
    for (int i = t; i < S; i += 256) m = fmaxf(m, p[i]);
    red[t] = m; __syncthreads();
    for (int s = 128; s > 0; s >>= 1) { if (t < s) red[t] = fmaxf(red[t], red[t+s]); __syncthreads(); }
    m = red[0]; __syncthreads();
    float sum = 0.f;
    for (int i = t; i < S; i += 256) { float e = __expf(p[i] - m); p[i] = e; sum += e; }
    red[t] = sum; __syncthreads();
    for (int s = 128; s > 0; s >>= 1) { if (t < s) red[t] += red[t+s]; __syncthreads(); }
    float inv = 1.f / red[0];
    for (int i = t; i < S; i += 256) p[i] *= inv;
}

// ---------------- ctx = attn @ V, output layout (b, q, h*64+d) ----------------
__global__ __launch_bounds__(256) void attn_ctx_kernel(const float* __restrict__ scores,
                                                       const float* __restrict__ qkv,
                                                       float* __restrict__ ctx, int S)
{
    int bh = blockIdx.z;
    int b = bh / HH, h = bh % HH;
    int q0 = blockIdx.y * 32, d0 = blockIdx.x * 32;
    __shared__ float Ps[32][33], Vs[32][33];
    int tx = threadIdx.x, ty = threadIdx.y;
    int tid = ty*16 + tx;
    float acc[2][2] = {{0,0},{0,0}};
    for (int k0 = 0; k0 < S; k0 += 32) {
        for (int i = tid; i < 32*32; i += 256) {
            int r = i >> 5, c = i & 31;
            Ps[r][c] = scores[((size_t)bh*S + q0 + r)*S + k0 + c];
            Vs[r][c] = qkv[(size_t)(b*S + k0 + r)*(3*DD) + 2*DD + h*DHD + d0 + c];
        }
        __syncthreads();
#pragma unroll
        for (int kk = 0; kk < 32; kk++) {
            float a0 = Ps[ty][kk],    a1 = Ps[ty+16][kk];
            float b0 = Vs[kk][tx],    b1 = Vs[kk][tx+16];
            acc[0][0] += a0*b0; acc[0][1] += a0*b1;
            acc[1][0] += a1*b0; acc[1][1] += a1*b1;
        }
        __syncthreads();
    }
#pragma unroll
    for (int i = 0; i < 2; i++)
#pragma unroll
        for (int j = 0; j < 2; j++) {
            int q = q0 + ty + 16*i, d = d0 + tx + 16*j;
            ctx[(size_t)(b*S + q)*DD + h*DHD + d] = acc[i][j];
        }
}

// ---------------- out = LN(resid + delta) * g + b ----------------
__global__ __launch_bounds__(256) void add_ln_kernel(const float* __restrict__ resid,
                                                     const float* __restrict__ delta,
                                                     const float* __restrict__ g,
                                                     const float* __restrict__ bb,
                                                     float* __restrict__ out)
{
    size_t row = blockIdx.x;
    int t = threadIdx.x;
    __shared__ float red[256];
    float v0 = resid[row*DD + t]       + delta[row*DD + t];
    float v1 = resid[row*DD + t + 256] + delta[row*DD + t + 256];
    red[t] = v0 + v1; __syncthreads();
    for (int s = 128; s > 0; s >>= 1) { if (t < s) red[t] += red[t+s]; __syncthreads(); }
    float mean = red[0] * (1.f/DD);
    __syncthreads();
    float d0 = v0 - mean, d1 = v1 - mean;
    red[t] = d0*d0 + d1*d1; __syncthreads();
    for (int s = 128; s > 0; s >>= 1) { if (t < s) red[t] += red[t+s]; __syncthreads(); }
    float var = red[0] * (1.f/DD);
    float sc = rsqrtf(var + 1e-5f);
    out[row*DD + t]       = d0*sc*g[t]     + bb[t];
    out[row*DD + t + 256] = d1*sc*g[t+256] + bb[t+256];
}

// ---------------- length regulator ----------------
__global__ void cumsum_kernel(const int* __restrict__ dur, int* __restrict__ cums)
{
    int b = blockIdx.x;
    if (threadIdx.x == 0) {
        int s = 0;
        for (int t = 0; t < TT; t++) { s += dur[b*TT + t]; cums[b*TT + t] = s; }
    }
}

__global__ __launch_bounds__(256) void regulate_kernel(const float* __restrict__ enc,
                                                       const int* __restrict__ cums,
                                                       const int* __restrict__ mellen,
                                                       float* __restrict__ dec_in)
{
    int bf = blockIdx.x;
    int b = bf / MELN, f = bf % MELN;
    const int* c = cums + b*TT;
    int lo = 0, hi = TT;
    while (lo < hi) { int mid = (lo + hi) >> 1; if (c[mid] <= f) lo = mid + 1; else hi = mid; }
    int idx = lo; if (idx > TT-1) idx = TT-1;
    float keep = (f <= mellen[b]) ? 1.f : 0.f;
    for (int d = threadIdx.x; d < DD; d += 256)
        dec_in[(size_t)bf*DD + d] = enc[(size_t)(b*TT + idx)*DD + d] * keep;
}

// ---------------- final transpose (b, f, o) -> (b, o, f) ----------------
__global__ __launch_bounds__(256) void transpose_out_kernel(const float* __restrict__ t1,
                                                            float* __restrict__ out)
{
    int i = blockIdx.x*256 + threadIdx.x;
    if (i >= BB*OUTC*MELN) return;
    int f = i % MELN;
    int rest = i / MELN;
    int o = rest % OUTC;
    int b = rest / OUTC;
    out[i] = t1[(size_t)(b*MELN + f)*OUTC + o];
}

// =============================== host side ===============================
static inline dim3 gemm_grid(int M, int N) { return dim3((N + 63)/64, (M + 63)/64); }

struct Ptrs {
    float *x, *qkv, *ctx, *t1, *h, *h2, *scores, *enc, *am, *am2;
    int *cums;
};

static void get_ptrs(Ptrs& p)
{
    cudaGetSymbolAddress((void**)&p.x,      g_x);
    cudaGetSymbolAddress((void**)&p.qkv,    g_qkv);
    cudaGetSymbolAddress((void**)&p.ctx,    g_ctx);
    cudaGetSymbolAddress((void**)&p.t1,     g_t1);
    cudaGetSymbolAddress((void**)&p.h,      g_h);
    cudaGetSymbolAddress((void**)&p.h2,     g_h2);
    cudaGetSymbolAddress((void**)&p.scores, g_scores);
    cudaGetSymbolAddress((void**)&p.enc,    g_enc);
    cudaGetSymbolAddress((void**)&p.am,     g_am);
    cudaGetSymbolAddress((void**)&p.am2,    g_am2);
    cudaGetSymbolAddress((void**)&p.cums,   g_cums);
}

static void run_layer(Ptrs& p, int S, const float* am,
                      const float* wqkv, const float* bqkv,
                      const float* wo,   const float* bo,
                      const float* ln1g, const float* ln1b,
                      const float* c1w,  const float* c1b,
                      const float* c2w,  const float* c2b,
                      const float* ln2g, const float* ln2b)
{
    const int M = BB * S;
    dim3 blk(16,16);

    // qkv = x @ wqkv + bqkv
    gemm_kernel<<<gemm_grid(M, 3*DD), blk>>>(p.x, wqkv, bqkv, p.qkv, M, 3*DD, DD, M, 0, 0, 0);

    // attention
    attn_scores_kernel<<<dim3(S/32, S/32, BB*HH), blk>>>(p.qkv, am, p.scores, S);
    softmax_kernel<<<BB*HH*S, 256>>>(p.scores, S);
    attn_ctx_kernel<<<dim3(DHD/32, S/32, BB*HH), blk>>>(p.scores, p.qkv, p.ctx, S);

    // t1 = ctx @ wo + bo ; y = LN(x + t1)   (y stored in p.ctx)
    gemm_kernel<<<gemm_grid(M, DD), blk>>>(p.ctx, wo, bo, p.t1, M, DD, DD, M, 0, 0, 0);
    add_ln_kernel<<<M, 256>>>(p.x, p.t1, ln1g, ln1b, p.ctx);

    // conv1 (K=3, SAME) + relu -> h
    for (int k = 0; k < 3; k++)
        gemm_kernel<<<gemm_grid(M, INTERN), blk>>>(p.ctx, c1w + (size_t)k*DD*INTERN, c1b,
                                                   p.h, M, INTERN, DD, S, k-1, k > 0, k == 2);
    // conv2 -> h2
    for (int k = 0; k < 3; k++)
        gemm_kernel<<<gemm_grid(M, DD), blk>>>(p.h, c2w + (size_t)k*INTERN*DD, c2b,
                                               p.h2, M, DD, INTERN, S, k-1, k > 0, 0);
    // x = LN(y + h2)
    add_ln_kernel<<<M, 256>>>(p.ctx, p.h2, ln2g, ln2b, p.x);
}

extern "C" void kernel_launch(void* const* d_in, const int* in_sizes, int n_in,
                              void* d_out, int out_size)
{
    const int*   tokens        = (const int*)  d_in[0];
    const int*   token_lengths = (const int*)  d_in[1];
    const int*   melspec_len   = (const int*)  d_in[2];
    const int*   durations     = (const int*)  d_in[3];
    /* d_in[4] = mel_len (compile-time MELN) */
    const float* emb           = (const float*)d_in[5];
    const float* ew[12]; for (int i = 0; i < 12; i++) ew[i] = (const float*)d_in[6 + i];
    const float* dw[12]; for (int i = 0; i < 12; i++) dw[i] = (const float*)d_in[18 + i];
    const float* out_w         = (const float*)d_in[30];
    const float* out_b         = (const float*)d_in[31];

    Ptrs p; get_ptrs(p);
    dim3 blk(16,16);

    // ---- embed + positional + encoder mask ----
    embed_kernel<<<(BB*TT*DD + 255)/256, 256>>>(tokens, emb, p.x);
    mask_kernel<<<(BB*TT + 255)/256, 256>>>(token_lengths, p.am, TT);

    // ---- encoder stack (S = TT) ----
    for (int l = 0; l < LLAY; l++) {
        run_layer(p, TT, p.am,
                  ew[0] + (size_t)l*DD*3*DD,       ew[1] + (size_t)l*3*DD,
                  ew[2] + (size_t)l*DD*DD,         ew[3] + (size_t)l*DD,
                  ew[4] + (size_t)l*DD,            ew[5] + (size_t)l*DD,
                  ew[6] + (size_t)l*3*DD*INTERN,   ew[7] + (size_t)l*INTERN,
                  ew[8] + (size_t)l*3*INTERN*DD,   ew[9] + (size_t)l*DD,
                  ew[10] + (size_t)l*DD,           ew[11] + (size_t)l*DD);
    }

    // ---- length regulator ----
    cudaMemcpyAsync(p.enc, p.x, (size_t)BB*TT*DD*sizeof(float), cudaMemcpyDeviceToDevice);
    cumsum_kernel<<<BB, 32>>>(durations, p.cums);
    regulate_kernel<<<BB*MELN, 256>>>(p.enc, p.cums, melspec_len, p.x);
    mask_kernel<<<(BB*MELN + 255)/256, 256>>>(melspec_len, p.am2, MELN);

    // ---- decoder stack (S = MELN) ----
    for (int l = 0; l < LLAY; l++) {
        run_layer(p, MELN, p.am2,
                  dw[0] + (size_t)l*DD*3*DD,       dw[1] + (size_t)l*3*DD,
                  dw[2] + (size_t)l*DD*DD,         dw[3] + (size_t)l*DD,
                  dw[4] + (size_t)l*DD,            dw[5] + (size_t)l*DD,
                  dw[6] + (size_t)l*3*DD*INTERN,   dw[7] + (size_t)l*INTERN,
                  dw[8] + (size_t)l*3*INTERN*DD,   dw[9] + (size_t)l*DD,
                  dw[10] + (size_t)l*DD,           dw[11] + (size_t)l*DD);
    }

    // ---- output projection + transpose ----
    gemm_kernel<<<gemm_grid(BB*MELN, OUTC), blk>>>(p.x, out_w, out_b, p.t1,
                                                   BB*MELN, OUTC, DD, BB*MELN, 0, 0, 0);
    transpose_out_kernel<<<(BB*OUTC*MELN + 255)/256, 256>>>(p.t1, (float*)d_out);
}

// round 2
// speedup vs baseline: 2.7567x; 2.7567x over previous
#include <cuda_runtime.h>
#include <math.h>
#include <stdint.h>

// ---------------- problem constants ----------------
#define BB    16
#define TT    256
#define MELN  1024
#define DD    512
#define HH    8
#define DHD   64
#define LLAY  4
#define INTERN 2048
#define OUTC  80

// ---------------- scratch (device globals; no allocation allowed) ----------
__device__ float g_x   [(size_t)BB*MELN*DD];
__device__ float g_qkv [(size_t)BB*MELN*3*DD];
__device__ float g_ctx [(size_t)BB*MELN*DD];
__device__ float g_t1  [(size_t)BB*MELN*DD];
__device__ float g_h   [(size_t)BB*MELN*INTERN];
__device__ float g_h2  [(size_t)BB*MELN*DD];
__device__ float g_scores[(size_t)BB*HH*MELN*MELN];
__device__ float g_enc [(size_t)BB*TT*DD];
__device__ float g_am  [BB*TT];
__device__ float g_am2 [BB*MELN];
__device__ int   g_cums[BB*TT];

// ---------------- small helpers ----------------
__device__ __forceinline__ uint32_t f2tf32(float x) {
    uint32_t u;
    asm("cvt.rna.tf32.f32 %0, %1;" : "=r"(u) : "f"(x));
    return u;
}

// ======================= tensor-core tf32 GEMM =======================
// C[M,N] = op( A' @ W + bias ), where A'[m, k'] for conv mode maps
// k' -> (tap = k'/Kin, col = k'%Kin), source row = (m%S) + tap - 1 within batch.
// W is (Ktot, N) row-major (conv weights (3,Kin,N) are exactly this, contiguous).
// CTA tile 128x128, BK=16, 256 threads = 8 warps, warp tile 64x32 (grid 2m x 4n).
// mma.sync.m16n8k8 tf32, fp32 accumulate. Double-buffered smem.
//
// Smem layouts (per buffer, 2112 floats each):
//  A: packed float2 pairs: As[((c*4+slot)*132 + m)*2 + comp]
//     where k within tile = c*8 + p, slot=p%4, comp=p/4  (pair (k, k+4) -> float2)
//  B: plain Bs[kk*132 + n], kk in [0,16)
#define GT_BM 128
#define GT_BN 128
#define GT_BK 16
#define GT_PAD 132

__global__ __launch_bounds__(256) void gemm_tc(
    const float* __restrict__ A, const float* __restrict__ W,
    const float* __restrict__ bias, float* __restrict__ C,
    int M, int N, int Ktot, int Kin, int sLog, int conv, int relu)
{
    __shared__ float As[2][2112];
    __shared__ float Bs[2][2112];

    const int tid  = threadIdx.x;
    const int warp = tid >> 5, lane = tid & 31;
    const int gid  = lane >> 2, tid4 = lane & 3;
    const int wm   = warp & 1,  wn   = warp >> 1;     // 2 x 4 warp grid
    const int bm   = blockIdx.y * GT_BM;
    const int bn   = blockIdx.x * GT_BN;
    const int S    = 1 << sLog;
    const int nFull = (bn + GT_BN <= N);              // fast path: no n guards

    float acc[4][4][4];
#pragma unroll
    for (int i = 0; i < 4; i++)
#pragma unroll
        for (int j = 0; j < 4; j++)
#pragma unroll
            for (int r = 0; r < 4; r++) acc[i][j][r] = 0.f;

    const int nStages = Ktot / GT_BK;
    float4 aReg[2], bReg[2];

    // ---- stage loader (global -> regs) ----
    auto load_stage = [&](int stg) {
        const int k0   = stg * GT_BK;
        const int tap  = conv ? (k0 / Kin) : 0;
        const int kcol = k0 - tap * Kin;
        const int shift = conv ? (tap - 1) : 0;
#pragma unroll
        for (int i = 0; i < 2; i++) {
            int s = tid + i * 256;
            int m = s >> 2, kq = s & 3;
            int gm = bm + m;
            int b = gm >> sLog;
            int l = gm & (S - 1);
            int src = l + shift;
            float4 v = make_float4(0.f, 0.f, 0.f, 0.f);
            if (src >= 0 && src < S)
                v = *(const float4*)&A[((size_t)(((size_t)b << sLog) + src)) * Kin + kcol + kq * 4];
            aReg[i] = v;
        }
#pragma unroll
        for (int i = 0; i < 2; i++) {
            int s = tid + i * 256;
            int kk = s >> 5, n4 = s & 31;
            int gn = bn + n4 * 4;
            float4 v = make_float4(0.f, 0.f, 0.f, 0.f);
            if (nFull) {
                v = *(const float4*)&W[(size_t)(k0 + kk) * N + gn];
            } else {
                const float* wr = &W[(size_t)(k0 + kk) * N];
                if (gn + 0 < N) v.x = wr[gn + 0];
                if (gn + 1 < N) v.y = wr[gn + 1];
                if (gn + 2 < N) v.z = wr[gn + 2];
                if (gn + 3 < N) v.w = wr[gn + 3];
            }
            bReg[i] = v;
        }
    };

    // ---- stage writer (regs -> smem, with tf32 rounding) ----
    auto store_stage = [&](int buf) {
        float* a_s = As[buf];
        float* b_s = Bs[buf];
#pragma unroll
        for (int i = 0; i < 2; i++) {
            int s = tid + i * 256;
            int m = s >> 2, kq = s & 3;
            float va[4] = {aReg[i].x, aReg[i].y, aReg[i].z, aReg[i].w};
#pragma unroll
            for (int j = 0; j < 4; j++) {
                int k = kq * 4 + j;
                int c = k >> 3, p = k & 7;
                int slot = p & 3, comp = p >> 2;
                a_s[((c * 4 + slot) * GT_PAD + m) * 2 + comp] = __uint_as_float(f2tf32(va[j]));
            }
        }
#pragma unroll
        for (int i = 0; i < 2; i++) {
            int s = tid + i * 256;
            int kk = s >> 5, n4 = s & 31;
            float4 v = bReg[i];
            v.x = __uint_as_float(f2tf32(v.x));
            v.y = __uint_as_float(f2tf32(v.y));
            v.z = __uint_as_float(f2tf32(v.z));
            v.w = __uint_as_float(f2tf32(v.w));
            *(float4*)&b_s[kk * GT_PAD + n4 * 4] = v;
        }
    };

    // ---- compute one buffered tile ----
    auto compute = [&](int buf) {
        const float* a_s = As[buf];
        const float* b_s = Bs[buf];
#pragma unroll
        for (int c = 0; c < 2; c++) {
            uint32_t af[4][4];
#pragma unroll
            for (int mi = 0; mi < 4; mi++) {
                int mbase = wm * 64 + mi * 16;
                float2 lo = *(const float2*)&a_s[((c * 4 + tid4) * GT_PAD + mbase + gid) * 2];
                float2 hi = *(const float2*)&a_s[((c * 4 + tid4) * GT_PAD + mbase + gid + 8) * 2];
                af[mi][0] = __float_as_uint(lo.x);  // (gid,     tid4)
                af[mi][1] = __float_as_uint(hi.x);  // (gid+8,   tid4)
                af[mi][2] = __float_as_uint(lo.y);  // (gid,   tid4+4)
                af[mi][3] = __float_as_uint(hi.y);  // (gid+8, tid4+4)
            }
            uint32_t bf[4][2];
#pragma unroll
            for (int nj = 0; nj < 4; nj++) {
                int nn = wn * 32 + nj * 8 + gid;
                bf[nj][0] = __float_as_uint(b_s[(c * 8 + tid4) * GT_PAD + nn]);
                bf[nj][1] = __float_as_uint(b_s[(c * 8 + tid4 + 4) * GT_PAD + nn]);
            }
#pragma unroll
            for (int mi = 0; mi < 4; mi++)
#pragma unroll
                for (int nj = 0; nj < 4; nj++) {
                    asm volatile(
                        "mma.sync.aligned.m16n8k8.row.col.f32.tf32.tf32.f32 "
                        "{%0,%1,%2,%3},{%4,%5,%6,%7},{%8,%9},{%0,%1,%2,%3};"
                        : "+f"(acc[mi][nj][0]), "+f"(acc[mi][nj][1]),
                          "+f"(acc[mi][nj][2]), "+f"(acc[mi][nj][3])
                        : "r"(af[mi][0]), "r"(af[mi][1]), "r"(af[mi][2]), "r"(af[mi][3]),
                          "r"(bf[nj][0]), "r"(bf[nj][1]));
                }
        }
    };

    // ---- main loop: double-buffered ----
    load_stage(0);
    store_stage(0);
    __syncthreads();
    for (int s = 0; s < nStages; s++) {
        int buf = s & 1;
        if (s + 1 < nStages) load_stage(s + 1);
        compute(buf);
        if (s + 1 < nStages) {
            store_stage(buf ^ 1);
            __syncthreads();
        }
    }

    // ---- epilogue ----
#pragma unroll
    for (int mi = 0; mi < 4; mi++) {
        int gm0 = bm + wm * 64 + mi * 16 + gid;
#pragma unroll
        for (int nj = 0; nj < 4; nj++) {
            int gn = bn + wn * 32 + nj * 8 + tid4 * 2;
            float b0 = 0.f, b1 = 0.f;
            if (bias) {
                if (gn < N)     b0 = bias[gn];
                if (gn + 1 < N) b1 = bias[gn + 1];
            }
            float v00 = acc[mi][nj][0] + b0;
            float v01 = acc[mi][nj][1] + b1;
            float v10 = acc[mi][nj][2] + b0;
            float v11 = acc[mi][nj][3] + b1;
            if (relu) {
                v00 = fmaxf(v00, 0.f); v01 = fmaxf(v01, 0.f);
                v10 = fmaxf(v10, 0.f); v11 = fmaxf(v11, 0.f);
            }
            if (gn < N) {
                C[(size_t)gm0 * N + gn]       = v00;
                C[(size_t)(gm0 + 8) * N + gn] = v10;
            }
            if (gn + 1 < N) {
                C[(size_t)gm0 * N + gn + 1]       = v01;
                C[(size_t)(gm0 + 8) * N + gn + 1] = v11;
            }
        }
    }
}

// ---------------- embed + positional (reference adds pos[b], not pos[t]) ----
__global__ __launch_bounds__(256) void embed_kernel(const int* __restrict__ tokens,
                                                    const float* __restrict__ emb,
                                                    float* __restrict__ x)
{
    int i = blockIdx.x * 256 + threadIdx.x;
    if (i >= BB*TT*DD) return;
    int d  = i & (DD-1);
    int bt = i / DD;
    int b  = bt / TT;
    int tok = tokens[bt];
    int half = d >> 1;
    float den = __expf(-(float)(2*half) * (logf(10000.f) / (float)DD));
    float ang = (float)b * den;
    float posv = (d & 1) ? cosf(ang) : sinf(ang);
    x[i] = 2.f * emb[(size_t)tok*DD + d] + posv;
}

__global__ __launch_bounds__(256) void mask_kernel(const int* __restrict__ lens,
                                                   float* __restrict__ am, int S)
{
    int i = blockIdx.x*256 + threadIdx.x;
    if (i >= BB*S) return;
    int b = i / S, t = i % S;
    am[i] = (t > lens[b]) ? -INFINITY : 0.f;
}

// ---------------- attention: scores = Q K^T / 8 + am[b, k] ----------------
__global__ __launch_bounds__(256) void attn_scores_kernel(const float* __restrict__ qkv,
                                                          const float* __restrict__ am,
                                                          float* __restrict__ scores, int S)
{
    int bh = blockIdx.z;
    int b = bh / HH, h = bh % HH;
    int q0 = blockIdx.y * 32, k0 = blockIdx.x * 32;
    __shared__ float Qs[32][65], Ks[32][65];
    int tx = threadIdx.x, ty = threadIdx.y;
    int tid = ty*16 + tx;
    for (int i = tid; i < 32*64; i += 256) {
        int r = i >> 6, d = i & 63;
        Qs[r][d] = qkv[(size_t)(b*S + q0 + r)*(3*DD) + h*DHD + d];
        Ks[r][d] = qkv[(size_t)(b*S + k0 + r)*(3*DD) + DD + h*DHD + d];
    }
    __syncthreads();
    float acc[2][2] = {{0,0},{0,0}};
#pragma unroll 8
    for (int d = 0; d < 64; d++) {
        float a0 = Qs[ty][d],    a1 = Qs[ty+16][d];
        float b0 = Ks[tx][d],    b1 = Ks[tx+16][d];
        acc[0][0] += a0*b0; acc[0][1] += a0*b1;
        acc[1][0] += a1*b0; acc[1][1] += a1*b1;
    }
#pragma unroll
    for (int i = 0; i < 2; i++)
#pragma unroll
        for (int j = 0; j < 2; j++) {
            int q = q0 + ty + 16*i, k = k0 + tx + 16*j;
            scores[((size_t)bh*S + q)*S + k] = acc[i][j]*0.125f + am[b*S + k];
        }
}

__global__ __launch_bounds__(256) void softmax_kernel(float* __restrict__ scores, int S)
{
    size_t row = blockIdx.x;
    float* p = scores + row*S;
    __shared__ float red[256];
    int t = threadIdx.x;
    float m = -INFINITY;
    for (int i = t; i < S; i += 256) m = fmaxf(m, p[i]);
    red[t] = m; __syncthreads();
    for (int s = 128; s > 0; s >>= 1) { if (t < s) red[t] = fmaxf(red[t], red[t+s]); __syncthreads(); }
    m = red[0]; __syncthreads();
    float sum = 0.f;
    for (int i = t; i < S; i += 256) { float e = __expf(p[i] - m); p[i] = e; sum += e; }
    red[t] = sum; __syncthreads();
    for (int s = 128; s > 0; s >>= 1) { if (t < s) red[t] += red[t+s]; __syncthreads(); }
    float inv = 1.f / red[0];
    for (int i = t; i < S; i += 256) p[i] *= inv;
}

// ---------------- ctx = attn @ V, output layout (b, q, h*64+d) ----------------
__global__ __launch_bounds__(256) void attn_ctx_kernel(const float* __restrict__ scores,
                                                       const float* __restrict__ qkv,
                                                       float* __restrict__ ctx, int S)
{
    int bh = blockIdx.z;
    int b = bh / HH, h = bh % HH;
    int q0 = blockIdx.y * 32, d0 = blockIdx.x * 32;
    __shared__ float Ps[32][33], Vs[32][33];
    int tx = threadIdx.x, ty = threadIdx.y;
    int tid = ty*16 + tx;
    float acc[2][2] = {{0,0},{0,0}};
    for (int k0 = 0; k0 < S; k0 += 32) {
        for (int i = tid; i < 32*32; i += 256) {
            int r = i >> 5, c = i & 31;
            Ps[r][c] = scores[((size_t)bh*S + q0 + r)*S + k0 + c];
            Vs[r][c] = qkv[(size_t)(b*S + k0 + r)*(3*DD) + 2*DD + h*DHD + d0 + c];
        }
        __syncthreads();
#pragma unroll
        for (int kk = 0; kk < 32; kk++) {
            float a0 = Ps[ty][kk],    a1 = Ps[ty+16][kk];
            float b0 = Vs[kk][tx],    b1 = Vs[kk][tx+16];
            acc[0][0] += a0*b0; acc[0][1] += a0*b1;
            acc[1][0] += a1*b0; acc[1][1] += a1*b1;
        }
        __syncthreads();
    }
#pragma unroll
    for (int i = 0; i < 2; i++)
#pragma unroll
        for (int j = 0; j < 2; j++) {
            int q = q0 + ty + 16*i, d = d0 + tx + 16*j;
            ctx[(size_t)(b*S + q)*DD + h*DHD + d] = acc[i][j];
        }
}

// ---------------- out = LN(resid + delta) * g + b ----------------
__global__ __launch_bounds__(256) void add_ln_kernel(const float* __restrict__ resid,
                                                     const float* __restrict__ delta,
                                                     const float* __restrict__ g,
                                                     const float* __restrict__ bb,
                                                     float* __restrict__ out)
{
    size_t row = blockIdx.x;
    int t = threadIdx.x;
    __shared__ float red[256];
    float v0 = resid[row*DD + t]       + delta[row*DD + t];
    float v1 = resid[row*DD + t + 256] + delta[row*DD + t + 256];
    red[t] = v0 + v1; __syncthreads();
    for (int s = 128; s > 0; s >>= 1) { if (t < s) red[t] += red[t+s]; __syncthreads(); }
    float mean = red[0] * (1.f/DD);
    __syncthreads();
    float d0 = v0 - mean, d1 = v1 - mean;
    red[t] = d0*d0 + d1*d1; __syncthreads();
    for (int s = 128; s > 0; s >>= 1) { if (t < s) red[t] += red[t+s]; __syncthreads(); }
    float var = red[0] * (1.f/DD);
    float sc = rsqrtf(var + 1e-5f);
    out[row*DD + t]       = d0*sc*g[t]     + bb[t];
    out[row*DD + t + 256] = d1*sc*g[t+256] + bb[t+256];
}

// ---------------- length regulator ----------------
__global__ void cumsum_kernel(const int* __restrict__ dur, int* __restrict__ cums)
{
    int b = blockIdx.x;
    if (threadIdx.x == 0) {
        int s = 0;
        for (int t = 0; t < TT; t++) { s += dur[b*TT + t]; cums[b*TT + t] = s; }
    }
}

__global__ __launch_bounds__(256) void regulate_kernel(const float* __restrict__ enc,
                                                       const int* __restrict__ cums,
                                                       const int* __restrict__ mellen,
                                                       float* __restrict__ dec_in)
{
    int bf = blockIdx.x;
    int b = bf / MELN, f = bf % MELN;
    const int* c = cums + b*TT;
    int lo = 0, hi = TT;
    while (lo < hi) { int mid = (lo + hi) >> 1; if (c[mid] <= f) lo = mid + 1; else hi = mid; }
    int idx = lo; if (idx > TT-1) idx = TT-1;
    float keep = (f <= mellen[b]) ? 1.f : 0.f;
    for (int d = threadIdx.x; d < DD; d += 256)
        dec_in[(size_t)bf*DD + d] = enc[(size_t)(b*TT + idx)*DD + d] * keep;
}

// ---------------- final transpose (b, f, o) -> (b, o, f) ----------------
__global__ __launch_bounds__(256) void transpose_out_kernel(const float* __restrict__ t1,
                                                            float* __restrict__ out)
{
    int i = blockIdx.x*256 + threadIdx.x;
    if (i >= BB*OUTC*MELN) return;
    int f = i % MELN;
    int rest = i / MELN;
    int o = rest % OUTC;
    int b = rest / OUTC;
    out[i] = t1[(size_t)(b*MELN + f)*OUTC + o];
}

// =============================== host side ===============================
struct Ptrs {
    float *x, *qkv, *ctx, *t1, *h, *h2, *scores, *enc, *am, *am2;
    int *cums;
};

static void get_ptrs(Ptrs& p)
{
    cudaGetSymbolAddress((void**)&p.x,      g_x);
    cudaGetSymbolAddress((void**)&p.qkv,    g_qkv);
    cudaGetSymbolAddress((void**)&p.ctx,    g_ctx);
    cudaGetSymbolAddress((void**)&p.t1,     g_t1);
    cudaGetSymbolAddress((void**)&p.h,      g_h);
    cudaGetSymbolAddress((void**)&p.h2,     g_h2);
    cudaGetSymbolAddress((void**)&p.scores, g_scores);
    cudaGetSymbolAddress((void**)&p.enc,    g_enc);
    cudaGetSymbolAddress((void**)&p.am,     g_am);
    cudaGetSymbolAddress((void**)&p.am2,    g_am2);
    cudaGetSymbolAddress((void**)&p.cums,   g_cums);
}

static inline dim3 tc_grid(int M, int N) { return dim3((N + 127)/128, M/128); }

static void run_layer(Ptrs& p, int S, int sLog, const float* am,
                      const float* wqkv, const float* bqkv,
                      const float* wo,   const float* bo,
                      const float* ln1g, const float* ln1b,
                      const float* c1w,  const float* c1b,
                      const float* c2w,  const float* c2b,
                      const float* ln2g, const float* ln2b)
{
    const int M = BB * S;
    dim3 blk(16,16);

    // qkv = x @ wqkv + bqkv
    gemm_tc<<<tc_grid(M, 3*DD), 256>>>(p.x, wqkv, bqkv, p.qkv, M, 3*DD, DD, DD, sLog, 0, 0);

    // attention
    attn_scores_kernel<<<dim3(S/32, S/32, BB*HH), blk>>>(p.qkv, am, p.scores, S);
    softmax_kernel<<<BB*HH*S, 256>>>(p.scores, S);
    attn_ctx_kernel<<<dim3(DHD/32, S/32, BB*HH), blk>>>(p.scores, p.qkv, p.ctx, S);

    // t1 = ctx @ wo + bo ; y = LN(x + t1)   (y stored in p.ctx)
    gemm_tc<<<tc_grid(M, DD), 256>>>(p.ctx, wo, bo, p.t1, M, DD, DD, DD, sLog, 0, 0);
    add_ln_kernel<<<M, 256>>>(p.x, p.t1, ln1g, ln1b, p.ctx);

    // conv1 (K=3, SAME) + relu -> h : one fused GEMM, K' = 3*D
    gemm_tc<<<tc_grid(M, INTERN), 256>>>(p.ctx, c1w, c1b, p.h, M, INTERN, 3*DD, DD, sLog, 1, 1);
    // conv2 -> h2 : K' = 3*INTER
    gemm_tc<<<tc_grid(M, DD), 256>>>(p.h, c2w, c2b, p.h2, M, DD, 3*INTERN, INTERN, sLog, 1, 0);

    // x = LN(y + h2)
    add_ln_kernel<<<M, 256>>>(p.ctx, p.h2, ln2g, ln2b, p.x);
}

extern "C" void kernel_launch(void* const* d_in, const int* in_sizes, int n_in,
                              void* d_out, int out_size)
{
    const int*   tokens        = (const int*)  d_in[0];
    const int*   token_lengths = (const int*)  d_in[1];
    const int*   melspec_len   = (const int*)  d_in[2];
    const int*   durations     = (const int*)  d_in[3];
    /* d_in[4] = mel_len (compile-time MELN) */
    const float* emb           = (const float*)d_in[5];
    const float* ew[12]; for (int i = 0; i < 12; i++) ew[i] = (const float*)d_in[6 + i];
    const float* dw[12]; for (int i = 0; i < 12; i++) dw[i] = (const float*)d_in[18 + i];
    const float* out_w         = (const float*)d_in[30];
    const float* out_b         = (const float*)d_in[31];

    Ptrs p; get_ptrs(p);

    // ---- embed + positional + encoder mask ----
    embed_kernel<<<(BB*TT*DD + 255)/256, 256>>>(tokens, emb, p.x);
    mask_kernel<<<(BB*TT + 255)/256, 256>>>(token_lengths, p.am, TT);

    // ---- encoder stack (S = TT) ----
    for (int l = 0; l < LLAY; l++) {
        run_layer(p, TT, 8, p.am,
                  ew[0] + (size_t)l*DD*3*DD,       ew[1] + (size_t)l*3*DD,
                  ew[2] + (size_t)l*DD*DD,         ew[3] + (size_t)l*DD,
                  ew[4] + (size_t)l*DD,            ew[5] + (size_t)l*DD,
                  ew[6] + (size_t)l*3*DD*INTERN,   ew[7] + (size_t)l*INTERN,
                  ew[8] + (size_t)l*3*INTERN*DD,   ew[9] + (size_t)l*DD,
                  ew[10] + (size_t)l*DD,           ew[11] + (size_t)l*DD);
    }

    // ---- length regulator ----
    cudaMemcpyAsync(p.enc, p.x, (size_t)BB*TT*DD*sizeof(float), cudaMemcpyDeviceToDevice);
    cumsum_kernel<<<BB, 32>>>(durations, p.cums);
    regulate_kernel<<<BB*MELN, 256>>>(p.enc, p.cums, melspec_len, p.x);
    mask_kernel<<<(BB*MELN + 255)/256, 256>>>(melspec_len, p.am2, MELN);

    // ---- decoder stack (S = MELN) ----
    for (int l = 0; l < LLAY; l++) {
        run_layer(p, MELN, 10, p.am2,
                  dw[0] + (size_t)l*DD*3*DD,       dw[1] + (size_t)l*3*DD,
                  dw[2] + (size_t)l*DD*DD,         dw[3] + (size_t)l*DD,
                  dw[4] + (size_t)l*DD,            dw[5] + (size_t)l*DD,
                  dw[6] + (size_t)l*3*DD*INTERN,   dw[7] + (size_t)l*INTERN,
                  dw[8] + (size_t)l*3*INTERN*DD,   dw[9] + (size_t)l*DD,
                  dw[10] + (size_t)l*DD,           dw[11] + (size_t)l*DD);
    }

    // ---- output projection + transpose ----
    gemm_tc<<<tc_grid(BB*MELN, OUTC), 256>>>(p.x, out_w, out_b, p.t1,
                                             BB*MELN, OUTC, DD, DD, 10, 0, 0);
    transpose_out_kernel<<<(BB*OUTC*MELN + 255)/256, 256>>>(p.t1, (float*)d_out);
}

// round 4
// speedup vs baseline: 2.8952x; 1.0502x over previous
#include <cuda_runtime.h>
#include <math.h>
#include <stdint.h>

// ---------------- problem constants ----------------
#define BB    16
#define TT    256
#define MELN  1024
#define DD    512
#define HH    8
#define DHD   64
#define LLAY  4
#define INTERN 2048
#define OUTC  80

// ---------------- scratch (device globals; no allocation allowed) ----------
__device__ float g_x   [(size_t)BB*MELN*DD];
__device__ float g_qkv [(size_t)BB*MELN*3*DD];
__device__ float g_ctx [(size_t)BB*MELN*DD];
__device__ float g_t1  [(size_t)BB*MELN*DD];
__device__ float g_h   [(size_t)BB*MELN*INTERN];
__device__ float g_h2  [(size_t)BB*MELN*DD];
__device__ float g_enc [(size_t)BB*TT*DD];
__device__ float g_am  [BB*TT];
__device__ float g_am2 [BB*MELN];
__device__ int   g_cums[BB*TT];

// ---------------- small helpers ----------------
__device__ __forceinline__ uint32_t f2tf32(float x) {
    uint32_t u;
    asm("cvt.rna.tf32.f32 %0, %1;" : "=r"(u) : "f"(x));
    return u;
}
__device__ __forceinline__ float tf32f(float x) { return __uint_as_float(f2tf32(x)); }

#define MMA_TF32(acc, a0,a1,a2,a3, b0,b1)                                     \
    asm volatile("mma.sync.aligned.m16n8k8.row.col.f32.tf32.tf32.f32 "        \
                 "{%0,%1,%2,%3},{%4,%5,%6,%7},{%8,%9},{%0,%1,%2,%3};"         \
                 : "+f"(acc[0]), "+f"(acc[1]), "+f"(acc[2]), "+f"(acc[3])     \
                 : "r"(a0), "r"(a1), "r"(a2), "r"(a3), "r"(b0), "r"(b1))

// ======================= tensor-core tf32 GEMM =======================
#define GT_PAD 132

__global__ __launch_bounds__(256) void gemm_tc(
    const float* __restrict__ A, const float* __restrict__ W,
    const float* __restrict__ bias, float* __restrict__ C,
    int M, int N, int Ktot, int Kin, int sLog, int conv, int relu)
{
    __shared__ float As[2][2112];
    __shared__ float Bs[2][2112];

    const int tid  = threadIdx.x;
    const int warp = tid >> 5, lane = tid & 31;
    const int gid  = lane >> 2, tid4 = lane & 3;
    const int wm   = warp & 1,  wn   = warp >> 1;
    const int bm   = blockIdx.y * 128;
    const int bn   = blockIdx.x * 128;
    const int S    = 1 << sLog;
    const int nFull = (bn + 128 <= N);

    float acc[4][4][4];
#pragma unroll
    for (int i = 0; i < 4; i++)
#pragma unroll
        for (int j = 0; j < 4; j++)
#pragma unroll
            for (int r = 0; r < 4; r++) acc[i][j][r] = 0.f;

    const int nStages = Ktot / 16;
    float4 aReg[2], bReg[2];

    auto load_stage = [&](int stg) {
        const int k0   = stg * 16;
        const int tap  = conv ? (k0 / Kin) : 0;
        const int kcol = k0 - tap * Kin;
        const int shift = conv ? (tap - 1) : 0;
#pragma unroll
        for (int i = 0; i < 2; i++) {
            int s = tid + i * 256;
            int m = s >> 2, kq = s & 3;
            int gm = bm + m;
            int b = gm >> sLog;
            int l = gm & (S - 1);
            int src = l + shift;
            float4 v = make_float4(0.f, 0.f, 0.f, 0.f);
            if (src >= 0 && src < S)
                v = *(const float4*)&A[((size_t)(((size_t)b << sLog) + src)) * Kin + kcol + kq * 4];
            aReg[i] = v;
        }
#pragma unroll
        for (int i = 0; i < 2; i++) {
            int s = tid + i * 256;
            int kk = s >> 5, n4 = s & 31;
            int gn = bn + n4 * 4;
            float4 v = make_float4(0.f, 0.f, 0.f, 0.f);
            if (nFull) {
                v = *(const float4*)&W[(size_t)(k0 + kk) * N + gn];
            } else {
                const float* wr = &W[(size_t)(k0 + kk) * N];
                if (gn + 0 < N) v.x = wr[gn + 0];
                if (gn + 1 < N) v.y = wr[gn + 1];
                if (gn + 2 < N) v.z = wr[gn + 2];
                if (gn + 3 < N) v.w = wr[gn + 3];
            }
            bReg[i] = v;
        }
    };

    auto store_stage = [&](int buf) {
        float* a_s = As[buf];
        float* b_s = Bs[buf];
#pragma unroll
        for (int i = 0; i < 2; i++) {
            int s = tid + i * 256;
            int m = s >> 2, kq = s & 3;
            float va[4] = {aReg[i].x, aReg[i].y, aReg[i].z, aReg[i].w};
#pragma unroll
            for (int j = 0; j < 4; j++) {
                int k = kq * 4 + j;
                int c = k >> 3, p = k & 7;
                int slot = p & 3, comp = p >> 2;
                a_s[((c * 4 + slot) * GT_PAD + m) * 2 + comp] = tf32f(va[j]);
            }
        }
#pragma unroll
        for (int i = 0; i < 2; i++) {
            int s = tid + i * 256;
            int kk = s >> 5, n4 = s & 31;
            float4 v = bReg[i];
            v.x = tf32f(v.x); v.y = tf32f(v.y); v.z = tf32f(v.z); v.w = tf32f(v.w);
            *(float4*)&b_s[kk * GT_PAD + n4 * 4] = v;
        }
    };

    auto compute = [&](int buf) {
        const float* a_s = As[buf];
        const float* b_s = Bs[buf];
#pragma unroll
        for (int c = 0; c < 2; c++) {
            uint32_t af[4][4];
#pragma unroll
            for (int mi = 0; mi < 4; mi++) {
                int mbase = wm * 64 + mi * 16;
                float2 lo = *(const float2*)&a_s[((c * 4 + tid4) * GT_PAD + mbase + gid) * 2];
                float2 hi = *(const float2*)&a_s[((c * 4 + tid4) * GT_PAD + mbase + gid + 8) * 2];
                af[mi][0] = __float_as_uint(lo.x);
                af[mi][1] = __float_as_uint(hi.x);
                af[mi][2] = __float_as_uint(lo.y);
                af[mi][3] = __float_as_uint(hi.y);
            }
            uint32_t bf[4][2];
#pragma unroll
            for (int nj = 0; nj < 4; nj++) {
                int nn = wn * 32 + nj * 8 + gid;
                bf[nj][0] = __float_as_uint(b_s[(c * 8 + tid4) * GT_PAD + nn]);
                bf[nj][1] = __float_as_uint(b_s[(c * 8 + tid4 + 4) * GT_PAD + nn]);
            }
#pragma unroll
            for (int mi = 0; mi < 4; mi++)
#pragma unroll
                for (int nj = 0; nj < 4; nj++)
                    MMA_TF32(acc[mi][nj], af[mi][0], af[mi][1], af[mi][2], af[mi][3],
                             bf[nj][0], bf[nj][1]);
        }
    };

    load_stage(0);
    store_stage(0);
    __syncthreads();
    for (int s = 0; s < nStages; s++) {
        int buf = s & 1;
        if (s + 1 < nStages) load_stage(s + 1);
        compute(buf);
        if (s + 1 < nStages) {
            store_stage(buf ^ 1);
            __syncthreads();
        }
    }

#pragma unroll
    for (int mi = 0; mi < 4; mi++) {
        int gm0 = bm + wm * 64 + mi * 16 + gid;
#pragma unroll
        for (int nj = 0; nj < 4; nj++) {
            int gn = bn + wn * 32 + nj * 8 + tid4 * 2;
            float b0 = 0.f, b1 = 0.f;
            if (bias) {
                if (gn < N)     b0 = bias[gn];
                if (gn + 1 < N) b1 = bias[gn + 1];
            }
            float v00 = acc[mi][nj][0] + b0;
            float v01 = acc[mi][nj][1] + b1;
            float v10 = acc[mi][nj][2] + b0;
            float v11 = acc[mi][nj][3] + b1;
            if (relu) {
                v00 = fmaxf(v00, 0.f); v01 = fmaxf(v01, 0.f);
                v10 = fmaxf(v10, 0.f); v11 = fmaxf(v11, 0.f);
            }
            if (gn < N) {
                C[(size_t)gm0 * N + gn]       = v00;
                C[(size_t)(gm0 + 8) * N + gn] = v10;
            }
            if (gn + 1 < N) {
                C[(size_t)gm0 * N + gn + 1]       = v01;
                C[(size_t)(gm0 + 8) * N + gn + 1] = v11;
            }
        }
    }
}

// ======================= fused flash attention (tf32 tensor cores) =========
// Grid: (S/128, BB*HH). Block 256 = 8 warps (4m x 2n), q-tile 128, k-tile 64.
// All smem tiles row-major with stride 68 -> fragment LDS bank-conflict-free.
#define FA_PAD 68
#define FA_SMEM_FLOATS (128*FA_PAD + 64*FA_PAD + 64*FA_PAD + 128*FA_PAD + 3*128)

__global__ __launch_bounds__(256) void flash_attn(const float* __restrict__ qkv,
                                                  const float* __restrict__ am,
                                                  float* __restrict__ ctx, int S)
{
    extern __shared__ float sm[];
    float* Qs   = sm;                    // 128 x 68
    float* Ks   = Qs + 128*FA_PAD;       // 64 x 68
    float* Vs   = Ks + 64*FA_PAD;        // 64 x 68
    float* Ss   = Vs + 64*FA_PAD;        // 128 x 68 (scores, then P in tf32)
    float* mrow = Ss + 128*FA_PAD;       // 128
    float* lrow = mrow + 128;            // 128
    float* arow = lrow + 128;            // 128

    const int tid  = threadIdx.x;
    const int warp = tid >> 5, lane = tid & 31;
    const int gid  = lane >> 2, tid4 = lane & 3;
    const int wm   = warp & 3, wn = warp >> 2;    // 4 x 2 warp grid
    const int bh   = blockIdx.y;
    const int b    = bh >> 3, h = bh & 7;
    const int q0   = blockIdx.x * 128;
    const float* amb = am + b * S;
    const float* qb  = qkv + (size_t)(b * S) * 1536 + h * 64;

    // ---- load Q tile (tf32) ----
#pragma unroll
    for (int i = 0; i < 8; i++) {
        int idx = tid + i * 256;
        int r = idx >> 4, c4 = idx & 15;
        float4 v = *(const float4*)&qb[(size_t)(q0 + r) * 1536 + c4 * 4];
        float* dst = &Qs[r * FA_PAD + c4 * 4];
        dst[0] = tf32f(v.x); dst[1] = tf32f(v.y); dst[2] = tf32f(v.z); dst[3] = tf32f(v.w);
    }
    if (tid < 128) { mrow[tid] = -INFINITY; lrow[tid] = 0.f; }

    float oacc[2][4][4];
#pragma unroll
    for (int mi = 0; mi < 2; mi++)
#pragma unroll
        for (int nj = 0; nj < 4; nj++)
#pragma unroll
            for (int r = 0; r < 4; r++) oacc[mi][nj][r] = 0.f;

    const int nkt = S >> 6;
    for (int kt = 0; kt < nkt; kt++) {
        const int k0 = kt * 64;
        __syncthreads();   // prev tile fully consumed

        // ---- load K, V tiles (tf32, row-major) ----
#pragma unroll
        for (int i = 0; i < 4; i++) {
            int idx = tid + i * 256;
            int r = idx >> 4, c4 = idx & 15;
            const float* src = &qb[(size_t)(k0 + r) * 1536];
            float4 kv = *(const float4*)&src[512 + c4 * 4];
            float4 vv = *(const float4*)&src[1024 + c4 * 4];
            float* kd = &Ks[r * FA_PAD + c4 * 4];
            float* vd = &Vs[r * FA_PAD + c4 * 4];
            kd[0] = tf32f(kv.x); kd[1] = tf32f(kv.y); kd[2] = tf32f(kv.z); kd[3] = tf32f(kv.w);
            vd[0] = tf32f(vv.x); vd[1] = tf32f(vv.y); vd[2] = tf32f(vv.z); vd[3] = tf32f(vv.w);
        }
        __syncthreads();

        // ---- S = Q @ K^T ----
        float sacc[2][4][4];
#pragma unroll
        for (int mi = 0; mi < 2; mi++)
#pragma unroll
            for (int nj = 0; nj < 4; nj++)
#pragma unroll
                for (int r = 0; r < 4; r++) sacc[mi][nj][r] = 0.f;

#pragma unroll
        for (int kc = 0; kc < 8; kc++) {
            uint32_t af[2][4];
#pragma unroll
            for (int mi = 0; mi < 2; mi++) {
                const float* ap = &Qs[(wm * 32 + mi * 16 + gid) * FA_PAD + kc * 8 + tid4];
                af[mi][0] = __float_as_uint(ap[0]);
                af[mi][1] = __float_as_uint(ap[8 * FA_PAD]);
                af[mi][2] = __float_as_uint(ap[4]);
                af[mi][3] = __float_as_uint(ap[8 * FA_PAD + 4]);
            }
            uint32_t bf[4][2];
#pragma unroll
            for (int nj = 0; nj < 4; nj++) {
                const float* bp = &Ks[(wn * 32 + nj * 8 + gid) * FA_PAD + kc * 8 + tid4];
                bf[nj][0] = __float_as_uint(bp[0]);
                bf[nj][1] = __float_as_uint(bp[4]);
            }
#pragma unroll
            for (int mi = 0; mi < 2; mi++)
#pragma unroll
                for (int nj = 0; nj < 4; nj++)
                    MMA_TF32(sacc[mi][nj], af[mi][0], af[mi][1], af[mi][2], af[mi][3],
                             bf[nj][0], bf[nj][1]);
        }

        // ---- scores -> smem with scale + mask ----
#pragma unroll
        for (int mi = 0; mi < 2; mi++) {
            int r = wm * 32 + mi * 16 + gid;
#pragma unroll
            for (int nj = 0; nj < 4; nj++) {
                int c = wn * 32 + nj * 8 + tid4 * 2;
                float am0 = amb[k0 + c], am1 = amb[k0 + c + 1];
                Ss[r * FA_PAD + c]           = sacc[mi][nj][0] * 0.125f + am0;
                Ss[r * FA_PAD + c + 1]       = sacc[mi][nj][1] * 0.125f + am1;
                Ss[(r + 8) * FA_PAD + c]     = sacc[mi][nj][2] * 0.125f + am0;
                Ss[(r + 8) * FA_PAD + c + 1] = sacc[mi][nj][3] * 0.125f + am1;
            }
        }
        __syncthreads();

        // ---- online softmax: 2 threads per row (32 cols each) ----
        {
            int r = tid >> 1, hf = tid & 1;
            float* srow = Ss + r * FA_PAD + hf * 32;
            float mx = -INFINITY;
#pragma unroll 8
            for (int j = 0; j < 32; j++) mx = fmaxf(mx, srow[j]);
            mx = fmaxf(mx, __shfl_xor_sync(0xffffffffu, mx, 1));
            float mold = mrow[r];
            float mnew = fmaxf(mold, mx);
            float sum = 0.f;
#pragma unroll 8
            for (int j = 0; j < 32; j++) {
                float pv = __expf(srow[j] - mnew);
                srow[j] = __uint_as_float(f2tf32(pv));
                sum += pv;
            }
            sum += __shfl_xor_sync(0xffffffffu, sum, 1);
            if (hf == 0) {
                float alpha = __expf(mold - mnew);
                lrow[r] = lrow[r] * alpha + sum;
                mrow[r] = mnew;
                arow[r] = alpha;
            }
        }
        __syncthreads();

        // ---- rescale O, then O += P @ V ----
        float al[2][2];
#pragma unroll
        for (int mi = 0; mi < 2; mi++) {
            int r = wm * 32 + mi * 16 + gid;
            al[mi][0] = arow[r];
            al[mi][1] = arow[r + 8];
        }
#pragma unroll
        for (int mi = 0; mi < 2; mi++)
#pragma unroll
            for (int nj = 0; nj < 4; nj++) {
                oacc[mi][nj][0] *= al[mi][0];
                oacc[mi][nj][1] *= al[mi][0];
                oacc[mi][nj][2] *= al[mi][1];
                oacc[mi][nj][3] *= al[mi][1];
            }

#pragma unroll
        for (int kc = 0; kc < 8; kc++) {
            uint32_t af[2][4];
#pragma unroll
            for (int mi = 0; mi < 2; mi++) {
                const float* ap = &Ss[(wm * 32 + mi * 16 + gid) * FA_PAD + kc * 8 + tid4];
                af[mi][0] = __float_as_uint(ap[0]);
                af[mi][1] = __float_as_uint(ap[8 * FA_PAD]);
                af[mi][2] = __float_as_uint(ap[4]);
                af[mi][3] = __float_as_uint(ap[8 * FA_PAD + 4]);
            }
            uint32_t bf[4][2];
#pragma unroll
            for (int nj = 0; nj < 4; nj++) {
                const float* bp = &Vs[(kc * 8 + tid4) * FA_PAD + wn * 32 + nj * 8 + gid];
                bf[nj][0] = __float_as_uint(bp[0]);
                bf[nj][1] = __float_as_uint(bp[4 * FA_PAD]);
            }
#pragma unroll
            for (int mi = 0; mi < 2; mi++)
#pragma unroll
                for (int nj = 0; nj < 4; nj++)
                    MMA_TF32(oacc[mi][nj], af[mi][0], af[mi][1], af[mi][2], af[mi][3],
                             bf[nj][0], bf[nj][1]);
        }
    }

    // ---- epilogue: divide by l, write ctx (b, q, h*64+d) ----
#pragma unroll
    for (int mi = 0; mi < 2; mi++) {
        int r = wm * 32 + mi * 16 + gid;
        float inv0 = 1.f / lrow[r];
        float inv1 = 1.f / lrow[r + 8];
#pragma unroll
        for (int nj = 0; nj < 4; nj++) {
            int c = wn * 32 + nj * 8 + tid4 * 2;
            float* o0 = &ctx[(size_t)(b * S + q0 + r) * DD + h * 64 + c];
            float* o1 = &ctx[(size_t)(b * S + q0 + r + 8) * DD + h * 64 + c];
            o0[0] = oacc[mi][nj][0] * inv0;
            o0[1] = oacc[mi][nj][1] * inv0;
            o1[0] = oacc[mi][nj][2] * inv1;
            o1[1] = oacc[mi][nj][3] * inv1;
        }
    }
}

// ---------------- embed + positional (reference adds pos[b], not pos[t]) ----
__global__ __launch_bounds__(256) void embed_kernel(const int* __restrict__ tokens,
                                                    const float* __restrict__ emb,
                                                    float* __restrict__ x)
{
    int i = blockIdx.x * 256 + threadIdx.x;
    if (i >= BB*TT*DD) return;
    int d  = i & (DD-1);
    int bt = i / DD;
    int b  = bt / TT;
    int tok = tokens[bt];
    int half = d >> 1;
    float den = __expf(-(float)(2*half) * (logf(10000.f) / (float)DD));
    float ang = (float)b * den;
    float posv = (d & 1) ? cosf(ang) : sinf(ang);
    x[i] = 2.f * emb[(size_t)tok*DD + d] + posv;
}

__global__ __launch_bounds__(256) void mask_kernel(const int* __restrict__ lens,
                                                   float* __restrict__ am, int S)
{
    int i = blockIdx.x*256 + threadIdx.x;
    if (i >= BB*S) return;
    int b = i / S, t = i % S;
    am[i] = (t > lens[b]) ? -INFINITY : 0.f;
}

// ---------------- out = LN(resid + delta) * g + b ----------------
__global__ __launch_bounds__(256) void add_ln_kernel(const float* __restrict__ resid,
                                                     const float* __restrict__ delta,
                                                     const float* __restrict__ g,
                                                     const float* __restrict__ bb,
                                                     float* __restrict__ out)
{
    size_t row = blockIdx.x;
    int t = threadIdx.x;
    __shared__ float red[256];
    float v0 = resid[row*DD + t]       + delta[row*DD + t];
    float v1 = resid[row*DD + t + 256] + delta[row*DD + t + 256];
    red[t] = v0 + v1; __syncthreads();
    for (int s = 128; s > 0; s >>= 1) { if (t < s) red[t] += red[t+s]; __syncthreads(); }
    float mean = red[0] * (1.f/DD);
    __syncthreads();
    float d0 = v0 - mean, d1 = v1 - mean;
    red[t] = d0*d0 + d1*d1; __syncthreads();
    for (int s = 128; s > 0; s >>= 1) { if (t < s) red[t] += red[t+s]; __syncthreads(); }
    float var = red[0] * (1.f/DD);
    float sc = rsqrtf(var + 1e-5f);
    out[row*DD + t]       = d0*sc*g[t]     + bb[t];
    out[row*DD + t + 256] = d1*sc*g[t+256] + bb[t+256];
}

// ---------------- length regulator ----------------
__global__ void cumsum_kernel(const int* __restrict__ dur, int* __restrict__ cums)
{
    int b = blockIdx.x;
    if (threadIdx.x == 0) {
        int s = 0;
        for (int t = 0; t < TT; t++) { s += dur[b*TT + t]; cums[b*TT + t] = s; }
    }
}

__global__ __launch_bounds__(256) void regulate_kernel(const float* __restrict__ enc,
                                                       const int* __restrict__ cums,
                                                       const int* __restrict__ mellen,
                                                       float* __restrict__ dec_in)
{
    int bf = blockIdx.x;
    int b = bf / MELN, f = bf % MELN;
    const int* c = cums + b*TT;
    int lo = 0, hi = TT;
    while (lo < hi) { int mid = (lo + hi) >> 1; if (c[mid] <= f) lo = mid + 1; else hi = mid; }
    int idx = lo; if (idx > TT-1) idx = TT-1;
    float keep = (f <= mellen[b]) ? 1.f : 0.f;
    for (int d = threadIdx.x; d < DD; d += 256)
        dec_in[(size_t)bf*DD + d] = enc[(size_t)(b*TT + idx)*DD + d] * keep;
}

// ---------------- final transpose (b, f, o) -> (b, o, f) ----------------
__global__ __launch_bounds__(256) void transpose_out_kernel(const float* __restrict__ t1,
                                                            float* __restrict__ out)
{
    int i = blockIdx.x*256 + threadIdx.x;
    if (i >= BB*OUTC*MELN) return;
    int f = i % MELN;
    int rest = i / MELN;
    int o = rest % OUTC;
    int b = rest / OUTC;
    out[i] = t1[(size_t)(b*MELN + f)*OUTC + o];
}

// =============================== host side ===============================
struct Ptrs {
    float *x, *qkv, *ctx, *t1, *h, *h2, *enc, *am, *am2;
    int *cums;
};

static void get_ptrs(Ptrs& p)
{
    cudaGetSymbolAddress((void**)&p.x,      g_x);
    cudaGetSymbolAddress((void**)&p.qkv,    g_qkv);
    cudaGetSymbolAddress((void**)&p.ctx,    g_ctx);
    cudaGetSymbolAddress((void**)&p.t1,     g_t1);
    cudaGetSymbolAddress((void**)&p.h,      g_h);
    cudaGetSymbolAddress((void**)&p.h2,     g_h2);
    cudaGetSymbolAddress((void**)&p.enc,    g_enc);
    cudaGetSymbolAddress((void**)&p.am,     g_am);
    cudaGetSymbolAddress((void**)&p.am2,    g_am2);
    cudaGetSymbolAddress((void**)&p.cums,   g_cums);
}

static inline dim3 tc_grid(int M, int N) { return dim3((N + 127)/128, M/128); }

static const size_t FA_SMEM_BYTES = (size_t)FA_SMEM_FLOATS * sizeof(float);

static void run_layer(Ptrs& p, int S, int sLog, const float* am,
                      const float* wqkv, const float* bqkv,
                      const float* wo,   const float* bo,
                      const float* ln1g, const float* ln1b,
                      const float* c1w,  const float* c1b,
                      const float* c2w,  const float* c2b,
                      const float* ln2g, const float* ln2b)
{
    const int M = BB * S;

    // qkv = x @ wqkv + bqkv
    gemm_tc<<<tc_grid(M, 3*DD), 256>>>(p.x, wqkv, bqkv, p.qkv, M, 3*DD, DD, DD, sLog, 0, 0);

    // fused flash attention -> ctx
    flash_attn<<<dim3(S/128, BB*HH), 256, FA_SMEM_BYTES>>>(p.qkv, am, p.ctx, S);

    // t1 = ctx @ wo + bo ; y = LN(x + t1)   (y stored in p.ctx)
    gemm_tc<<<tc_grid(M, DD), 256>>>(p.ctx, wo, bo, p.t1, M, DD, DD, DD, sLog, 0, 0);
    add_ln_kernel<<<M, 256>>>(p.x, p.t1, ln1g, ln1b, p.ctx);

    // conv1 (K=3, SAME) + relu -> h : one fused GEMM, K' = 3*D
    gemm_tc<<<tc_grid(M, INTERN), 256>>>(p.ctx, c1w, c1b, p.h, M, INTERN, 3*DD, DD, sLog, 1, 1);
    // conv2 -> h2 : K' = 3*INTER
    gemm_tc<<<tc_grid(M, DD), 256>>>(p.h, c2w, c2b, p.h2, M, DD, 3*INTERN, INTERN, sLog, 1, 0);

    // x = LN(y + h2)
    add_ln_kernel<<<M, 256>>>(p.ctx, p.h2, ln2g, ln2b, p.x);
}

extern "C" void kernel_launch(void* const* d_in, const int* in_sizes, int n_in,
                              void* d_out, int out_size)
{
    const int*   tokens        = (const int*)  d_in[0];
    const int*   token_lengths = (const int*)  d_in[1];
    const int*   melspec_len   = (const int*)  d_in[2];
    const int*   durations     = (const int*)  d_in[3];
    /* d_in[4] = mel_len (compile-time MELN) */
    const float* emb           = (const float*)d_in[5];
    const float* ew[12]; for (int i = 0; i < 12; i++) ew[i] = (const float*)d_in[6 + i];
    const float* dw[12]; for (int i = 0; i < 12; i++) dw[i] = (const float*)d_in[18 + i];
    const float* out_w         = (const float*)d_in[30];
    const float* out_b         = (const float*)d_in[31];

    cudaFuncSetAttribute(flash_attn, cudaFuncAttributeMaxDynamicSharedMemorySize,
                         (int)FA_SMEM_BYTES);

    Ptrs p; get_ptrs(p);

    // ---- embed + positional + encoder mask ----
    embed_kernel<<<(BB*TT*DD + 255)/256, 256>>>(tokens, emb, p.x);
    mask_kernel<<<(BB*TT + 255)/256, 256>>>(token_lengths, p.am, TT);

    // ---- encoder stack (S = TT) ----
    for (int l = 0; l < LLAY; l++) {
        run_layer(p, TT, 8, p.am,
                  ew[0] + (size_t)l*DD*3*DD,       ew[1] + (size_t)l*3*DD,
                  ew[2] + (size_t)l*DD*DD,         ew[3] + (size_t)l*DD,
                  ew[4] + (size_t)l*DD,            ew[5] + (size_t)l*DD,
                  ew[6] + (size_t)l*3*DD*INTERN,   ew[7] + (size_t)l*INTERN,
                  ew[8] + (size_t)l*3*INTERN*DD,   ew[9] + (size_t)l*DD,
                  ew[10] + (size_t)l*DD,           ew[11] + (size_t)l*DD);
    }

    // ---- length regulator ----
    cudaMemcpyAsync(p.enc, p.x, (size_t)BB*TT*DD*sizeof(float), cudaMemcpyDeviceToDevice);
    cumsum_kernel<<<BB, 32>>>(durations, p.cums);
    regulate_kernel<<<BB*MELN, 256>>>(p.enc, p.cums, melspec_len, p.x);
    mask_kernel<<<(BB*MELN + 255)/256, 256>>>(melspec_len, p.am2, MELN);

    // ---- decoder stack (S = MELN) ----
    for (int l = 0; l < LLAY; l++) {
        run_layer(p, MELN, 10, p.am2,
                  dw[0] + (size_t)l*DD*3*DD,       dw[1] + (size_t)l*3*DD,
                  dw[2] + (size_t)l*DD*DD,         dw[3] + (size_t)l*DD,
                  dw[4] + (size_t)l*DD,            dw[5] + (size_t)l*DD,
                  dw[6] + (size_t)l*3*DD*INTERN,   dw[7] + (size_t)l*INTERN,
                  dw[8] + (size_t)l*3*INTERN*DD,   dw[9] + (size_t)l*DD,
                  dw[10] + (size_t)l*DD,           dw[11] + (size_t)l*DD);
    }

    // ---- output projection + transpose ----
    gemm_tc<<<tc_grid(BB*MELN, OUTC), 256>>>(p.x, out_w, out_b, p.t1,
                                             BB*MELN, OUTC, DD, DD, 10, 0, 0);
    transpose_out_kernel<<<(BB*OUTC*MELN + 255)/256, 256>>>(p.t1, (float*)d_out);
}

// round 6
// speedup vs baseline: 4.8042x; 1.6594x over previous
#include <cuda_runtime.h>
#include <math.h>
#include <stdint.h>

// ---------------- problem constants ----------------
#define BB    16
#define TT    256
#define MELN  1024
#define DD    512
#define HH    8
#define DHD   64
#define LLAY  4
#define INTERN 2048
#define OUTC  80

// ---------------- scratch (device globals; no allocation allowed) ----------
__device__ float g_x   [(size_t)BB*MELN*DD];
__device__ float g_qkv [(size_t)BB*MELN*3*DD];
__device__ float g_ctx [(size_t)BB*MELN*DD];
__device__ float g_t1  [(size_t)BB*MELN*DD];
__device__ float g_h   [(size_t)BB*MELN*INTERN];
__device__ float g_h2  [(size_t)BB*MELN*DD];
__device__ float g_enc [(size_t)BB*TT*DD];
__device__ float g_am  [BB*TT];
__device__ float g_am2 [BB*MELN];
__device__ int   g_cums[BB*TT];

// ---------------- small helpers ----------------
__device__ __forceinline__ uint32_t f2tf32(float x) {
    uint32_t u;
    asm("cvt.rna.tf32.f32 %0, %1;" : "=r"(u) : "f"(x));
    return u;
}
__device__ __forceinline__ float tf32f(float x) { return __uint_as_float(f2tf32(x)); }

__device__ __forceinline__ uint32_t smem_u32(const void* p) {
    uint32_t a;
    asm("{ .reg .u64 t; cvta.to.shared.u64 t, %1; cvt.u32.u64 %0, t; }" : "=r"(a) : "l"(p));
    return a;
}

#define MMA_TF32(acc, a0,a1,a2,a3, b0,b1)                                     \
    asm volatile("mma.sync.aligned.m16n8k8.row.col.f32.tf32.tf32.f32 "        \
                 "{%0,%1,%2,%3},{%4,%5,%6,%7},{%8,%9},{%0,%1,%2,%3};"         \
                 : "+f"(acc[0]), "+f"(acc[1]), "+f"(acc[2]), "+f"(acc[3])     \
                 : "r"(a0), "r"(a1), "r"(a2), "r"(a3), "r"(b0), "r"(b1))

#define CP16(dst, src, sz)                                                    \
    asm volatile("cp.async.cg.shared.global [%0], [%1], 16, %2;"              \
                 :: "r"(dst), "l"(src), "r"(sz) : "memory")
#define CP_COMMIT()  asm volatile("cp.async.commit_group;" ::: "memory")
#define CP_WAIT1()   asm volatile("cp.async.wait_group 1;" ::: "memory")

// ================== cp.async pipelined tf32 GEMM (mma.sync) =================
// C[M,N] = op(A' @ W + bias). A (M,Kin) fp32 row-major; conv mode: K'=3*Kin,
// k' -> (tap, col), source row (m%S)+tap-1 (zero-filled OOB). W (Ktot,N) fp32
// row-major (original weights). tf32 rounding applied at fragment load (rna),
// numerics identical to the validated mma.sync kernel.
// CTA tile 128x256, BK=16, 3-stage cp.async pipeline, 512 threads = 16 warps
// (2m x 8n grid, 64x32 warp tiles). Requires M%128==0, N%256==0, Kin%16==0.
#define CPA_STRIDE 20
#define CPB_STRIDE 264
#define CPA_FLOATS (128*CPA_STRIDE)          // 2560 (10240 B)
#define CPB_FLOATS (16*CPB_STRIDE)           // 4224 (16896 B)
#define CP_STAGE_BYTES ((CPA_FLOATS + CPB_FLOATS) * 4)   // 27136
#define CP_SMEM_BYTES  (3 * CP_STAGE_BYTES)              // 81408

__global__ __launch_bounds__(512) void gemm_cp(
    const float* __restrict__ A, const float* __restrict__ W,
    const float* __restrict__ bias, float* __restrict__ C,
    int M, int N, int Ktot, int Kin, int sLog, int conv, int relu)
{
    extern __shared__ char sm[];
    const uint32_t sbase = smem_u32(sm);

    const int tid  = threadIdx.x;
    const int warp = tid >> 5, lane = tid & 31;
    const int gid  = lane >> 2, tid4 = lane & 3;
    const int wm   = warp & 1,  wn   = warp >> 1;    // 2 x 8 warps
    const int bm   = blockIdx.y * 128;
    const int bn   = blockIdx.x * 256;
    const int S    = 1 << sLog;
    const int nst  = Ktot / 16;

    float acc[4][4][4];
#pragma unroll
    for (int i = 0; i < 4; i++)
#pragma unroll
        for (int j = 0; j < 4; j++)
#pragma unroll
            for (int r = 0; r < 4; r++) acc[i][j][r] = 0.f;

    // ---- async stage issue: global -> smem (raw fp32) ----
    auto issue_stage = [&](int stg) {
        const int k0    = stg * 16;
        const int tap   = conv ? (k0 / Kin) : 0;
        const int kcol  = k0 - tap * Kin;
        const int shift = conv ? (tap - 1) : 0;
        const uint32_t aB = sbase + (stg % 3) * CP_STAGE_BYTES;
        const uint32_t bB = aB + CPA_FLOATS * 4;
        // A: 128 rows x 16 floats = 512 x 16B chunks (1 per thread)
        {
            int row = tid >> 2, cq = tid & 3;
            int gm = bm + row;
            int b = gm >> sLog, l = gm & (S - 1);
            int src = l + shift;
            uint32_t sz = (src >= 0 && src < S) ? 16u : 0u;
            int srcc = (src >= 0 && src < S) ? src : 0;
            const float* gp = A + (size_t)(((size_t)b << sLog) + srcc) * Kin + kcol + cq * 4;
            CP16(aB + (row * CPA_STRIDE + cq * 4) * 4, gp, sz);
        }
        // B: 16 k-rows x 256 floats = 1024 x 16B chunks (2 per thread)
#pragma unroll
        for (int i = 0; i < 2; i++) {
            int flat = tid + i * 512;
            int kr = flat >> 6, n4 = flat & 63;
            const float* gp = W + (size_t)(k0 + kr) * N + bn + n4 * 4;
            CP16(bB + (kr * CPB_STRIDE + n4 * 4) * 4, gp, 16u);
        }
    };

    // ---- compute one stage ----
    auto compute = [&](int stg) {
        const float* aS = (const float*)(sm + (stg % 3) * CP_STAGE_BYTES);
        const float* bS = aS + CPA_FLOATS;
#pragma unroll
        for (int c = 0; c < 2; c++) {
            uint32_t af[4][4];
#pragma unroll
            for (int mi = 0; mi < 4; mi++) {
                const float* ap = &aS[(wm * 64 + mi * 16 + gid) * CPA_STRIDE + c * 8 + tid4];
                af[mi][0] = f2tf32(ap[0]);
                af[mi][1] = f2tf32(ap[8 * CPA_STRIDE]);
                af[mi][2] = f2tf32(ap[4]);
                af[mi][3] = f2tf32(ap[8 * CPA_STRIDE + 4]);
            }
            uint32_t bf[4][2];
#pragma unroll
            for (int nj = 0; nj < 4; nj++) {
                const float* bp = &bS[(c * 8 + tid4) * CPB_STRIDE + wn * 32 + nj * 8 + gid];
                bf[nj][0] = f2tf32(bp[0]);
                bf[nj][1] = f2tf32(bp[4 * CPB_STRIDE]);
            }
#pragma unroll
            for (int mi = 0; mi < 4; mi++)
#pragma unroll
                for (int nj = 0; nj < 4; nj++)
                    MMA_TF32(acc[mi][nj], af[mi][0], af[mi][1], af[mi][2], af[mi][3],
                             bf[nj][0], bf[nj][1]);
        }
    };

    // ---- 3-deep pipeline ----
    issue_stage(0); CP_COMMIT();
    issue_stage(1); CP_COMMIT();
    for (int s = 0; s < nst; s++) {
        CP_WAIT1();
        __syncthreads();
        if (s + 2 < nst) issue_stage(s + 2);
        CP_COMMIT();
        compute(s);
    }

    // ---- epilogue ----
#pragma unroll
    for (int mi = 0; mi < 4; mi++) {
        int gm0 = bm + wm * 64 + mi * 16 + gid;
#pragma unroll
        for (int nj = 0; nj < 4; nj++) {
            int gn = bn + wn * 32 + nj * 8 + tid4 * 2;
            float b0 = bias[gn], b1 = bias[gn + 1];
            float v00 = acc[mi][nj][0] + b0;
            float v01 = acc[mi][nj][1] + b1;
            float v10 = acc[mi][nj][2] + b0;
            float v11 = acc[mi][nj][3] + b1;
            if (relu) {
                v00 = fmaxf(v00, 0.f); v01 = fmaxf(v01, 0.f);
                v10 = fmaxf(v10, 0.f); v11 = fmaxf(v11, 0.f);
            }
            C[(size_t)gm0 * N + gn]           = v00;
            C[(size_t)gm0 * N + gn + 1]       = v01;
            C[(size_t)(gm0 + 8) * N + gn]     = v10;
            C[(size_t)(gm0 + 8) * N + gn + 1] = v11;
        }
    }
}

// ======================= legacy mma.sync GEMM (out-proj only, N=80) ========
#define GT_PAD 132
__global__ __launch_bounds__(256) void gemm_tc(
    const float* __restrict__ A, const float* __restrict__ W,
    const float* __restrict__ bias, float* __restrict__ C,
    int M, int N, int Ktot, int Kin, int sLog, int conv, int relu)
{
    __shared__ float As[2][2112];
    __shared__ float Bs[2][2112];
    const int tid  = threadIdx.x;
    const int warp = tid >> 5, lane = tid & 31;
    const int gid  = lane >> 2, tid4 = lane & 3;
    const int wm   = warp & 1,  wn   = warp >> 1;
    const int bm   = blockIdx.y * 128;
    const int bn   = blockIdx.x * 128;
    const int S    = 1 << sLog;
    const int nFull = (bn + 128 <= N);

    float acc[4][4][4];
#pragma unroll
    for (int i = 0; i < 4; i++)
#pragma unroll
        for (int j = 0; j < 4; j++)
#pragma unroll
            for (int r = 0; r < 4; r++) acc[i][j][r] = 0.f;

    const int nStages = Ktot / 16;
    float4 aReg[2], bReg[2];

    auto load_stage = [&](int stg) {
        const int k0   = stg * 16;
        const int tap  = conv ? (k0 / Kin) : 0;
        const int kcol = k0 - tap * Kin;
        const int shift = conv ? (tap - 1) : 0;
#pragma unroll
        for (int i = 0; i < 2; i++) {
            int s = tid + i * 256;
            int m = s >> 2, kq = s & 3;
            int gm = bm + m;
            int b = gm >> sLog;
            int l = gm & (S - 1);
            int src = l + shift;
            float4 v = make_float4(0.f, 0.f, 0.f, 0.f);
            if (src >= 0 && src < S)
                v = *(const float4*)&A[((size_t)(((size_t)b << sLog) + src)) * Kin + kcol + kq * 4];
            aReg[i] = v;
        }
#pragma unroll
        for (int i = 0; i < 2; i++) {
            int s = tid + i * 256;
            int kk = s >> 5, n4 = s & 31;
            int gn = bn + n4 * 4;
            float4 v = make_float4(0.f, 0.f, 0.f, 0.f);
            if (nFull) {
                v = *(const float4*)&W[(size_t)(k0 + kk) * N + gn];
            } else {
                const float* wr = &W[(size_t)(k0 + kk) * N];
                if (gn + 0 < N) v.x = wr[gn + 0];
                if (gn + 1 < N) v.y = wr[gn + 1];
                if (gn + 2 < N) v.z = wr[gn + 2];
                if (gn + 3 < N) v.w = wr[gn + 3];
            }
            bReg[i] = v;
        }
    };
    auto store_stage = [&](int buf) {
        float* a_s = As[buf];
        float* b_s = Bs[buf];
#pragma unroll
        for (int i = 0; i < 2; i++) {
            int s = tid + i * 256;
            int m = s >> 2, kq = s & 3;
            float va[4] = {aReg[i].x, aReg[i].y, aReg[i].z, aReg[i].w};
#pragma unroll
            for (int j = 0; j < 4; j++) {
                int k = kq * 4 + j;
                int c = k >> 3, p = k & 7;
                int slot = p & 3, comp = p >> 2;
                a_s[((c * 4 + slot) * GT_PAD + m) * 2 + comp] = tf32f(va[j]);
            }
        }
#pragma unroll
        for (int i = 0; i < 2; i++) {
            int s = tid + i * 256;
            int kk = s >> 5, n4 = s & 31;
            float4 v = bReg[i];
            v.x = tf32f(v.x); v.y = tf32f(v.y); v.z = tf32f(v.z); v.w = tf32f(v.w);
            *(float4*)&b_s[kk * GT_PAD + n4 * 4] = v;
        }
    };
    auto compute = [&](int buf) {
        const float* a_s = As[buf];
        const float* b_s = Bs[buf];
#pragma unroll
        for (int c = 0; c < 2; c++) {
            uint32_t af[4][4];
#pragma unroll
            for (int mi = 0; mi < 4; mi++) {
                int mbase = wm * 64 + mi * 16;
                float2 lo = *(const float2*)&a_s[((c * 4 + tid4) * GT_PAD + mbase + gid) * 2];
                float2 hi = *(const float2*)&a_s[((c * 4 + tid4) * GT_PAD + mbase + gid + 8) * 2];
                af[mi][0] = __float_as_uint(lo.x);
                af[mi][1] = __float_as_uint(hi.x);
                af[mi][2] = __float_as_uint(lo.y);
                af[mi][3] = __float_as_uint(hi.y);
            }
            uint32_t bf[4][2];
#pragma unroll
            for (int nj = 0; nj < 4; nj++) {
                int nn = wn * 32 + nj * 8 + gid;
                bf[nj][0] = __float_as_uint(b_s[(c * 8 + tid4) * GT_PAD + nn]);
                bf[nj][1] = __float_as_uint(b_s[(c * 8 + tid4 + 4) * GT_PAD + nn]);
            }
#pragma unroll
            for (int mi = 0; mi < 4; mi++)
#pragma unroll
                for (int nj = 0; nj < 4; nj++)
                    MMA_TF32(acc[mi][nj], af[mi][0], af[mi][1], af[mi][2], af[mi][3],
                             bf[nj][0], bf[nj][1]);
        }
    };

    load_stage(0);
    store_stage(0);
    __syncthreads();
    for (int s = 0; s < nStages; s++) {
        int buf = s & 1;
        if (s + 1 < nStages) load_stage(s + 1);
        compute(buf);
        if (s + 1 < nStages) {
            store_stage(buf ^ 1);
            __syncthreads();
        }
    }
#pragma unroll
    for (int mi = 0; mi < 4; mi++) {
        int gm0 = bm + wm * 64 + mi * 16 + gid;
#pragma unroll
        for (int nj = 0; nj < 4; nj++) {
            int gn = bn + wn * 32 + nj * 8 + tid4 * 2;
            float b0 = 0.f, b1 = 0.f;
            if (bias) {
                if (gn < N)     b0 = bias[gn];
                if (gn + 1 < N) b1 = bias[gn + 1];
            }
            float v00 = acc[mi][nj][0] + b0;
            float v01 = acc[mi][nj][1] + b1;
            float v10 = acc[mi][nj][2] + b0;
            float v11 = acc[mi][nj][3] + b1;
            if (relu) {
                v00 = fmaxf(v00, 0.f); v01 = fmaxf(v01, 0.f);
                v10 = fmaxf(v10, 0.f); v11 = fmaxf(v11, 0.f);
            }
            if (gn < N) {
                C[(size_t)gm0 * N + gn]       = v00;
                C[(size_t)(gm0 + 8) * N + gn] = v10;
            }
            if (gn + 1 < N) {
                C[(size_t)gm0 * N + gn + 1]       = v01;
                C[(size_t)(gm0 + 8) * N + gn + 1] = v11;
            }
        }
    }
}

// ======================= fused flash attention (tf32 mma.sync) =============
#define FA_PAD 68
#define FA_SMEM_FLOATS (128*FA_PAD + 64*FA_PAD + 64*FA_PAD + 128*FA_PAD + 3*128)

__global__ __launch_bounds__(256) void flash_attn(const float* __restrict__ qkv,
                                                  const float* __restrict__ am,
                                                  float* __restrict__ ctx, int S)
{
    extern __shared__ float smf[];
    float* Qs   = smf;
    float* Ks   = Qs + 128*FA_PAD;
    float* Vs   = Ks + 64*FA_PAD;
    float* Ss   = Vs + 64*FA_PAD;
    float* mrow = Ss + 128*FA_PAD;
    float* lrow = mrow + 128;
    float* arow = lrow + 128;

    const int tid  = threadIdx.x;
    const int warp = tid >> 5, lane = tid & 31;
    const int gid  = lane >> 2, tid4 = lane & 3;
    const int wm   = warp & 3, wn = warp >> 2;
    const int bh   = blockIdx.y;
    const int b    = bh >> 3, h = bh & 7;
    const int q0   = blockIdx.x * 128;
    const float* amb = am + b * S;
    const float* qb  = qkv + (size_t)(b * S) * 1536 + h * 64;

#pragma unroll
    for (int i = 0; i < 8; i++) {
        int idx = tid + i * 256;
        int r = idx >> 4, c4 = idx & 15;
        float4 v = *(const float4*)&qb[(size_t)(q0 + r) * 1536 + c4 * 4];
        float* dst = &Qs[r * FA_PAD + c4 * 4];
        dst[0] = tf32f(v.x); dst[1] = tf32f(v.y); dst[2] = tf32f(v.z); dst[3] = tf32f(v.w);
    }
    if (tid < 128) { mrow[tid] = -INFINITY; lrow[tid] = 0.f; }

    float oacc[2][4][4];
#pragma unroll
    for (int mi = 0; mi < 2; mi++)
#pragma unroll
        for (int nj = 0; nj < 4; nj++)
#pragma unroll
            for (int r = 0; r < 4; r++) oacc[mi][nj][r] = 0.f;

    const int nkt = S >> 6;
    for (int kt = 0; kt < nkt; kt++) {
        const int k0 = kt * 64;
        __syncthreads();
#pragma unroll
        for (int i = 0; i < 4; i++) {
            int idx = tid + i * 256;
            int r = idx >> 4, c4 = idx & 15;
            const float* src = &qb[(size_t)(k0 + r) * 1536];
            float4 kv = *(const float4*)&src[512 + c4 * 4];
            float4 vv = *(const float4*)&src[1024 + c4 * 4];
            float* kd = &Ks[r * FA_PAD + c4 * 4];
            float* vd = &Vs[r * FA_PAD + c4 * 4];
            kd[0] = tf32f(kv.x); kd[1] = tf32f(kv.y); kd[2] = tf32f(kv.z); kd[3] = tf32f(kv.w);
            vd[0] = tf32f(vv.x); vd[1] = tf32f(vv.y); vd[2] = tf32f(vv.z); vd[3] = tf32f(vv.w);
        }
        __syncthreads();

        float sacc[2][4][4];
#pragma unroll
        for (int mi = 0; mi < 2; mi++)
#pragma unroll
            for (int nj = 0; nj < 4; nj++)
#pragma unroll
                for (int r = 0; r < 4; r++) sacc[mi][nj][r] = 0.f;
#pragma unroll
        for (int kc = 0; kc < 8; kc++) {
            uint32_t af[2][4];
#pragma unroll
            for (int mi = 0; mi < 2; mi++) {
                const float* ap = &Qs[(wm * 32 + mi * 16 + gid) * FA_PAD + kc * 8 + tid4];
                af[mi][0] = __float_as_uint(ap[0]);
                af[mi][1] = __float_as_uint(ap[8 * FA_PAD]);
                af[mi][2] = __float_as_uint(ap[4]);
                af[mi][3] = __float_as_uint(ap[8 * FA_PAD + 4]);
            }
            uint32_t bf[4][2];
#pragma unroll
            for (int nj = 0; nj < 4; nj++) {
                const float* bp = &Ks[(wn * 32 + nj * 8 + gid) * FA_PAD + kc * 8 + tid4];
                bf[nj][0] = __float_as_uint(bp[0]);
                bf[nj][1] = __float_as_uint(bp[4]);
            }
#pragma unroll
            for (int mi = 0; mi < 2; mi++)
#pragma unroll
                for (int nj = 0; nj < 4; nj++)
                    MMA_TF32(sacc[mi][nj], af[mi][0], af[mi][1], af[mi][2], af[mi][3],
                             bf[nj][0], bf[nj][1]);
        }
#pragma unroll
        for (int mi = 0; mi < 2; mi++) {
            int r = wm * 32 + mi * 16 + gid;
#pragma unroll
            for (int nj = 0; nj < 4; nj++) {
                int c = wn * 32 + nj * 8 + tid4 * 2;
                float am0 = amb[k0 + c], am1 = amb[k0 + c + 1];
                Ss[r * FA_PAD + c]           = sacc[mi][nj][0] * 0.125f + am0;
                Ss[r * FA_PAD + c + 1]       = sacc[mi][nj][1] * 0.125f + am1;
                Ss[(r + 8) * FA_PAD + c]     = sacc[mi][nj][2] * 0.125f + am0;
                Ss[(r + 8) * FA_PAD + c + 1] = sacc[mi][nj][3] * 0.125f + am1;
            }
        }
        __syncthreads();
        {
            int r = tid >> 1, hf = tid & 1;
            float* srow = Ss + r * FA_PAD + hf * 32;
            float mx = -INFINITY;
#pragma unroll 8
            for (int j = 0; j < 32; j++) mx = fmaxf(mx, srow[j]);
            mx = fmaxf(mx, __shfl_xor_sync(0xffffffffu, mx, 1));
            float mold = mrow[r];
            float mnew = fmaxf(mold, mx);
            float sum = 0.f;
#pragma unroll 8
            for (int j = 0; j < 32; j++) {
                float pv = __expf(srow[j] - mnew);
                srow[j] = __uint_as_float(f2tf32(pv));
                sum += pv;
            }
            sum += __shfl_xor_sync(0xffffffffu, sum, 1);
            if (hf == 0) {
                float alpha = __expf(mold - mnew);
                lrow[r] = lrow[r] * alpha + sum;
                mrow[r] = mnew;
                arow[r] = alpha;
            }
        }
        __syncthreads();

        float al[2][2];
#pragma unroll
        for (int mi = 0; mi < 2; mi++) {
            int r = wm * 32 + mi * 16 + gid;
            al[mi][0] = arow[r];
            al[mi][1] = arow[r + 8];
        }
#pragma unroll
        for (int mi = 0; mi < 2; mi++)
#pragma unroll
            for (int nj = 0; nj < 4; nj++) {
                oacc[mi][nj][0] *= al[mi][0];
                oacc[mi][nj][1] *= al[mi][0];
                oacc[mi][nj][2] *= al[mi][1];
                oacc[mi][nj][3] *= al[mi][1];
            }
#pragma unroll
        for (int kc = 0; kc < 8; kc++) {
            uint32_t af[2][4];
#pragma unroll
            for (int mi = 0; mi < 2; mi++) {
                const float* ap = &Ss[(wm * 32 + mi * 16 + gid) * FA_PAD + kc * 8 + tid4];
                af[mi][0] = __float_as_uint(ap[0]);
                af[mi][1] = __float_as_uint(ap[8 * FA_PAD]);
                af[mi][2] = __float_as_uint(ap[4]);
                af[mi][3] = __float_as_uint(ap[8 * FA_PAD + 4]);
            }
            uint32_t bf[4][2];
#pragma unroll
            for (int nj = 0; nj < 4; nj++) {
                const float* bp = &Vs[(kc * 8 + tid4) * FA_PAD + wn * 32 + nj * 8 + gid];
                bf[nj][0] = __float_as_uint(bp[0]);
                bf[nj][1] = __float_as_uint(bp[4 * FA_PAD]);
            }
#pragma unroll
            for (int mi = 0; mi < 2; mi++)
#pragma unroll
                for (int nj = 0; nj < 4; nj++)
                    MMA_TF32(oacc[mi][nj], af[mi][0], af[mi][1], af[mi][2], af[mi][3],
                             bf[nj][0], bf[nj][1]);
        }
    }
#pragma unroll
    for (int mi = 0; mi < 2; mi++) {
        int r = wm * 32 + mi * 16 + gid;
        float inv0 = 1.f / lrow[r];
        float inv1 = 1.f / lrow[r + 8];
#pragma unroll
        for (int nj = 0; nj < 4; nj++) {
            int c = wn * 32 + nj * 8 + tid4 * 2;
            float* o0 = &ctx[(size_t)(b * S + q0 + r) * DD + h * 64 + c];
            float* o1 = &ctx[(size_t)(b * S + q0 + r + 8) * DD + h * 64 + c];
            o0[0] = oacc[mi][nj][0] * inv0;
            o0[1] = oacc[mi][nj][1] * inv0;
            o1[0] = oacc[mi][nj][2] * inv1;
            o1[1] = oacc[mi][nj][3] * inv1;
        }
    }
}

// ---------------- embed + positional (reference adds pos[b], not pos[t]) ----
__global__ __launch_bounds__(256) void embed_kernel(const int* __restrict__ tokens,
                                                    const float* __restrict__ emb,
                                                    float* __restrict__ x)
{
    int i = blockIdx.x * 256 + threadIdx.x;
    if (i >= BB*TT*DD) return;
    int d  = i & (DD-1);
    int bt = i / DD;
    int b  = bt / TT;
    int tok = tokens[bt];
    int half = d >> 1;
    float den = __expf(-(float)(2*half) * (logf(10000.f) / (float)DD));
    float ang = (float)b * den;
    float posv = (d & 1) ? cosf(ang) : sinf(ang);
    x[i] = 2.f * emb[(size_t)tok*DD + d] + posv;
}

__global__ __launch_bounds__(256) void mask_kernel(const int* __restrict__ lens,
                                                   float* __restrict__ am, int S)
{
    int i = blockIdx.x*256 + threadIdx.x;
    if (i >= BB*S) return;
    int b = i / S, t = i % S;
    am[i] = (t > lens[b]) ? -INFINITY : 0.f;
}

__global__ __launch_bounds__(256) void add_ln_kernel(const float* __restrict__ resid,
                                                     const float* __restrict__ delta,
                                                     const float* __restrict__ g,
                                                     const float* __restrict__ bb,
                                                     float* __restrict__ out)
{
    size_t row = blockIdx.x;
    int t = threadIdx.x;
    __shared__ float red[256];
    float v0 = resid[row*DD + t]       + delta[row*DD + t];
    float v1 = resid[row*DD + t + 256] + delta[row*DD + t + 256];
    red[t] = v0 + v1; __syncthreads();
    for (int s = 128; s > 0; s >>= 1) { if (t < s) red[t] += red[t+s]; __syncthreads(); }
    float mean = red[0] * (1.f/DD);
    __syncthreads();
    float d0 = v0 - mean, d1 = v1 - mean;
    red[t] = d0*d0 + d1*d1; __syncthreads();
    for (int s = 128; s > 0; s >>= 1) { if (t < s) red[t] += red[t+s]; __syncthreads(); }
    float var = red[0] * (1.f/DD);
    float sc = rsqrtf(var + 1e-5f);
    out[row*DD + t]       = d0*sc*g[t]     + bb[t];
    out[row*DD + t + 256] = d1*sc*g[t+256] + bb[t+256];
}

__global__ void cumsum_kernel(const int* __restrict__ dur, int* __restrict__ cums)
{
    int b = blockIdx.x;
    if (threadIdx.x == 0) {
        int s = 0;
        for (int t = 0; t < TT; t++) { s += dur[b*TT + t]; cums[b*TT + t] = s; }
    }
}

__global__ __launch_bounds__(256) void regulate_kernel(const float* __restrict__ enc,
                                                       const int* __restrict__ cums,
                                                       const int* __restrict__ mellen,
                                                       float* __restrict__ dec_in)
{
    int bf = blockIdx.x;
    int b = bf / MELN, f = bf % MELN;
    const int* c = cums + b*TT;
    int lo = 0, hi = TT;
    while (lo < hi) { int mid = (lo + hi) >> 1; if (c[mid] <= f) lo = mid + 1; else hi = mid; }
    int idx = lo; if (idx > TT-1) idx = TT-1;
    float keep = (f <= mellen[b]) ? 1.f : 0.f;
    for (int d = threadIdx.x; d < DD; d += 256)
        dec_in[(size_t)bf*DD + d] = enc[(size_t)(b*TT + idx)*DD + d] * keep;
}

__global__ __launch_bounds__(256) void transpose_out_kernel(const float* __restrict__ t1,
                                                            float* __restrict__ out)
{
    int i = blockIdx.x*256 + threadIdx.x;
    if (i >= BB*OUTC*MELN) return;
    int f = i % MELN;
    int rest = i / MELN;
    int o = rest % OUTC;
    int b = rest / OUTC;
    out[i] = t1[(size_t)(b*MELN + f)*OUTC + o];
}

// =============================== host side ===============================
struct Ptrs {
    float *x, *qkv, *ctx, *t1, *h, *h2, *enc, *am, *am2;
    int *cums;
};

static void get_ptrs(Ptrs& p)
{
    cudaGetSymbolAddress((void**)&p.x,      g_x);
    cudaGetSymbolAddress((void**)&p.qkv,    g_qkv);
    cudaGetSymbolAddress((void**)&p.ctx,    g_ctx);
    cudaGetSymbolAddress((void**)&p.t1,     g_t1);
    cudaGetSymbolAddress((void**)&p.h,      g_h);
    cudaGetSymbolAddress((void**)&p.h2,     g_h2);
    cudaGetSymbolAddress((void**)&p.enc,    g_enc);
    cudaGetSymbolAddress((void**)&p.am,     g_am);
    cudaGetSymbolAddress((void**)&p.am2,    g_am2);
    cudaGetSymbolAddress((void**)&p.cums,   g_cums);
}

static const size_t FA_SMEM_BYTES = (size_t)FA_SMEM_FLOATS * sizeof(float);

static void run_layer(Ptrs& p, int S, int sLog, const float* am,
                      const float* wqkv, const float* bqkv,
                      const float* wo,   const float* bo,
                      const float* ln1g, const float* ln1b,
                      const float* c1w,  const float* c1b,
                      const float* c2w,  const float* c2b,
                      const float* ln2g, const float* ln2b)
{
    const int M = BB * S;

    // qkv = x @ wqkv + bqkv
    gemm_cp<<<dim3(6, M/128), 512, CP_SMEM_BYTES>>>(p.x, wqkv, bqkv, p.qkv,
                                                    M, 3*DD, DD, DD, sLog, 0, 0);
    // fused flash attention -> ctx
    flash_attn<<<dim3(S/128, BB*HH), 256, FA_SMEM_BYTES>>>(p.qkv, am, p.ctx, S);
    // t1 = ctx @ wo + bo ; y = LN(x + t1) -> ctx
    gemm_cp<<<dim3(2, M/128), 512, CP_SMEM_BYTES>>>(p.ctx, wo, bo, p.t1,
                                                    M, DD, DD, DD, sLog, 0, 0);
    add_ln_kernel<<<M, 256>>>(p.x, p.t1, ln1g, ln1b, p.ctx);
    // conv1 (K=3, SAME) + relu, fused GEMM K'=3*D
    gemm_cp<<<dim3(8, M/128), 512, CP_SMEM_BYTES>>>(p.ctx, c1w, c1b, p.h,
                                                    M, INTERN, 3*DD, DD, sLog, 1, 1);
    // conv2, K'=3*INTER
    gemm_cp<<<dim3(2, M/128), 512, CP_SMEM_BYTES>>>(p.h, c2w, c2b, p.h2,
                                                    M, DD, 3*INTERN, INTERN, sLog, 1, 0);
    // x = LN(y + h2)
    add_ln_kernel<<<M, 256>>>(p.ctx, p.h2, ln2g, ln2b, p.x);
}

extern "C" void kernel_launch(void* const* d_in, const int* in_sizes, int n_in,
                              void* d_out, int out_size)
{
    const int*   tokens        = (const int*)  d_in[0];
    const int*   token_lengths = (const int*)  d_in[1];
    const int*   melspec_len   = (const int*)  d_in[2];
    const int*   durations     = (const int*)  d_in[3];
    const float* emb           = (const float*)d_in[5];
    const float* ew[12]; for (int i = 0; i < 12; i++) ew[i] = (const float*)d_in[6 + i];
    const float* dw[12]; for (int i = 0; i < 12; i++) dw[i] = (const float*)d_in[18 + i];
    const float* out_w         = (const float*)d_in[30];
    const float* out_b         = (const float*)d_in[31];

    cudaFuncSetAttribute(flash_attn, cudaFuncAttributeMaxDynamicSharedMemorySize,
                         (int)FA_SMEM_BYTES);
    cudaFuncSetAttribute(gemm_cp, cudaFuncAttributeMaxDynamicSharedMemorySize,
                         CP_SMEM_BYTES);

    Ptrs p; get_ptrs(p);

    // ---- embed + positional + encoder mask ----
    embed_kernel<<<(BB*TT*DD + 255)/256, 256>>>(tokens, emb, p.x);
    mask_kernel<<<(BB*TT + 255)/256, 256>>>(token_lengths, p.am, TT);

    // ---- encoder stack (S = TT) ----
    for (int l = 0; l < LLAY; l++) {
        run_layer(p, TT, 8, p.am,
                  ew[0] + (size_t)l*DD*3*DD,       ew[1] + (size_t)l*3*DD,
                  ew[2] + (size_t)l*DD*DD,         ew[3] + (size_t)l*DD,
                  ew[4] + (size_t)l*DD,            ew[5] + (size_t)l*DD,
                  ew[6] + (size_t)l*3*DD*INTERN,   ew[7] + (size_t)l*INTERN,
                  ew[8] + (size_t)l*3*INTERN*DD,   ew[9] + (size_t)l*DD,
                  ew[10] + (size_t)l*DD,           ew[11] + (size_t)l*DD);
    }

    // ---- length regulator ----
    cudaMemcpyAsync(p.enc, p.x, (size_t)BB*TT*DD*sizeof(float), cudaMemcpyDeviceToDevice);
    cumsum_kernel<<<BB, 32>>>(durations, p.cums);
    regulate_kernel<<<BB*MELN, 256>>>(p.enc, p.cums, melspec_len, p.x);
    mask_kernel<<<(BB*MELN + 255)/256, 256>>>(melspec_len, p.am2, MELN);

    // ---- decoder stack (S = MELN) ----
    for (int l = 0; l < LLAY; l++) {
        run_layer(p, MELN, 10, p.am2,
                  dw[0] + (size_t)l*DD*3*DD,       dw[1] + (size_t)l*3*DD,
                  dw[2] + (size_t)l*DD*DD,         dw[3] + (size_t)l*DD,
                  dw[4] + (size_t)l*DD,            dw[5] + (size_t)l*DD,
                  dw[6] + (size_t)l*3*DD*INTERN,   dw[7] + (size_t)l*INTERN,
                  dw[8] + (size_t)l*3*INTERN*DD,   dw[9] + (size_t)l*DD,
                  dw[10] + (size_t)l*DD,           dw[11] + (size_t)l*DD);
    }

    // ---- output projection (N=80, legacy path) + transpose ----
    gemm_tc<<<dim3(1, BB*MELN/128), 256>>>(p.x, out_w, out_b, p.t1,
                                           BB*MELN, OUTC, DD, DD, 10, 0, 0);
    transpose_out_kernel<<<(BB*OUTC*MELN + 255)/256, 256>>>(p.t1, (float*)d_out);
}

// round 7
// speedup vs baseline: 7.7357x; 1.6102x over previous
#include <cuda_runtime.h>
#include <cuda_fp16.h>
#include <math.h>
#include <stdint.h>

// ---------------- problem constants ----------------
#define BB    16
#define TT    256
#define MELN  1024
#define DD    512
#define HH    8
#define DHD   64
#define LLAY  4
#define INTERN 2048
#define OUTC  80

// ---------------- scratch (device globals; no allocation allowed) ----------
__device__ float  g_x   [(size_t)BB*MELN*DD];       // fp32 activations (residual)
__device__ __half g_xh  [(size_t)BB*MELN*DD];       // fp16 GEMM-input copy
__device__ __half g_qkvh[(size_t)BB*MELN*3*DD];     // qkv (fp16)
__device__ float  g_ctx [(size_t)BB*MELN*DD];       // LN1 output y (fp32)
__device__ __half g_ctxh[(size_t)BB*MELN*DD];       // attn ctx / (fp16)
__device__ float  g_t1  [(size_t)BB*MELN*DD];       // wo out / final proj (fp32)
__device__ __half g_hh  [(size_t)BB*MELN*INTERN];   // conv1 out (fp16)
__device__ float  g_h2  [(size_t)BB*MELN*DD];       // conv2 out (fp32)
__device__ float  g_enc [(size_t)BB*TT*DD];
__device__ float  g_am  [BB*TT];
__device__ float  g_am2 [BB*MELN];
__device__ int    g_cums[BB*TT];
// transposed fp16 weights (N,K) per layer: qkv 1536x512, wo 512x512,
// c1 2048x1536, c2 512x6144 -> 7340032 halves/layer, 8 layers
#define WT_QKV   0
#define WT_WO    786432
#define WT_C1    1048576
#define WT_C2    4194304
#define WT_LAYER 7340032
__device__ __half g_wh [(size_t)WT_LAYER * 8];

// ---------------- small helpers ----------------
__device__ __forceinline__ uint32_t f2tf32(float x) {
    uint32_t u;
    asm("cvt.rna.tf32.f32 %0, %1;" : "=r"(u) : "f"(x));
    return u;
}
__device__ __forceinline__ uint32_t smem_u32(const void* p) {
    uint32_t a;
    asm("{ .reg .u64 t; cvta.to.shared.u64 t, %1; cvt.u32.u64 %0, t; }" : "=r"(a) : "l"(p));
    return a;
}

#define MMA_TF32(acc, a0,a1,a2,a3, b0,b1)                                     \
    asm volatile("mma.sync.aligned.m16n8k8.row.col.f32.tf32.tf32.f32 "        \
                 "{%0,%1,%2,%3},{%4,%5,%6,%7},{%8,%9},{%0,%1,%2,%3};"         \
                 : "+f"(acc[0]), "+f"(acc[1]), "+f"(acc[2]), "+f"(acc[3])     \
                 : "r"(a0), "r"(a1), "r"(a2), "r"(a3), "r"(b0), "r"(b1))

#define MMA_F16(acc, a0,a1,a2,a3, b0,b1)                                      \
    asm volatile("mma.sync.aligned.m16n8k16.row.col.f32.f16.f16.f32 "         \
                 "{%0,%1,%2,%3},{%4,%5,%6,%7},{%8,%9},{%0,%1,%2,%3};"         \
                 : "+f"(acc[0]), "+f"(acc[1]), "+f"(acc[2]), "+f"(acc[3])     \
                 : "r"(a0), "r"(a1), "r"(a2), "r"(a3), "r"(b0), "r"(b1))

#define CP16(dst, src, sz)                                                    \
    asm volatile("cp.async.cg.shared.global [%0], [%1], 16, %2;"              \
                 :: "r"(dst), "l"(src), "r"(sz) : "memory")
#define CP_COMMIT()  asm volatile("cp.async.commit_group;" ::: "memory")
#define CP_WAIT1()   asm volatile("cp.async.wait_group 1;" ::: "memory")

// ========= weight transpose + fp16 convert: W(K,N) fp32 -> WH(N,K) fp16 =====
__global__ __launch_bounds__(256) void transpose_wh(const float* __restrict__ W,
                                                    __half* __restrict__ WH,
                                                    int K, int N)
{
    __shared__ float t[32][33];
    int k0 = blockIdx.x * 32, n0 = blockIdx.y * 32;
    int tx = threadIdx.x & 31, ty = threadIdx.x >> 5;
#pragma unroll
    for (int i = 0; i < 4; i++) {
        int r = ty + i * 8;
        t[r][tx] = W[(size_t)(k0 + r) * N + n0 + tx];
    }
    __syncthreads();
#pragma unroll
    for (int i = 0; i < 4; i++) {
        int r = ty + i * 8;
        WH[(size_t)(n0 + r) * K + k0 + tx] = __float2half_rn(t[tx][r]);
    }
}

// ================== cp.async pipelined fp16 GEMM (m16n8k16) =================
// C = op(A' @ WT^T + bias). A (M,Kin) fp16 row-major (conv: K'=3*Kin, source
// row (m%S)+tap-1, zero-filled OOB). WT (N,Ktot) fp16 row-major.
// CTA 128x256, BK=32, 3-stage cp.async pipeline, 512 thr = 16 warps (2m x 8n),
// warp tile 64x32. fp32 accumulate. Output fp32 or fp16 (halfOut).
// Requires M%128==0, N%256==0, Kin%32==0.
#define H_STRIDE 40                      // halves per smem row (32 + 8 pad)
#define HA_HALVES (128*H_STRIDE)         // 5120
#define HB_HALVES (256*H_STRIDE)         // 10240
#define H_STAGE_BYTES ((HA_HALVES + HB_HALVES) * 2)   // 30720
#define H_SMEM_BYTES  (3 * H_STAGE_BYTES)             // 92160

__global__ __launch_bounds__(512) void gemm_h(
    const __half* __restrict__ A, const __half* __restrict__ WT,
    const float* __restrict__ bias, float* __restrict__ C32,
    __half* __restrict__ C16,
    int M, int N, int Ktot, int Kin, int sLog, int conv, int relu, int halfOut)
{
    extern __shared__ char sm[];
    const uint32_t sbase = smem_u32(sm);

    const int tid  = threadIdx.x;
    const int warp = tid >> 5, lane = tid & 31;
    const int gid  = lane >> 2, tid4 = lane & 3;
    const int wm   = warp & 1,  wn   = warp >> 1;
    const int bm   = blockIdx.y * 128;
    const int bn   = blockIdx.x * 256;
    const int S    = 1 << sLog;
    const int nst  = Ktot / 32;

    float acc[4][4][4];
#pragma unroll
    for (int i = 0; i < 4; i++)
#pragma unroll
        for (int j = 0; j < 4; j++)
#pragma unroll
            for (int r = 0; r < 4; r++) acc[i][j][r] = 0.f;

    auto issue_stage = [&](int stg) {
        const int k0    = stg * 32;
        const int tap   = conv ? (k0 / Kin) : 0;
        const int kcol  = k0 - tap * Kin;
        const int shift = conv ? (tap - 1) : 0;
        const uint32_t aB = sbase + (stg % 3) * H_STAGE_BYTES;
        const uint32_t bB = aB + HA_HALVES * 2;
        // A: 128 rows x 32 halves = 512 x 16B chunks (1/thread)
        {
            int row = tid >> 2, cq = tid & 3;
            int gm = bm + row;
            int b = gm >> sLog, l = gm & (S - 1);
            int src = l + shift;
            uint32_t sz = (src >= 0 && src < S) ? 16u : 0u;
            int srcc = (src >= 0 && src < S) ? src : 0;
            const __half* gp = A + (size_t)(((size_t)b << sLog) + srcc) * Kin + kcol + cq * 8;
            CP16(aB + (row * H_STRIDE + cq * 8) * 2, gp, sz);
        }
        // B: 256 rows x 32 halves = 1024 x 16B chunks (2/thread)
#pragma unroll
        for (int i = 0; i < 2; i++) {
            int flat = tid + i * 512;
            int nr = flat >> 2, cq = flat & 3;
            const __half* gp = WT + (size_t)(bn + nr) * Ktot + k0 + cq * 8;
            CP16(bB + (nr * H_STRIDE + cq * 8) * 2, gp, 16u);
        }
    };

    auto compute = [&](int stg) {
        const __half* aS = (const __half*)(sm + (stg % 3) * H_STAGE_BYTES);
        const __half* bS = aS + HA_HALVES;
#pragma unroll
        for (int c = 0; c < 2; c++) {
            uint32_t af[4][4];
#pragma unroll
            for (int mi = 0; mi < 4; mi++) {
                const __half* ap = &aS[(wm * 64 + mi * 16 + gid) * H_STRIDE + c * 16 + tid4 * 2];
                af[mi][0] = *(const uint32_t*)ap;
                af[mi][1] = *(const uint32_t*)(ap + 8 * H_STRIDE);
                af[mi][2] = *(const uint32_t*)(ap + 8);
                af[mi][3] = *(const uint32_t*)(ap + 8 * H_STRIDE + 8);
            }
            uint32_t bf[4][2];
#pragma unroll
            for (int nj = 0; nj < 4; nj++) {
                const __half* bp = &bS[(wn * 32 + nj * 8 + gid) * H_STRIDE + c * 16 + tid4 * 2];
                bf[nj][0] = *(const uint32_t*)bp;
                bf[nj][1] = *(const uint32_t*)(bp + 8);
            }
#pragma unroll
            for (int mi = 0; mi < 4; mi++)
#pragma unroll
                for (int nj = 0; nj < 4; nj++)
                    MMA_F16(acc[mi][nj], af[mi][0], af[mi][1], af[mi][2], af[mi][3],
                            bf[nj][0], bf[nj][1]);
        }
    };

    issue_stage(0); CP_COMMIT();
    issue_stage(1); CP_COMMIT();
    for (int s = 0; s < nst; s++) {
        CP_WAIT1();
        __syncthreads();
        if (s + 2 < nst) issue_stage(s + 2);
        CP_COMMIT();
        compute(s);
    }

#pragma unroll
    for (int mi = 0; mi < 4; mi++) {
        int gm0 = bm + wm * 64 + mi * 16 + gid;
#pragma unroll
        for (int nj = 0; nj < 4; nj++) {
            int gn = bn + wn * 32 + nj * 8 + tid4 * 2;
            float b0 = bias[gn], b1 = bias[gn + 1];
            float v00 = acc[mi][nj][0] + b0;
            float v01 = acc[mi][nj][1] + b1;
            float v10 = acc[mi][nj][2] + b0;
            float v11 = acc[mi][nj][3] + b1;
            if (relu) {
                v00 = fmaxf(v00, 0.f); v01 = fmaxf(v01, 0.f);
                v10 = fmaxf(v10, 0.f); v11 = fmaxf(v11, 0.f);
            }
            if (halfOut) {
                *(__half2*)&C16[(size_t)gm0 * N + gn]       = __floats2half2_rn(v00, v01);
                *(__half2*)&C16[(size_t)(gm0 + 8) * N + gn] = __floats2half2_rn(v10, v11);
            } else {
                C32[(size_t)gm0 * N + gn]           = v00;
                C32[(size_t)gm0 * N + gn + 1]       = v01;
                C32[(size_t)(gm0 + 8) * N + gn]     = v10;
                C32[(size_t)(gm0 + 8) * N + gn + 1] = v11;
            }
        }
    }
}

// ======================= legacy mma.sync GEMM (out-proj only, N=80) ========
#define GT_PAD 132
__global__ __launch_bounds__(256) void gemm_tc(
    const float* __restrict__ A, const float* __restrict__ W,
    const float* __restrict__ bias, float* __restrict__ C,
    int M, int N, int Ktot, int Kin, int sLog, int conv, int relu)
{
    __shared__ float As[2][2112];
    __shared__ float Bs[2][2112];
    const int tid  = threadIdx.x;
    const int warp = tid >> 5, lane = tid & 31;
    const int gid  = lane >> 2, tid4 = lane & 3;
    const int wm   = warp & 1,  wn   = warp >> 1;
    const int bm   = blockIdx.y * 128;
    const int bn   = blockIdx.x * 128;
    const int S    = 1 << sLog;
    const int nFull = (bn + 128 <= N);

    float acc[4][4][4];
#pragma unroll
    for (int i = 0; i < 4; i++)
#pragma unroll
        for (int j = 0; j < 4; j++)
#pragma unroll
            for (int r = 0; r < 4; r++) acc[i][j][r] = 0.f;

    const int nStages = Ktot / 16;
    float4 aReg[2], bReg[2];

    auto load_stage = [&](int stg) {
        const int k0   = stg * 16;
        const int tap  = conv ? (k0 / Kin) : 0;
        const int kcol = k0 - tap * Kin;
        const int shift = conv ? (tap - 1) : 0;
#pragma unroll
        for (int i = 0; i < 2; i++) {
            int s = tid + i * 256;
            int m = s >> 2, kq = s & 3;
            int gm = bm + m;
            int b = gm >> sLog;
            int l = gm & (S - 1);
            int src = l + shift;
            float4 v = make_float4(0.f, 0.f, 0.f, 0.f);
            if (src >= 0 && src < S)
                v = *(const float4*)&A[((size_t)(((size_t)b << sLog) + src)) * Kin + kcol + kq * 4];
            aReg[i] = v;
        }
#pragma unroll
        for (int i = 0; i < 2; i++) {
            int s = tid + i * 256;
            int kk = s >> 5, n4 = s & 31;
            int gn = bn + n4 * 4;
            float4 v = make_float4(0.f, 0.f, 0.f, 0.f);
            if (nFull) {
                v = *(const float4*)&W[(size_t)(k0 + kk) * N + gn];
            } else {
                const float* wr = &W[(size_t)(k0 + kk) * N];
                if (gn + 0 < N) v.x = wr[gn + 0];
                if (gn + 1 < N) v.y = wr[gn + 1];
                if (gn + 2 < N) v.z = wr[gn + 2];
                if (gn + 3 < N) v.w = wr[gn + 3];
            }
            bReg[i] = v;
        }
    };
    auto store_stage = [&](int buf) {
        float* a_s = As[buf];
        float* b_s = Bs[buf];
#pragma unroll
        for (int i = 0; i < 2; i++) {
            int s = tid + i * 256;
            int m = s >> 2, kq = s & 3;
            float va[4] = {aReg[i].x, aReg[i].y, aReg[i].z, aReg[i].w};
#pragma unroll
            for (int j = 0; j < 4; j++) {
                int k = kq * 4 + j;
                int c = k >> 3, p = k & 7;
                int slot = p & 3, comp = p >> 2;
                a_s[((c * 4 + slot) * GT_PAD + m) * 2 + comp] = __uint_as_float(f2tf32(va[j]));
            }
        }
#pragma unroll
        for (int i = 0; i < 2; i++) {
            int s = tid + i * 256;
            int kk = s >> 5, n4 = s & 31;
            float4 v = bReg[i];
            v.x = __uint_as_float(f2tf32(v.x));
            v.y = __uint_as_float(f2tf32(v.y));
            v.z = __uint_as_float(f2tf32(v.z));
            v.w = __uint_as_float(f2tf32(v.w));
            *(float4*)&b_s[kk * GT_PAD + n4 * 4] = v;
        }
    };
    auto compute = [&](int buf) {
        const float* a_s = As[buf];
        const float* b_s = Bs[buf];
#pragma unroll
        for (int c = 0; c < 2; c++) {
            uint32_t af[4][4];
#pragma unroll
            for (int mi = 0; mi < 4; mi++) {
                int mbase = wm * 64 + mi * 16;
                float2 lo = *(const float2*)&a_s[((c * 4 + tid4) * GT_PAD + mbase + gid) * 2];
                float2 hi = *(const float2*)&a_s[((c * 4 + tid4) * GT_PAD + mbase + gid + 8) * 2];
                af[mi][0] = __float_as_uint(lo.x);
                af[mi][1] = __float_as_uint(hi.x);
                af[mi][2] = __float_as_uint(lo.y);
                af[mi][3] = __float_as_uint(hi.y);
            }
            uint32_t bf[4][2];
#pragma unroll
            for (int nj = 0; nj < 4; nj++) {
                int nn = wn * 32 + nj * 8 + gid;
                bf[nj][0] = __float_as_uint(b_s[(c * 8 + tid4) * GT_PAD + nn]);
                bf[nj][1] = __float_as_uint(b_s[(c * 8 + tid4 + 4) * GT_PAD + nn]);
            }
#pragma unroll
            for (int mi = 0; mi < 4; mi++)
#pragma unroll
                for (int nj = 0; nj < 4; nj++)
                    MMA_TF32(acc[mi][nj], af[mi][0], af[mi][1], af[mi][2], af[mi][3],
                             bf[nj][0], bf[nj][1]);
        }
    };

    load_stage(0);
    store_stage(0);
    __syncthreads();
    for (int s = 0; s < nStages; s++) {
        int buf = s & 1;
        if (s + 1 < nStages) load_stage(s + 1);
        compute(buf);
        if (s + 1 < nStages) {
            store_stage(buf ^ 1);
            __syncthreads();
        }
    }
#pragma unroll
    for (int mi = 0; mi < 4; mi++) {
        int gm0 = bm + wm * 64 + mi * 16 + gid;
#pragma unroll
        for (int nj = 0; nj < 4; nj++) {
            int gn = bn + wn * 32 + nj * 8 + tid4 * 2;
            float b0 = 0.f, b1 = 0.f;
            if (bias) {
                if (gn < N)     b0 = bias[gn];
                if (gn + 1 < N) b1 = bias[gn + 1];
            }
            float v00 = acc[mi][nj][0] + b0;
            float v01 = acc[mi][nj][1] + b1;
            float v10 = acc[mi][nj][2] + b0;
            float v11 = acc[mi][nj][3] + b1;
            if (relu) {
                v00 = fmaxf(v00, 0.f); v01 = fmaxf(v01, 0.f);
                v10 = fmaxf(v10, 0.f); v11 = fmaxf(v11, 0.f);
            }
            if (gn < N) {
                C[(size_t)gm0 * N + gn]       = v00;
                C[(size_t)(gm0 + 8) * N + gn] = v10;
            }
            if (gn + 1 < N) {
                C[(size_t)gm0 * N + gn + 1]       = v01;
                C[(size_t)(gm0 + 8) * N + gn + 1] = v11;
            }
        }
    }
}

// ============== fused flash attention (fp16 in/out, tf32 mma) ==============
#define FA_PAD 68
#define FA_SMEM_FLOATS (128*FA_PAD + 64*FA_PAD + 64*FA_PAD + 128*FA_PAD + 3*128)

__device__ __forceinline__ void h8_to_f8(const __half* src, float* dst) {
    uint4 u = *(const uint4*)src;
    float2 f0 = __half22float2(*(__half2*)&u.x);
    float2 f1 = __half22float2(*(__half2*)&u.y);
    float2 f2 = __half22float2(*(__half2*)&u.z);
    float2 f3 = __half22float2(*(__half2*)&u.w);
    float4 lo = make_float4(f0.x, f0.y, f1.x, f1.y);
    float4 hi = make_float4(f2.x, f2.y, f3.x, f3.y);
    *(float4*)dst = lo;
    *(float4*)(dst + 4) = hi;
}

__global__ __launch_bounds__(256) void flash_attn(const __half* __restrict__ qkv,
                                                  const float* __restrict__ am,
                                                  __half* __restrict__ ctx, int S)
{
    extern __shared__ float smf[];
    float* Qs   = smf;
    float* Ks   = Qs + 128*FA_PAD;
    float* Vs   = Ks + 64*FA_PAD;
    float* Ss   = Vs + 64*FA_PAD;
    float* mrow = Ss + 128*FA_PAD;
    float* lrow = mrow + 128;
    float* arow = lrow + 128;

    const int tid  = threadIdx.x;
    const int warp = tid >> 5, lane = tid & 31;
    const int gid  = lane >> 2, tid4 = lane & 3;
    const int wm   = warp & 3, wn = warp >> 2;
    const int bh   = blockIdx.y;
    const int b    = bh >> 3, h = bh & 7;
    const int q0   = blockIdx.x * 128;
    const float* amb = am + b * S;
    const __half* qb = qkv + (size_t)(b * S) * 1536 + h * 64;

    // Q tile: 128 x 64 halves = 1024 chunks of 8
#pragma unroll
    for (int i = 0; i < 4; i++) {
        int idx = tid + i * 256;
        int r = idx >> 3, c8 = idx & 7;
        h8_to_f8(&qb[(size_t)(q0 + r) * 1536 + c8 * 8], &Qs[r * FA_PAD + c8 * 8]);
    }
    if (tid < 128) { mrow[tid] = -INFINITY; lrow[tid] = 0.f; }

    float oacc[2][4][4];
#pragma unroll
    for (int mi = 0; mi < 2; mi++)
#pragma unroll
        for (int nj = 0; nj < 4; nj++)
#pragma unroll
            for (int r = 0; r < 4; r++) oacc[mi][nj][r] = 0.f;

    const int nkt = S >> 6;
    for (int kt = 0; kt < nkt; kt++) {
        const int k0 = kt * 64;
        __syncthreads();
        // K,V tiles: 64 x 64 halves each = 512 chunks each
#pragma unroll
        for (int i = 0; i < 2; i++) {
            int idx = tid + i * 256;
            int r = idx >> 3, c8 = idx & 7;
            const __half* src = &qb[(size_t)(k0 + r) * 1536];
            h8_to_f8(&src[512 + c8 * 8],  &Ks[r * FA_PAD + c8 * 8]);
            h8_to_f8(&src[1024 + c8 * 8], &Vs[r * FA_PAD + c8 * 8]);
        }
        __syncthreads();

        float sacc[2][4][4];
#pragma unroll
        for (int mi = 0; mi < 2; mi++)
#pragma unroll
            for (int nj = 0; nj < 4; nj++)
#pragma unroll
                for (int r = 0; r < 4; r++) sacc[mi][nj][r] = 0.f;
#pragma unroll
        for (int kc = 0; kc < 8; kc++) {
            uint32_t af[2][4];
#pragma unroll
            for (int mi = 0; mi < 2; mi++) {
                const float* ap = &Qs[(wm * 32 + mi * 16 + gid) * FA_PAD + kc * 8 + tid4];
                af[mi][0] = __float_as_uint(ap[0]);
                af[mi][1] = __float_as_uint(ap[8 * FA_PAD]);
                af[mi][2] = __float_as_uint(ap[4]);
                af[mi][3] = __float_as_uint(ap[8 * FA_PAD + 4]);
            }
            uint32_t bf[4][2];
#pragma unroll
            for (int nj = 0; nj < 4; nj++) {
                const float* bp = &Ks[(wn * 32 + nj * 8 + gid) * FA_PAD + kc * 8 + tid4];
                bf[nj][0] = __float_as_uint(bp[0]);
                bf[nj][1] = __float_as_uint(bp[4]);
            }
#pragma unroll
            for (int mi = 0; mi < 2; mi++)
#pragma unroll
                for (int nj = 0; nj < 4; nj++)
                    MMA_TF32(sacc[mi][nj], af[mi][0], af[mi][1], af[mi][2], af[mi][3],
                             bf[nj][0], bf[nj][1]);
        }
#pragma unroll
        for (int mi = 0; mi < 2; mi++) {
            int r = wm * 32 + mi * 16 + gid;
#pragma unroll
            for (int nj = 0; nj < 4; nj++) {
                int c = wn * 32 + nj * 8 + tid4 * 2;
                float am0 = amb[k0 + c], am1 = amb[k0 + c + 1];
                Ss[r * FA_PAD + c]           = sacc[mi][nj][0] * 0.125f + am0;
                Ss[r * FA_PAD + c + 1]       = sacc[mi][nj][1] * 0.125f + am1;
                Ss[(r + 8) * FA_PAD + c]     = sacc[mi][nj][2] * 0.125f + am0;
                Ss[(r + 8) * FA_PAD + c + 1] = sacc[mi][nj][3] * 0.125f + am1;
            }
        }
        __syncthreads();
        {
            int r = tid >> 1, hf = tid & 1;
            float* srow = Ss + r * FA_PAD + hf * 32;
            float mx = -INFINITY;
#pragma unroll 8
            for (int j = 0; j < 32; j++) mx = fmaxf(mx, srow[j]);
            mx = fmaxf(mx, __shfl_xor_sync(0xffffffffu, mx, 1));
            float mold = mrow[r];
            float mnew = fmaxf(mold, mx);
            float sum = 0.f;
#pragma unroll 8
            for (int j = 0; j < 32; j++) {
                float pv = __expf(srow[j] - mnew);
                srow[j] = __uint_as_float(f2tf32(pv));
                sum += pv;
            }
            sum += __shfl_xor_sync(0xffffffffu, sum, 1);
            if (hf == 0) {
                float alpha = __expf(mold - mnew);
                lrow[r] = lrow[r] * alpha + sum;
                mrow[r] = mnew;
                arow[r] = alpha;
            }
        }
        __syncthreads();

        float al[2][2];
#pragma unroll
        for (int mi = 0; mi < 2; mi++) {
            int r = wm * 32 + mi * 16 + gid;
            al[mi][0] = arow[r];
            al[mi][1] = arow[r + 8];
        }
#pragma unroll
        for (int mi = 0; mi < 2; mi++)
#pragma unroll
            for (int nj = 0; nj < 4; nj++) {
                oacc[mi][nj][0] *= al[mi][0];
                oacc[mi][nj][1] *= al[mi][0];
                oacc[mi][nj][2] *= al[mi][1];
                oacc[mi][nj][3] *= al[mi][1];
            }
#pragma unroll
        for (int kc = 0; kc < 8; kc++) {
            uint32_t af[2][4];
#pragma unroll
            for (int mi = 0; mi < 2; mi++) {
                const float* ap = &Ss[(wm * 32 + mi * 16 + gid) * FA_PAD + kc * 8 + tid4];
                af[mi][0] = __float_as_uint(ap[0]);
                af[mi][1] = __float_as_uint(ap[8 * FA_PAD]);
                af[mi][2] = __float_as_uint(ap[4]);
                af[mi][3] = __float_as_uint(ap[8 * FA_PAD + 4]);
            }
            uint32_t bf[4][2];
#pragma unroll
            for (int nj = 0; nj < 4; nj++) {
                const float* bp = &Vs[(kc * 8 + tid4) * FA_PAD + wn * 32 + nj * 8 + gid];
                bf[nj][0] = __float_as_uint(bp[0]);
                bf[nj][1] = __float_as_uint(bp[4 * FA_PAD]);
            }
#pragma unroll
            for (int mi = 0; mi < 2; mi++)
#pragma unroll
                for (int nj = 0; nj < 4; nj++)
                    MMA_TF32(oacc[mi][nj], af[mi][0], af[mi][1], af[mi][2], af[mi][3],
                             bf[nj][0], bf[nj][1]);
        }
    }
#pragma unroll
    for (int mi = 0; mi < 2; mi++) {
        int r = wm * 32 + mi * 16 + gid;
        float inv0 = 1.f / lrow[r];
        float inv1 = 1.f / lrow[r + 8];
#pragma unroll
        for (int nj = 0; nj < 4; nj++) {
            int c = wn * 32 + nj * 8 + tid4 * 2;
            __half2* o0 = (__half2*)&ctx[(size_t)(b * S + q0 + r) * DD + h * 64 + c];
            __half2* o1 = (__half2*)&ctx[(size_t)(b * S + q0 + r + 8) * DD + h * 64 + c];
            *o0 = __floats2half2_rn(oacc[mi][nj][0] * inv0, oacc[mi][nj][1] * inv0);
            *o1 = __floats2half2_rn(oacc[mi][nj][2] * inv1, oacc[mi][nj][3] * inv1);
        }
    }
}

// ---------------- embed + positional (reference adds pos[b], not pos[t]) ----
__global__ __launch_bounds__(256) void embed_kernel(const int* __restrict__ tokens,
                                                    const float* __restrict__ emb,
                                                    float* __restrict__ x,
                                                    __half* __restrict__ xh)
{
    int i = blockIdx.x * 256 + threadIdx.x;
    if (i >= BB*TT*DD) return;
    int d  = i & (DD-1);
    int bt = i / DD;
    int b  = bt / TT;
    int tok = tokens[bt];
    int half = d >> 1;
    float den = __expf(-(float)(2*half) * (logf(10000.f) / (float)DD));
    float ang = (float)b * den;
    float posv = (d & 1) ? cosf(ang) : sinf(ang);
    float v = 2.f * emb[(size_t)tok*DD + d] + posv;
    x[i] = v;
    xh[i] = __float2half_rn(v);
}

__global__ __launch_bounds__(256) void mask_kernel(const int* __restrict__ lens,
                                                   float* __restrict__ am, int S)
{
    int i = blockIdx.x*256 + threadIdx.x;
    if (i >= BB*S) return;
    int b = i / S, t = i % S;
    am[i] = (t > lens[b]) ? -INFINITY : 0.f;
}

// ---------------- out = LN(resid + delta); writes fp32 + fp16 ----------------
__global__ __launch_bounds__(256) void add_ln_kernel(const float* __restrict__ resid,
                                                     const float* __restrict__ delta,
                                                     const float* __restrict__ g,
                                                     const float* __restrict__ bb,
                                                     float* __restrict__ out,
                                                     __half* __restrict__ outh)
{
    size_t row = blockIdx.x;
    int t = threadIdx.x;
    __shared__ float red[256];
    float v0 = resid[row*DD + t]       + delta[row*DD + t];
    float v1 = resid[row*DD + t + 256] + delta[row*DD + t + 256];
    red[t] = v0 + v1; __syncthreads();
    for (int s = 128; s > 0; s >>= 1) { if (t < s) red[t] += red[t+s]; __syncthreads(); }
    float mean = red[0] * (1.f/DD);
    __syncthreads();
    float d0 = v0 - mean, d1 = v1 - mean;
    red[t] = d0*d0 + d1*d1; __syncthreads();
    for (int s = 128; s > 0; s >>= 1) { if (t < s) red[t] += red[t+s]; __syncthreads(); }
    float var = red[0] * (1.f/DD);
    float sc = rsqrtf(var + 1e-5f);
    float o0 = d0*sc*g[t]     + bb[t];
    float o1 = d1*sc*g[t+256] + bb[t+256];
    out[row*DD + t]        = o0;
    out[row*DD + t + 256]  = o1;
    outh[row*DD + t]       = __float2half_rn(o0);
    outh[row*DD + t + 256] = __float2half_rn(o1);
}

__global__ void cumsum_kernel(const int* __restrict__ dur, int* __restrict__ cums)
{
    int b = blockIdx.x;
    if (threadIdx.x == 0) {
        int s = 0;
        for (int t = 0; t < TT; t++) { s += dur[b*TT + t]; cums[b*TT + t] = s; }
    }
}

__global__ __launch_bounds__(256) void regulate_kernel(const float* __restrict__ enc,
                                                       const int* __restrict__ cums,
                                                       const int* __restrict__ mellen,
                                                       float* __restrict__ dec_in,
                                                       __half* __restrict__ dec_inh)
{
    int bf = blockIdx.x;
    int b = bf / MELN, f = bf % MELN;
    const int* c = cums + b*TT;
    int lo = 0, hi = TT;
    while (lo < hi) { int mid = (lo + hi) >> 1; if (c[mid] <= f) lo = mid + 1; else hi = mid; }
    int idx = lo; if (idx > TT-1) idx = TT-1;
    float keep = (f <= mellen[b]) ? 1.f : 0.f;
    for (int d = threadIdx.x; d < DD; d += 256) {
        float v = enc[(size_t)(b*TT + idx)*DD + d] * keep;
        dec_in[(size_t)bf*DD + d]  = v;
        dec_inh[(size_t)bf*DD + d] = __float2half_rn(v);
    }
}

__global__ __launch_bounds__(256) void transpose_out_kernel(const float* __restrict__ t1,
                                                            float* __restrict__ out)
{
    int i = blockIdx.x*256 + threadIdx.x;
    if (i >= BB*OUTC*MELN) return;
    int f = i % MELN;
    int rest = i / MELN;
    int o = rest % OUTC;
    int b = rest / OUTC;
    out[i] = t1[(size_t)(b*MELN + f)*OUTC + o];
}

// =============================== host side ===============================
struct Ptrs {
    float *x, *ctx, *t1, *h2, *enc, *am, *am2;
    __half *xh, *qkvh, *ctxh, *hh, *wh;
    int *cums;
};

static void get_ptrs(Ptrs& p)
{
    cudaGetSymbolAddress((void**)&p.x,     g_x);
    cudaGetSymbolAddress((void**)&p.xh,    g_xh);
    cudaGetSymbolAddress((void**)&p.qkvh,  g_qkvh);
    cudaGetSymbolAddress((void**)&p.ctx,   g_ctx);
    cudaGetSymbolAddress((void**)&p.ctxh,  g_ctxh);
    cudaGetSymbolAddress((void**)&p.t1,    g_t1);
    cudaGetSymbolAddress((void**)&p.hh,    g_hh);
    cudaGetSymbolAddress((void**)&p.h2,    g_h2);
    cudaGetSymbolAddress((void**)&p.enc,   g_enc);
    cudaGetSymbolAddress((void**)&p.am,    g_am);
    cudaGetSymbolAddress((void**)&p.am2,   g_am2);
    cudaGetSymbolAddress((void**)&p.wh,    g_wh);
    cudaGetSymbolAddress((void**)&p.cums,  g_cums);
}

static const size_t FA_SMEM_BYTES = (size_t)FA_SMEM_FLOATS * sizeof(float);

static void run_layer(Ptrs& p, int S, int sLog, const float* am, const __half* whl,
                      const float* bqkv, const float* bo,
                      const float* ln1g, const float* ln1b,
                      const float* c1b,  const float* c2b,
                      const float* ln2g, const float* ln2b)
{
    const int M = BB * S;

    // qkv = xh @ Wqkv + bqkv  (fp16 out)
    gemm_h<<<dim3(6, M/128), 512, H_SMEM_BYTES>>>(p.xh, whl + WT_QKV, bqkv,
                                                  nullptr, p.qkvh,
                                                  M, 3*DD, DD, DD, sLog, 0, 0, 1);
    // flash attention -> ctxh (fp16)
    flash_attn<<<dim3(S/128, BB*HH), 256, FA_SMEM_BYTES>>>(p.qkvh, am, p.ctxh, S);
    // t1 = ctxh @ Wo + bo (fp32 out)
    gemm_h<<<dim3(2, M/128), 512, H_SMEM_BYTES>>>(p.ctxh, whl + WT_WO, bo,
                                                  p.t1, nullptr,
                                                  M, DD, DD, DD, sLog, 0, 0, 0);
    // y = LN(x + t1) -> ctx (fp32) + xh (fp16, reused as conv1 input)
    add_ln_kernel<<<M, 256>>>(p.x, p.t1, ln1g, ln1b, p.ctx, p.xh);
    // conv1 (K=3) + relu -> hh (fp16)
    gemm_h<<<dim3(8, M/128), 512, H_SMEM_BYTES>>>(p.xh, whl + WT_C1, c1b,
                                                  nullptr, p.hh,
                                                  M, INTERN, 3*DD, DD, sLog, 1, 1, 1);
    // conv2 -> h2 (fp32)
    gemm_h<<<dim3(2, M/128), 512, H_SMEM_BYTES>>>(p.hh, whl + WT_C2, c2b,
                                                  p.h2, nullptr,
                                                  M, DD, 3*INTERN, INTERN, sLog, 1, 0, 0);
    // x = LN(y + h2) -> x (fp32) + xh (fp16)
    add_ln_kernel<<<M, 256>>>(p.ctx, p.h2, ln2g, ln2b, p.x, p.xh);
}

extern "C" void kernel_launch(void* const* d_in, const int* in_sizes, int n_in,
                              void* d_out, int out_size)
{
    const int*   tokens        = (const int*)  d_in[0];
    const int*   token_lengths = (const int*)  d_in[1];
    const int*   melspec_len   = (const int*)  d_in[2];
    const int*   durations     = (const int*)  d_in[3];
    const float* emb           = (const float*)d_in[5];
    const float* ew[12]; for (int i = 0; i < 12; i++) ew[i] = (const float*)d_in[6 + i];
    const float* dw[12]; for (int i = 0; i < 12; i++) dw[i] = (const float*)d_in[18 + i];
    const float* out_w         = (const float*)d_in[30];
    const float* out_b         = (const float*)d_in[31];

    cudaFuncSetAttribute(flash_attn, cudaFuncAttributeMaxDynamicSharedMemorySize,
                         (int)FA_SMEM_BYTES);
    cudaFuncSetAttribute(gemm_h, cudaFuncAttributeMaxDynamicSharedMemorySize,
                         H_SMEM_BYTES);

    Ptrs p; get_ptrs(p);

    // ---- weight transpose + fp16 convert ----
    for (int l = 0; l < 2*LLAY; l++) {
        const float* const* w = (l < LLAY) ? ew : dw;
        int li = (l < LLAY) ? l : l - LLAY;
        __half* whl = p.wh + (size_t)l * WT_LAYER;
        transpose_wh<<<dim3(16, 48), 256>>>(w[0] + (size_t)li*DD*3*DD,
                                            whl + WT_QKV, DD, 3*DD);
        transpose_wh<<<dim3(16, 16), 256>>>(w[2] + (size_t)li*DD*DD,
                                            whl + WT_WO, DD, DD);
        transpose_wh<<<dim3(48, 64), 256>>>(w[6] + (size_t)li*3*DD*INTERN,
                                            whl + WT_C1, 3*DD, INTERN);
        transpose_wh<<<dim3(192, 16), 256>>>(w[8] + (size_t)li*3*INTERN*DD,
                                             whl + WT_C2, 3*INTERN, DD);
    }

    // ---- embed + positional + encoder mask ----
    embed_kernel<<<(BB*TT*DD + 255)/256, 256>>>(tokens, emb, p.x, p.xh);
    mask_kernel<<<(BB*TT + 255)/256, 256>>>(token_lengths, p.am, TT);

    // ---- encoder stack (S = TT) ----
    for (int l = 0; l < LLAY; l++) {
        run_layer(p, TT, 8, p.am, p.wh + (size_t)l * WT_LAYER,
                  ew[1] + (size_t)l*3*DD,  ew[3] + (size_t)l*DD,
                  ew[4] + (size_t)l*DD,    ew[5] + (size_t)l*DD,
                  ew[7] + (size_t)l*INTERN, ew[9] + (size_t)l*DD,
                  ew[10] + (size_t)l*DD,   ew[11] + (size_t)l*DD);
    }

    // ---- length regulator ----
    cudaMemcpyAsync(p.enc, p.x, (size_t)BB*TT*DD*sizeof(float), cudaMemcpyDeviceToDevice);
    cumsum_kernel<<<BB, 32>>>(durations, p.cums);
    regulate_kernel<<<BB*MELN, 256>>>(p.enc, p.cums, melspec_len, p.x, p.xh);
    mask_kernel<<<(BB*MELN + 255)/256, 256>>>(melspec_len, p.am2, MELN);

    // ---- decoder stack (S = MELN) ----
    for (int l = 0; l < LLAY; l++) {
        run_layer(p, MELN, 10, p.am2, p.wh + (size_t)(LLAY + l) * WT_LAYER,
                  dw[1] + (size_t)l*3*DD,  dw[3] + (size_t)l*DD,
                  dw[4] + (size_t)l*DD,    dw[5] + (size_t)l*DD,
                  dw[7] + (size_t)l*INTERN, dw[9] + (size_t)l*DD,
                  dw[10] + (size_t)l*DD,   dw[11] + (size_t)l*DD);
    }

    // ---- output projection (N=80, legacy fp32 path) + transpose ----
    gemm_tc<<<dim3(1, BB*MELN/128), 256>>>(p.x, out_w, out_b, p.t1,
                                           BB*MELN, OUTC, DD, DD, 10, 0, 0);
    transpose_out_kernel<<<(BB*OUTC*MELN + 255)/256, 256>>>(p.t1, (float*)d_out);
}

// round 10
// speedup vs baseline: 8.2171x; 1.0622x over previous
#include <cuda_runtime.h>
#include <cuda_fp16.h>
#include <math.h>
#include <stdint.h>

// ---------------- problem constants ----------------
#define BB    16
#define TT    256
#define MELN  1024
#define DD    512
#define HH    8
#define DHD   64
#define LLAY  4
#define INTERN 2048
#define OUTC  80

// ---------------- scratch (device globals; no allocation allowed) ----------
__device__ float  g_x   [(size_t)BB*MELN*DD];       // fp32 activations (residual)
__device__ __half g_xh  [(size_t)BB*MELN*DD];       // fp16 GEMM-input copy
__device__ __half g_qkvh[(size_t)BB*MELN*3*DD];     // qkv (fp16)
__device__ float  g_ctx [(size_t)BB*MELN*DD];       // LN1 output y (fp32)
__device__ __half g_ctxh[(size_t)BB*MELN*DD];       // attn ctx (fp16)
__device__ float  g_t1  [(size_t)BB*MELN*DD];       // wo out / final proj (fp32)
__device__ __half g_hh  [(size_t)BB*MELN*INTERN];   // conv1 out (fp16)
__device__ float  g_h2  [(size_t)BB*MELN*DD];       // conv2 out (fp32)
__device__ float  g_enc [(size_t)BB*TT*DD];
__device__ float  g_am  [BB*TT];
__device__ float  g_am2 [BB*MELN];
__device__ int    g_cums[BB*TT];
#define WT_QKV   0
#define WT_WO    786432
#define WT_C1    1048576
#define WT_C2    4194304
#define WT_LAYER 7340032
__device__ __half g_wh [(size_t)WT_LAYER * 8];

// ---------------- small helpers ----------------
__device__ __forceinline__ uint32_t f2tf32(float x) {
    uint32_t u;
    asm("cvt.rna.tf32.f32 %0, %1;" : "=r"(u) : "f"(x));
    return u;
}
__device__ __forceinline__ uint32_t smem_u32(const void* p) {
    uint32_t a;
    asm("{ .reg .u64 t; cvta.to.shared.u64 t, %1; cvt.u32.u64 %0, t; }" : "=r"(a) : "l"(p));
    return a;
}

#define MMA_TF32(acc, a0,a1,a2,a3, b0,b1)                                     \
    asm volatile("mma.sync.aligned.m16n8k8.row.col.f32.tf32.tf32.f32 "        \
                 "{%0,%1,%2,%3},{%4,%5,%6,%7},{%8,%9},{%0,%1,%2,%3};"         \
                 : "+f"(acc[0]), "+f"(acc[1]), "+f"(acc[2]), "+f"(acc[3])     \
                 : "r"(a0), "r"(a1), "r"(a2), "r"(a3), "r"(b0), "r"(b1))

#define MMA_F16(acc, a0,a1,a2,a3, b0,b1)                                      \
    asm volatile("mma.sync.aligned.m16n8k16.row.col.f32.f16.f16.f32 "         \
                 "{%0,%1,%2,%3},{%4,%5,%6,%7},{%8,%9},{%0,%1,%2,%3};"         \
                 : "+f"(acc[0]), "+f"(acc[1]), "+f"(acc[2]), "+f"(acc[3])     \
                 : "r"(a0), "r"(a1), "r"(a2), "r"(a3), "r"(b0), "r"(b1))

#define LDM_X4(r0,r1,r2,r3, addr)                                             \
    asm volatile("ldmatrix.sync.aligned.m8n8.x4.shared.b16 {%0,%1,%2,%3}, [%4];" \
                 : "=r"(r0), "=r"(r1), "=r"(r2), "=r"(r3) : "r"(addr))

#define CP16(dst, src, sz)                                                    \
    asm volatile("cp.async.cg.shared.global [%0], [%1], 16, %2;"              \
                 :: "r"(dst), "l"(src), "r"(sz) : "memory")
#define CP_COMMIT()  asm volatile("cp.async.commit_group;" ::: "memory")
#define CP_WAIT1()   asm volatile("cp.async.wait_group 1;" ::: "memory")

// ========= weight transpose + fp16 convert (batched over layers via z) =====
__global__ __launch_bounds__(256) void transpose_wh(const float* __restrict__ W,
                                                    __half* __restrict__ WH,
                                                    int K, int N,
                                                    size_t wStride, size_t whStride)
{
    const float* Wl = W + (size_t)blockIdx.z * wStride;
    __half* WHl = WH + (size_t)blockIdx.z * whStride;
    __shared__ float t[32][33];
    int k0 = blockIdx.x * 32, n0 = blockIdx.y * 32;
    int tx = threadIdx.x & 31, ty = threadIdx.x >> 5;
#pragma unroll
    for (int i = 0; i < 4; i++) {
        int r = ty + i * 8;
        t[r][tx] = Wl[(size_t)(k0 + r) * N + n0 + tx];
    }
    __syncthreads();
#pragma unroll
    for (int i = 0; i < 4; i++) {
        int r = ty + i * 8;
        WHl[(size_t)(n0 + r) * K + k0 + tx] = __float2half_rn(t[tx][r]);
    }
}

// ========== cp.async pipelined fp16 GEMM (m16n8k16 + ldmatrix) =============
// C = op(A' @ WT^T + bias). A (M,Kin) fp16 row-major (conv: K'=3*Kin, source
// row (m%S)+tap-1, zero-filled OOB). WT (N,Ktot) fp16 row-major.
// CTA 128x256, BK=32, 3-stage cp.async pipeline, 512 thr = 16 warps (2m x 8n),
// warp tile 64x32. fp32 accumulate. Requires M%128==0, N%256==0, Kin%32==0.
#define H_STRIDE 40                      // halves per smem row (32 + 8 pad)
#define HA_HALVES (128*H_STRIDE)         // 5120
#define HB_HALVES (256*H_STRIDE)         // 10240
#define H_STAGE_BYTES ((HA_HALVES + HB_HALVES) * 2)   // 30720
#define H_SMEM_BYTES  (3 * H_STAGE_BYTES)             // 92160

__global__ __launch_bounds__(512) void gemm_h(
    const __half* __restrict__ A, const __half* __restrict__ WT,
    const float* __restrict__ bias, float* __restrict__ C32,
    __half* __restrict__ C16,
    int M, int N, int Ktot, int Kin, int sLog, int conv, int relu, int halfOut)
{
    extern __shared__ char sm[];
    const uint32_t sbase = smem_u32(sm);

    const int tid  = threadIdx.x;
    const int warp = tid >> 5, lane = tid & 31;
    const int gid  = lane >> 2, tid4 = lane & 3;
    const int wm   = warp & 1,  wn   = warp >> 1;
    const int bm   = blockIdx.y * 128;
    const int bn   = blockIdx.x * 256;
    const int S    = 1 << sLog;
    const int nst  = Ktot / 32;

    // ldmatrix lane roles (shared by A and B x4 loads)
    const int lrow = lane & 7;
    const int lsel = lane >> 3;            // matrix index 0..3
    const int rowOffA = (lsel & 1) * 8;    // +8 m-rows for matrices 1,3
    const int colOffA = (lsel >> 1) * 8;   // +8 k for matrices 2,3
    const int rowOffB = (lsel >> 1) * 8;   // +8 n-rows for matrices 2,3
    const int colOffB = (lsel & 1) * 8;    // +8 k for matrices 1,3

    float acc[4][4][4];
#pragma unroll
    for (int i = 0; i < 4; i++)
#pragma unroll
        for (int j = 0; j < 4; j++)
#pragma unroll
            for (int r = 0; r < 4; r++) acc[i][j][r] = 0.f;

    auto issue_stage = [&](int stg) {
        const int k0    = stg * 32;
        const int tap   = conv ? (k0 / Kin) : 0;
        const int kcol  = k0 - tap * Kin;
        const int shift = conv ? (tap - 1) : 0;
        const uint32_t aB = sbase + (stg % 3) * H_STAGE_BYTES;
        const uint32_t bB = aB + HA_HALVES * 2;
        {
            int row = tid >> 2, cq = tid & 3;
            int gm = bm + row;
            int b = gm >> sLog, l = gm & (S - 1);
            int src = l + shift;
            uint32_t sz = (src >= 0 && src < S) ? 16u : 0u;
            int srcc = (src >= 0 && src < S) ? src : 0;
            const __half* gp = A + (size_t)(((size_t)b << sLog) + srcc) * Kin + kcol + cq * 8;
            CP16(aB + (row * H_STRIDE + cq * 8) * 2, gp, sz);
        }
#pragma unroll
        for (int i = 0; i < 2; i++) {
            int flat = tid + i * 512;
            int nr = flat >> 2, cq = flat & 3;
            const __half* gp = WT + (size_t)(bn + nr) * Ktot + k0 + cq * 8;
            CP16(bB + (nr * H_STRIDE + cq * 8) * 2, gp, 16u);
        }
    };

    auto compute = [&](int stg) {
        const uint32_t aB = sbase + (stg % 3) * H_STAGE_BYTES;
        const uint32_t bB = aB + HA_HALVES * 2;
#pragma unroll
        for (int c = 0; c < 2; c++) {
            uint32_t af[4][4];
#pragma unroll
            for (int mi = 0; mi < 4; mi++) {
                uint32_t ap = aB + ((wm * 64 + mi * 16 + lrow + rowOffA) * H_STRIDE
                                    + c * 16 + colOffA) * 2;
                LDM_X4(af[mi][0], af[mi][1], af[mi][2], af[mi][3], ap);
            }
            uint32_t bf[4][2];
#pragma unroll
            for (int njp = 0; njp < 2; njp++) {
                uint32_t bp = bB + ((wn * 32 + njp * 16 + lrow + rowOffB) * H_STRIDE
                                    + c * 16 + colOffB) * 2;
                uint32_t r0, r1, r2, r3;
                LDM_X4(r0, r1, r2, r3, bp);
                bf[njp * 2][0]     = r0;
                bf[njp * 2][1]     = r1;
                bf[njp * 2 + 1][0] = r2;
                bf[njp * 2 + 1][1] = r3;
            }
#pragma unroll
            for (int mi = 0; mi < 4; mi++)
#pragma unroll
                for (int nj = 0; nj < 4; nj++)
                    MMA_F16(acc[mi][nj], af[mi][0], af[mi][1], af[mi][2], af[mi][3],
                            bf[nj][0], bf[nj][1]);
        }
    };

    issue_stage(0); CP_COMMIT();
    issue_stage(1); CP_COMMIT();
    for (int s = 0; s < nst; s++) {
        CP_WAIT1();
        __syncthreads();
        if (s + 2 < nst) issue_stage(s + 2);
        CP_COMMIT();
        compute(s);
    }

#pragma unroll
    for (int mi = 0; mi < 4; mi++) {
        int gm0 = bm + wm * 64 + mi * 16 + gid;
#pragma unroll
        for (int nj = 0; nj < 4; nj++) {
            int gn = bn + wn * 32 + nj * 8 + tid4 * 2;
            float b0 = bias[gn], b1 = bias[gn + 1];
            float v00 = acc[mi][nj][0] + b0;
            float v01 = acc[mi][nj][1] + b1;
            float v10 = acc[mi][nj][2] + b0;
            float v11 = acc[mi][nj][3] + b1;
            if (relu) {
                v00 = fmaxf(v00, 0.f); v01 = fmaxf(v01, 0.f);
                v10 = fmaxf(v10, 0.f); v11 = fmaxf(v11, 0.f);
            }
            if (halfOut) {
                *(__half2*)&C16[(size_t)gm0 * N + gn]       = __floats2half2_rn(v00, v01);
                *(__half2*)&C16[(size_t)(gm0 + 8) * N + gn] = __floats2half2_rn(v10, v11);
            } else {
                C32[(size_t)gm0 * N + gn]           = v00;
                C32[(size_t)gm0 * N + gn + 1]       = v01;
                C32[(size_t)(gm0 + 8) * N + gn]     = v10;
                C32[(size_t)(gm0 + 8) * N + gn + 1] = v11;
            }
        }
    }
}

// ======================= legacy mma.sync GEMM (out-proj only, N=80) ========
#define GT_PAD 132
__global__ __launch_bounds__(256) void gemm_tc(
    const float* __restrict__ A, const float* __restrict__ W,
    const float* __restrict__ bias, float* __restrict__ C,
    int M, int N, int Ktot, int Kin, int sLog, int conv, int relu)
{
    __shared__ float As[2][2112];
    __shared__ float Bs[2][2112];
    const int tid  = threadIdx.x;
    const int warp = tid >> 5, lane = tid & 31;
    const int gid  = lane >> 2, tid4 = lane & 3;
    const int wm   = warp & 1,  wn   = warp >> 1;
    const int bm   = blockIdx.y * 128;
    const int bn   = blockIdx.x * 128;
    const int S    = 1 << sLog;
    const int nFull = (bn + 128 <= N);

    float acc[4][4][4];
#pragma unroll
    for (int i = 0; i < 4; i++)
#pragma unroll
        for (int j = 0; j < 4; j++)
#pragma unroll
            for (int r = 0; r < 4; r++) acc[i][j][r] = 0.f;

    const int nStages = Ktot / 16;
    float4 aReg[2], bReg[2];

    auto load_stage = [&](int stg) {
        const int k0   = stg * 16;
        const int tap  = conv ? (k0 / Kin) : 0;
        const int kcol = k0 - tap * Kin;
        const int shift = conv ? (tap - 1) : 0;
#pragma unroll
        for (int i = 0; i < 2; i++) {
            int s = tid + i * 256;
            int m = s >> 2, kq = s & 3;
            int gm = bm + m;
            int b = gm >> sLog;
            int l = gm & (S - 1);
            int src = l + shift;
            float4 v = make_float4(0.f, 0.f, 0.f, 0.f);
            if (src >= 0 && src < S)
                v = *(const float4*)&A[((size_t)(((size_t)b << sLog) + src)) * Kin + kcol + kq * 4];
            aReg[i] = v;
        }
#pragma unroll
        for (int i = 0; i < 2; i++) {
            int s = tid + i * 256;
            int kk = s >> 5, n4 = s & 31;
            int gn = bn + n4 * 4;
            float4 v = make_float4(0.f, 0.f, 0.f, 0.f);
            if (nFull) {
                v = *(const float4*)&W[(size_t)(k0 + kk) * N + gn];
            } else {
                const float* wr = &W[(size_t)(k0 + kk) * N];
                if (gn + 0 < N) v.x = wr[gn + 0];
                if (gn + 1 < N) v.y = wr[gn + 1];
                if (gn + 2 < N) v.z = wr[gn + 2];
                if (gn + 3 < N) v.w = wr[gn + 3];
            }
            bReg[i] = v;
        }
    };
    auto store_stage = [&](int buf) {
        float* a_s = As[buf];
        float* b_s = Bs[buf];
#pragma unroll
        for (int i = 0; i < 2; i++) {
            int s = tid + i * 256;
            int m = s >> 2, kq = s & 3;
            float va[4] = {aReg[i].x, aReg[i].y, aReg[i].z, aReg[i].w};
#pragma unroll
            for (int j = 0; j < 4; j++) {
                int k = kq * 4 + j;
                int c = k >> 3, p = k & 7;
                int slot = p & 3, comp = p >> 2;
                a_s[((c * 4 + slot) * GT_PAD + m) * 2 + comp] = __uint_as_float(f2tf32(va[j]));
            }
        }
#pragma unroll
        for (int i = 0; i < 2; i++) {
            int s = tid + i * 256;
            int kk = s >> 5, n4 = s & 31;
            float4 v = bReg[i];
            v.x = __uint_as_float(f2tf32(v.x));
            v.y = __uint_as_float(f2tf32(v.y));
            v.z = __uint_as_float(f2tf32(v.z));
            v.w = __uint_as_float(f2tf32(v.w));
            *(float4*)&b_s[kk * GT_PAD + n4 * 4] = v;
        }
    };
    auto compute = [&](int buf) {
        const float* a_s = As[buf];
        const float* b_s = Bs[buf];
#pragma unroll
        for (int c = 0; c < 2; c++) {
            uint32_t af[4][4];
#pragma unroll
            for (int mi = 0; mi < 4; mi++) {
                int mbase = wm * 64 + mi * 16;
                float2 lo = *(const float2*)&a_s[((c * 4 + tid4) * GT_PAD + mbase + gid) * 2];
                float2 hi = *(const float2*)&a_s[((c * 4 + tid4) * GT_PAD + mbase + gid + 8) * 2];
                af[mi][0] = __float_as_uint(lo.x);
                af[mi][1] = __float_as_uint(hi.x);
                af[mi][2] = __float_as_uint(lo.y);
                af[mi][3] = __float_as_uint(hi.y);
            }
            uint32_t bf[4][2];
#pragma unroll
            for (int nj = 0; nj < 4; nj++) {
                int nn = wn * 32 + nj * 8 + gid;
                bf[nj][0] = __float_as_uint(b_s[(c * 8 + tid4) * GT_PAD + nn]);
                bf[nj][1] = __float_as_uint(b_s[(c * 8 + tid4 + 4) * GT_PAD + nn]);
            }
#pragma unroll
            for (int mi = 0; mi < 4; mi++)
#pragma unroll
                for (int nj = 0; nj < 4; nj++)
                    MMA_TF32(acc[mi][nj], af[mi][0], af[mi][1], af[mi][2], af[mi][3],
                             bf[nj][0], bf[nj][1]);
        }
    };

    load_stage(0);
    store_stage(0);
    __syncthreads();
    for (int s = 0; s < nStages; s++) {
        int buf = s & 1;
        if (s + 1 < nStages) load_stage(s + 1);
        compute(buf);
        if (s + 1 < nStages) {
            store_stage(buf ^ 1);
            __syncthreads();
        }
    }
#pragma unroll
    for (int mi = 0; mi < 4; mi++) {
        int gm0 = bm + wm * 64 + mi * 16 + gid;
#pragma unroll
        for (int nj = 0; nj < 4; nj++) {
            int gn = bn + wn * 32 + nj * 8 + tid4 * 2;
            float b0 = 0.f, b1 = 0.f;
            if (bias) {
                if (gn < N)     b0 = bias[gn];
                if (gn + 1 < N) b1 = bias[gn + 1];
            }
            float v00 = acc[mi][nj][0] + b0;
            float v01 = acc[mi][nj][1] + b1;
            float v10 = acc[mi][nj][2] + b0;
            float v11 = acc[mi][nj][3] + b1;
            if (relu) {
                v00 = fmaxf(v00, 0.f); v01 = fmaxf(v01, 0.f);
                v10 = fmaxf(v10, 0.f); v11 = fmaxf(v11, 0.f);
            }
            if (gn < N) {
                C[(size_t)gm0 * N + gn]       = v00;
                C[(size_t)(gm0 + 8) * N + gn] = v10;
            }
            if (gn + 1 < N) {
                C[(size_t)gm0 * N + gn + 1]       = v01;
                C[(size_t)(gm0 + 8) * N + gn + 1] = v11;
            }
        }
    }
}

// ============== fused flash attention (fp16 in/out, tf32 mma) ==============
#define FA_PAD 68
#define FA_SMEM_FLOATS (128*FA_PAD + 64*FA_PAD + 64*FA_PAD + 128*FA_PAD + 3*128)

__device__ __forceinline__ void h8_to_f8(const __half* src, float* dst) {
    uint4 u = *(const uint4*)src;
    float2 f0 = __half22float2(*(__half2*)&u.x);
    float2 f1 = __half22float2(*(__half2*)&u.y);
    float2 f2 = __half22float2(*(__half2*)&u.z);
    float2 f3 = __half22float2(*(__half2*)&u.w);
    *(float4*)dst       = make_float4(f0.x, f0.y, f1.x, f1.y);
    *(float4*)(dst + 4) = make_float4(f2.x, f2.y, f3.x, f3.y);
}

__global__ __launch_bounds__(256) void flash_attn(const __half* __restrict__ qkv,
                                                  const float* __restrict__ am,
                                                  __half* __restrict__ ctx, int S)
{
    extern __shared__ float smf[];
    float* Qs   = smf;
    float* Ks   = Qs + 128*FA_PAD;
    float* Vs   = Ks + 64*FA_PAD;
    float* Ss   = Vs + 64*FA_PAD;
    float* mrow = Ss + 128*FA_PAD;
    float* lrow = mrow + 128;
    float* arow = lrow + 128;

    const int tid  = threadIdx.x;
    const int warp = tid >> 5, lane = tid & 31;
    const int gid  = lane >> 2, tid4 = lane & 3;
    const int wm   = warp & 3, wn = warp >> 2;
    const int bh   = blockIdx.y;
    const int b    = bh >> 3, h = bh & 7;
    const int q0   = blockIdx.x * 128;
    const float* amb = am + b * S;
    const __half* qb = qkv + (size_t)(b * S) * 1536 + h * 64;

#pragma unroll
    for (int i = 0; i < 4; i++) {
        int idx = tid + i * 256;
        int r = idx >> 3, c8 = idx & 7;
        h8_to_f8(&qb[(size_t)(q0 + r) * 1536 + c8 * 8], &Qs[r * FA_PAD + c8 * 8]);
    }
    if (tid < 128) { mrow[tid] = -INFINITY; lrow[tid] = 0.f; }

    float oacc[2][4][4];
#pragma unroll
    for (int mi = 0; mi < 2; mi++)
#pragma unroll
        for (int nj = 0; nj < 4; nj++)
#pragma unroll
            for (int r = 0; r < 4; r++) oacc[mi][nj][r] = 0.f;

    const int nkt = S >> 6;
    for (int kt = 0; kt < nkt; kt++) {
        const int k0 = kt * 64;
        __syncthreads();
#pragma unroll
        for (int i = 0; i < 2; i++) {
            int idx = tid + i * 256;
            int r = idx >> 3, c8 = idx & 7;
            const __half* src = &qb[(size_t)(k0 + r) * 1536];
            h8_to_f8(&src[512 + c8 * 8],  &Ks[r * FA_PAD + c8 * 8]);
            h8_to_f8(&src[1024 + c8 * 8], &Vs[r * FA_PAD + c8 * 8]);
        }
        __syncthreads();

        float sacc[2][4][4];
#pragma unroll
        for (int mi = 0; mi < 2; mi++)
#pragma unroll
            for (int nj = 0; nj < 4; nj++)
#pragma unroll
                for (int r = 0; r < 4; r++) sacc[mi][nj][r] = 0.f;
#pragma unroll
        for (int kc = 0; kc < 8; kc++) {
            uint32_t af[2][4];
#pragma unroll
            for (int mi = 0; mi < 2; mi++) {
                const float* ap = &Qs[(wm * 32 + mi * 16 + gid) * FA_PAD + kc * 8 + tid4];
                af[mi][0] = __float_as_uint(ap[0]);
                af[mi][1] = __float_as_uint(ap[8 * FA_PAD]);
                af[mi][2] = __float_as_uint(ap[4]);
                af[mi][3] = __float_as_uint(ap[8 * FA_PAD + 4]);
            }
            uint32_t bf[4][2];
#pragma unroll
            for (int nj = 0; nj < 4; nj++) {
                const float* bp = &Ks[(wn * 32 + nj * 8 + gid) * FA_PAD + kc * 8 + tid4];
                bf[nj][0] = __float_as_uint(bp[0]);
                bf[nj][1] = __float_as_uint(bp[4]);
            }
#pragma unroll
            for (int mi = 0; mi < 2; mi++)
#pragma unroll
                for (int nj = 0; nj < 4; nj++)
                    MMA_TF32(sacc[mi][nj], af[mi][0], af[mi][1], af[mi][2], af[mi][3],
                             bf[nj][0], bf[nj][1]);
        }
#pragma unroll
        for (int mi = 0; mi < 2; mi++) {
            int r = wm * 32 + mi * 16 + gid;
#pragma unroll
            for (int nj = 0; nj < 4; nj++) {
                int c = wn * 32 + nj * 8 + tid4 * 2;
                float am0 = amb[k0 + c], am1 = amb[k0 + c + 1];
                Ss[r * FA_PAD + c]           = sacc[mi][nj][0] * 0.125f + am0;
                Ss[r * FA_PAD + c + 1]       = sacc[mi][nj][1] * 0.125f + am1;
                Ss[(r + 8) * FA_PAD + c]     = sacc[mi][nj][2] * 0.125f + am0;
                Ss[(r + 8) * FA_PAD + c + 1] = sacc[mi][nj][3] * 0.125f + am1;
            }
        }
        __syncthreads();
        {
            int r = tid >> 1, hf = tid & 1;
            float* srow = Ss + r * FA_PAD + hf * 32;
            float mx = -INFINITY;
#pragma unroll 8
            for (int j = 0; j < 32; j++) mx = fmaxf(mx, srow[j]);
            mx = fmaxf(mx, __shfl_xor_sync(0xffffffffu, mx, 1));
            float mold = mrow[r];
            float mnew = fmaxf(mold, mx);
            float sum = 0.f;
#pragma unroll 8
            for (int j = 0; j < 32; j++) {
                float pv = __expf(srow[j] - mnew);
                srow[j] = __uint_as_float(f2tf32(pv));
                sum += pv;
            }
            sum += __shfl_xor_sync(0xffffffffu, sum, 1);
            if (hf == 0) {
                float alpha = __expf(mold - mnew);
                lrow[r] = lrow[r] * alpha + sum;
                mrow[r] = mnew;
                arow[r] = alpha;
            }
        }
        __syncthreads();

        float al[2][2];
#pragma unroll
        for (int mi = 0; mi < 2; mi++) {
            int r = wm * 32 + mi * 16 + gid;
            al[mi][0] = arow[r];
            al[mi][1] = arow[r + 8];
        }
#pragma unroll
        for (int mi = 0; mi < 2; mi++)
#pragma unroll
            for (int nj = 0; nj < 4; nj++) {
                oacc[mi][nj][0] *= al[mi][0];
                oacc[mi][nj][1] *= al[mi][0];
                oacc[mi][nj][2] *= al[mi][1];
                oacc[mi][nj][3] *= al[mi][1];
            }
#pragma unroll
        for (int kc = 0; kc < 8; kc++) {
            uint32_t af[2][4];
#pragma unroll
            for (int mi = 0; mi < 2; mi++) {
                const float* ap = &Ss[(wm * 32 + mi * 16 + gid) * FA_PAD + kc * 8 + tid4];
                af[mi][0] = __float_as_uint(ap[0]);
                af[mi][1] = __float_as_uint(ap[8 * FA_PAD]);
                af[mi][2] = __float_as_uint(ap[4]);
                af[mi][3] = __float_as_uint(ap[8 * FA_PAD + 4]);
            }
            uint32_t bf[4][2];
#pragma unroll
            for (int nj = 0; nj < 4; nj++) {
                const float* bp = &Vs[(kc * 8 + tid4) * FA_PAD + wn * 32 + nj * 8 + gid];
                bf[nj][0] = __float_as_uint(bp[0]);
                bf[nj][1] = __float_as_uint(bp[4 * FA_PAD]);
            }
#pragma unroll
            for (int mi = 0; mi < 2; mi++)
#pragma unroll
                for (int nj = 0; nj < 4; nj++)
                    MMA_TF32(oacc[mi][nj], af[mi][0], af[mi][1], af[mi][2], af[mi][3],
                             bf[nj][0], bf[nj][1]);
        }
    }
#pragma unroll
    for (int mi = 0; mi < 2; mi++) {
        int r = wm * 32 + mi * 16 + gid;
        float inv0 = 1.f / lrow[r];
        float inv1 = 1.f / lrow[r + 8];
#pragma unroll
        for (int nj = 0; nj < 4; nj++) {
            int c = wn * 32 + nj * 8 + tid4 * 2;
            __half2* o0 = (__half2*)&ctx[(size_t)(b * S + q0 + r) * DD + h * 64 + c];
            __half2* o1 = (__half2*)&ctx[(size_t)(b * S + q0 + r + 8) * DD + h * 64 + c];
            *o0 = __floats2half2_rn(oacc[mi][nj][0] * inv0, oacc[mi][nj][1] * inv0);
            *o1 = __floats2half2_rn(oacc[mi][nj][2] * inv1, oacc[mi][nj][3] * inv1);
        }
    }
}

// ---------------- embed + positional (reference adds pos[b], not pos[t]) ----
__global__ __launch_bounds__(256) void embed_kernel(const int* __restrict__ tokens,
                                                    const float* __restrict__ emb,
                                                    float* __restrict__ x,
                                                    __half* __restrict__ xh)
{
    int i = blockIdx.x * 256 + threadIdx.x;
    if (i >= BB*TT*DD) return;
    int d  = i & (DD-1);
    int bt = i / DD;
    int b  = bt / TT;
    int tok = tokens[bt];
    int half = d >> 1;
    float den = __expf(-(float)(2*half) * (logf(10000.f) / (float)DD));
    float ang = (float)b * den;
    float posv = (d & 1) ? cosf(ang) : sinf(ang);
    float v = 2.f * emb[(size_t)tok*DD + d] + posv;
    x[i] = v;
    xh[i] = __float2half_rn(v);
}

__global__ __launch_bounds__(256) void mask_kernel(const int* __restrict__ lens,
                                                   float* __restrict__ am, int S)
{
    int i = blockIdx.x*256 + threadIdx.x;
    if (i >= BB*S) return;
    int b = i / S, t = i % S;
    am[i] = (t > lens[b]) ? -INFINITY : 0.f;
}

__global__ __launch_bounds__(256) void add_ln_kernel(const float* __restrict__ resid,
                                                     const float* __restrict__ delta,
                                                     const float* __restrict__ g,
                                                     const float* __restrict__ bb,
                                                     float* __restrict__ out,
                                                     __half* __restrict__ outh)
{
    size_t row = blockIdx.x;
    int t = threadIdx.x;
    __shared__ float red[256];
    float v0 = resid[row*DD + t]       + delta[row*DD + t];
    float v1 = resid[row*DD + t + 256] + delta[row*DD + t + 256];
    red[t] = v0 + v1; __syncthreads();
    for (int s = 128; s > 0; s >>= 1) { if (t < s) red[t] += red[t+s]; __syncthreads(); }
    float mean = red[0] * (1.f/DD);
    __syncthreads();
    float d0 = v0 - mean, d1 = v1 - mean;
    red[t] = d0*d0 + d1*d1; __syncthreads();
    for (int s = 128; s > 0; s >>= 1) { if (t < s) red[t] += red[t+s]; __syncthreads(); }
    float var = red[0] * (1.f/DD);
    float sc = rsqrtf(var + 1e-5f);
    float o0 = d0*sc*g[t]     + bb[t];
    float o1 = d1*sc*g[t+256] + bb[t+256];
    out[row*DD + t]        = o0;
    out[row*DD + t + 256]  = o1;
    outh[row*DD + t]       = __float2half_rn(o0);
    outh[row*DD + t + 256] = __float2half_rn(o1);
}

__global__ void cumsum_kernel(const int* __restrict__ dur, int* __restrict__ cums)
{
    int b = blockIdx.x;
    if (threadIdx.x == 0) {
        int s = 0;
        for (int t = 0; t < TT; t++) { s += dur[b*TT + t]; cums[b*TT + t] = s; }
    }
}

__global__ __launch_bounds__(256) void regulate_kernel(const float* __restrict__ enc,
                                                       const int* __restrict__ cums,
                                                       const int* __restrict__ mellen,
                                                       float* __restrict__ dec_in,
                                                       __half* __restrict__ dec_inh)
{
    int bf = blockIdx.x;
    int b = bf / MELN, f = bf % MELN;
    const int* c = cums + b*TT;
    int lo = 0, hi = TT;
    while (lo < hi) { int mid = (lo + hi) >> 1; if (c[mid] <= f) lo = mid + 1; else hi = mid; }
    int idx = lo; if (idx > TT-1) idx = TT-1;
    float keep = (f <= mellen[b]) ? 1.f : 0.f;
    for (int d = threadIdx.x; d < DD; d += 256) {
        float v = enc[(size_t)(b*TT + idx)*DD + d] * keep;
        dec_in[(size_t)bf*DD + d]  = v;
        dec_inh[(size_t)bf*DD + d] = __float2half_rn(v);
    }
}

__global__ __launch_bounds__(256) void transpose_out_kernel(const float* __restrict__ t1,
                                                            float* __restrict__ out)
{
    int i = blockIdx.x*256 + threadIdx.x;
    if (i >= BB*OUTC*MELN) return;
    int f = i % MELN;
    int rest = i / MELN;
    int o = rest % OUTC;
    int b = rest / OUTC;
    out[i] = t1[(size_t)(b*MELN + f)*OUTC + o];
}

// =============================== host side ===============================
struct Ptrs {
    float *x, *ctx, *t1, *h2, *enc, *am, *am2;
    __half *xh, *qkvh, *ctxh, *hh, *wh;
    int *cums;
};

static void get_ptrs(Ptrs& p)
{
    cudaGetSymbolAddress((void**)&p.x,     g_x);
    cudaGetSymbolAddress((void**)&p.xh,    g_xh);
    cudaGetSymbolAddress((void**)&p.qkvh,  g_qkvh);
    cudaGetSymbolAddress((void**)&p.ctx,   g_ctx);
    cudaGetSymbolAddress((void**)&p.ctxh,  g_ctxh);
    cudaGetSymbolAddress((void**)&p.t1,    g_t1);
    cudaGetSymbolAddress((void**)&p.hh,    g_hh);
    cudaGetSymbolAddress((void**)&p.h2,    g_h2);
    cudaGetSymbolAddress((void**)&p.enc,   g_enc);
    cudaGetSymbolAddress((void**)&p.am,    g_am);
    cudaGetSymbolAddress((void**)&p.am2,   g_am2);
    cudaGetSymbolAddress((void**)&p.wh,    g_wh);
    cudaGetSymbolAddress((void**)&p.cums,  g_cums);
}

static const size_t FA_SMEM_BYTES = (size_t)FA_SMEM_FLOATS * sizeof(float);

static void run_layer(Ptrs& p, int S, int sLog, const float* am, const __half* whl,
                      const float* bqkv, const float* bo,
                      const float* ln1g, const float* ln1b,
                      const float* c1b,  const float* c2b,
                      const float* ln2g, const float* ln2b)
{
    const int M = BB * S;

    gemm_h<<<dim3(6, M/128), 512, H_SMEM_BYTES>>>(p.xh, whl + WT_QKV, bqkv,
                                                  nullptr, p.qkvh,
                                                  M, 3*DD, DD, DD, sLog, 0, 0, 1);
    flash_attn<<<dim3(S/128, BB*HH), 256, FA_SMEM_BYTES>>>(p.qkvh, am, p.ctxh, S);
    gemm_h<<<dim3(2, M/128), 512, H_SMEM_BYTES>>>(p.ctxh, whl + WT_WO, bo,
                                                  p.t1, nullptr,
                                                  M, DD, DD, DD, sLog, 0, 0, 0);
    add_ln_kernel<<<M, 256>>>(p.x, p.t1, ln1g, ln1b, p.ctx, p.xh);
    gemm_h<<<dim3(8, M/128), 512, H_SMEM_BYTES>>>(p.xh, whl + WT_C1, c1b,
                                                  nullptr, p.hh,
                                                  M, INTERN, 3*DD, DD, sLog, 1, 1, 1);
    gemm_h<<<dim3(2, M/128), 512, H_SMEM_BYTES>>>(p.hh, whl + WT_C2, c2b,
                                                  p.h2, nullptr,
                                                  M, DD, 3*INTERN, INTERN, sLog, 1, 0, 0);
    add_ln_kernel<<<M, 256>>>(p.ctx, p.h2, ln2g, ln2b, p.x, p.xh);
}

extern "C" void kernel_launch(void* const* d_in, const int* in_sizes, int n_in,
                              void* d_out, int out_size)
{
    const int*   tokens        = (const int*)  d_in[0];
    const int*   token_lengths = (const int*)  d_in[1];
    const int*   melspec_len   = (const int*)  d_in[2];
    const int*   durations     = (const int*)  d_in[3];
    const float* emb           = (const float*)d_in[5];
    const float* ew[12]; for (int i = 0; i < 12; i++) ew[i] = (const float*)d_in[6 + i];
    const float* dw[12]; for (int i = 0; i < 12; i++) dw[i] = (const float*)d_in[18 + i];
    const float* out_w         = (const float*)d_in[30];
    const float* out_b         = (const float*)d_in[31];

    cudaFuncSetAttribute(flash_attn, cudaFuncAttributeMaxDynamicSharedMemorySize,
                         (int)FA_SMEM_BYTES);
    cudaFuncSetAttribute(gemm_h, cudaFuncAttributeMaxDynamicSharedMemorySize,
                         H_SMEM_BYTES);

    Ptrs p; get_ptrs(p);

    // ---- weight transpose + fp16 convert (batched: blockIdx.z = layer) ----
    for (int half = 0; half < 2; half++) {
        const float* const* w = (half == 0) ? ew : dw;
        __half* whb = p.wh + (size_t)half * LLAY * WT_LAYER;
        transpose_wh<<<dim3(16, 48, LLAY), 256>>>(w[0], whb + WT_QKV, DD, 3*DD,
                                                  (size_t)DD*3*DD, WT_LAYER);
        transpose_wh<<<dim3(16, 16, LLAY), 256>>>(w[2], whb + WT_WO, DD, DD,
                                                  (size_t)DD*DD, WT_LAYER);
        transpose_wh<<<dim3(48, 64, LLAY), 256>>>(w[6], whb + WT_C1, 3*DD, INTERN,
                                                  (size_t)3*DD*INTERN, WT_LAYER);
        transpose_wh<<<dim3(192, 16, LLAY), 256>>>(w[8], whb + WT_C2, 3*INTERN, DD,
                                                   (size_t)3*INTERN*DD, WT_LAYER);
    }

    // ---- embed + positional + encoder mask ----
    embed_kernel<<<(BB*TT*DD + 255)/256, 256>>>(tokens, emb, p.x, p.xh);
    mask_kernel<<<(BB*TT + 255)/256, 256>>>(token_lengths, p.am, TT);

    // ---- encoder stack (S = TT) ----
    for (int l = 0; l < LLAY; l++) {
        run_layer(p, TT, 8, p.am, p.wh + (size_t)l * WT_LAYER,
                  ew[1] + (size_t)l*3*DD,  ew[3] + (size_t)l*DD,
                  ew[4] + (size_t)l*DD,    ew[5] + (size_t)l*DD,
                  ew[7] + (size_t)l*INTERN, ew[9] + (size_t)l*DD,
                  ew[10] + (size_t)l*DD,   ew[11] + (size_t)l*DD);
    }

    // ---- length regulator ----
    cudaMemcpyAsync(p.enc, p.x, (size_t)BB*TT*DD*sizeof(float), cudaMemcpyDeviceToDevice);
    cumsum_kernel<<<BB, 32>>>(durations, p.cums);
    regulate_kernel<<<BB*MELN, 256>>>(p.enc, p.cums, melspec_len, p.x, p.xh);
    mask_kernel<<<(BB*MELN + 255)/256, 256>>>(melspec_len, p.am2, MELN);

    // ---- decoder stack (S = MELN) ----
    for (int l = 0; l < LLAY; l++) {
        run_layer(p, MELN, 10, p.am2, p.wh + (size_t)(LLAY + l) * WT_LAYER,
                  dw[1] + (size_t)l*3*DD,  dw[3] + (size_t)l*DD,
                  dw[4] + (size_t)l*DD,    dw[5] + (size_t)l*DD,
                  dw[7] + (size_t)l*INTERN, dw[9] + (size_t)l*DD,
                  dw[10] + (size_t)l*DD,   dw[11] + (size_t)l*DD);
    }

    // ---- output projection (N=80, legacy fp32 path) + transpose ----
    gemm_tc<<<dim3(1, BB*MELN/128), 256>>>(p.x, out_w, out_b, p.t1,
                                           BB*MELN, OUTC, DD, DD, 10, 0, 0);
    transpose_out_kernel<<<(BB*OUTC*MELN + 255)/256, 256>>>(p.t1, (float*)d_out);
}

// round 12
// speedup vs baseline: 10.1085x; 1.2302x over previous
#include <cuda_runtime.h>
#include <cuda_fp16.h>
#include <math.h>
#include <stdint.h>

// ---------------- problem constants ----------------
#define BB    16
#define TT    256
#define MELN  1024
#define DD    512
#define HH    8
#define DHD   64
#define LLAY  4
#define INTERN 2048
#define OUTC  80

// ---------------- scratch (device globals; no allocation allowed) ----------
__device__ float  g_x   [(size_t)BB*MELN*DD];       // fp32 activations (residual)
__device__ __half g_xh  [(size_t)BB*MELN*DD];       // fp16 GEMM-input copy
__device__ __half g_qkvh[(size_t)BB*MELN*3*DD];     // qkv (fp16)
__device__ float  g_ctx [(size_t)BB*MELN*DD];       // LN1 output y (fp32)
__device__ __half g_ctxh[(size_t)BB*MELN*DD];       // attn ctx (fp16)
__device__ float  g_t1  [(size_t)BB*MELN*DD];       // wo out (fp32)
__device__ __half g_hh  [(size_t)BB*MELN*INTERN];   // conv1 out (fp16)
__device__ float  g_h2  [(size_t)BB*MELN*DD];       // conv2 out (fp32)
__device__ float  g_enc [(size_t)BB*TT*DD];
__device__ float  g_am  [BB*TT];
__device__ float  g_am2 [BB*MELN];
__device__ int    g_cums[BB*TT];
#define WT_QKV   0
#define WT_WO    786432
#define WT_C1    1048576
#define WT_C2    4194304
#define WT_LAYER 7340032
__device__ __half g_wh   [(size_t)WT_LAYER * 8];
__device__ __half g_whOut[OUTC * DD];               // out_w transposed (80,512)

// ---------------- small helpers ----------------
__device__ __forceinline__ uint32_t f2tf32(float x) {
    uint32_t u;
    asm("cvt.rna.tf32.f32 %0, %1;" : "=r"(u) : "f"(x));
    return u;
}
__device__ __forceinline__ uint32_t smem_u32(const void* p) {
    uint32_t a;
    asm("{ .reg .u64 t; cvta.to.shared.u64 t, %1; cvt.u32.u64 %0, t; }" : "=r"(a) : "l"(p));
    return a;
}

#define MMA_TF32(acc, a0,a1,a2,a3, b0,b1)                                     \
    asm volatile("mma.sync.aligned.m16n8k8.row.col.f32.tf32.tf32.f32 "        \
                 "{%0,%1,%2,%3},{%4,%5,%6,%7},{%8,%9},{%0,%1,%2,%3};"         \
                 : "+f"(acc[0]), "+f"(acc[1]), "+f"(acc[2]), "+f"(acc[3])     \
                 : "r"(a0), "r"(a1), "r"(a2), "r"(a3), "r"(b0), "r"(b1))

#define MMA_F16(acc, a0,a1,a2,a3, b0,b1)                                      \
    asm volatile("mma.sync.aligned.m16n8k16.row.col.f32.f16.f16.f32 "         \
                 "{%0,%1,%2,%3},{%4,%5,%6,%7},{%8,%9},{%0,%1,%2,%3};"         \
                 : "+f"(acc[0]), "+f"(acc[1]), "+f"(acc[2]), "+f"(acc[3])     \
                 : "r"(a0), "r"(a1), "r"(a2), "r"(a3), "r"(b0), "r"(b1))

#define LDM_X4(r0,r1,r2,r3, addr)                                             \
    asm volatile("ldmatrix.sync.aligned.m8n8.x4.shared.b16 {%0,%1,%2,%3}, [%4];" \
                 : "=r"(r0), "=r"(r1), "=r"(r2), "=r"(r3) : "r"(addr))

#define CP16(dst, src, sz)                                                    \
    asm volatile("cp.async.cg.shared.global [%0], [%1], 16, %2;"              \
                 :: "r"(dst), "l"(src), "r"(sz) : "memory")
#define CP_COMMIT()  asm volatile("cp.async.commit_group;" ::: "memory")
#define CP_WAIT1()   asm volatile("cp.async.wait_group 1;" ::: "memory")

// ========= weight transpose + fp16 convert (batched over layers via z) =====
// W (K,N) fp32 -> WH (N,K) fp16, with N-bound guard (for out_w N=80).
__global__ __launch_bounds__(256) void transpose_wh(const float* __restrict__ W,
                                                    __half* __restrict__ WH,
                                                    int K, int N,
                                                    size_t wStride, size_t whStride)
{
    const float* Wl = W + (size_t)blockIdx.z * wStride;
    __half* WHl = WH + (size_t)blockIdx.z * whStride;
    __shared__ float t[32][33];
    int k0 = blockIdx.x * 32, n0 = blockIdx.y * 32;
    int tx = threadIdx.x & 31, ty = threadIdx.x >> 5;
#pragma unroll
    for (int i = 0; i < 4; i++) {
        int r = ty + i * 8;
        t[r][tx] = (n0 + tx < N) ? Wl[(size_t)(k0 + r) * N + n0 + tx] : 0.f;
    }
    __syncthreads();
#pragma unroll
    for (int i = 0; i < 4; i++) {
        int r = ty + i * 8;
        if (n0 + r < N)
            WHl[(size_t)(n0 + r) * K + k0 + tx] = __float2half_rn(t[tx][r]);
    }
}

// ========== cp.async pipelined fp16 GEMM (m16n8k16 + ldmatrix) =============
// C = op(A' @ WT^T + bias). A (M,Kin) fp16 row-major (conv: K'=3*Kin, source
// row (m%S)+tap-1, zero-filled OOB). WT (N,Ktot) fp16 row-major (N may be
// non-multiple of 128: guarded via cp.async zfill + store guards).
// CTA 128x128, BK=32, 3-stage cp.async pipeline, 256 thr = 8 warps (2m x 4n),
// warp tile 64x32. fp32 accumulate. 2 CTAs/SM. transOut: write (b, n, f).
#define H_STRIDE 40                      // halves per smem row (32 + 8 pad)
#define HA_HALVES (128*H_STRIDE)         // 5120
#define HB_HALVES (128*H_STRIDE)         // 5120
#define H_STAGE_BYTES ((HA_HALVES + HB_HALVES) * 2)   // 20480
#define H_SMEM_BYTES  (3 * H_STAGE_BYTES)             // 61440

__global__ __launch_bounds__(256, 2) void gemm_h(
    const __half* __restrict__ A, const __half* __restrict__ WT,
    const float* __restrict__ bias, float* __restrict__ C32,
    __half* __restrict__ C16,
    int M, int N, int Ktot, int Kin, int sLog, int conv, int relu,
    int halfOut, int transOut)
{
    extern __shared__ char sm[];
    const uint32_t sbase = smem_u32(sm);

    const int tid  = threadIdx.x;
    const int warp = tid >> 5, lane = tid & 31;
    const int gid  = lane >> 2, tid4 = lane & 3;
    const int wm   = warp & 1,  wn   = warp >> 1;    // 2 x 4 warps
    const int bm   = blockIdx.y * 128;
    const int bn   = blockIdx.x * 128;
    const int S    = 1 << sLog;
    const int nst  = Ktot / 32;

    const int lrow = lane & 7;
    const int lsel = lane >> 3;
    const int rowOffA = (lsel & 1) * 8;
    const int colOffA = (lsel >> 1) * 8;
    const int rowOffB = (lsel >> 1) * 8;
    const int colOffB = (lsel & 1) * 8;

    float acc[4][4][4];
#pragma unroll
    for (int i = 0; i < 4; i++)
#pragma unroll
        for (int j = 0; j < 4; j++)
#pragma unroll
            for (int r = 0; r < 4; r++) acc[i][j][r] = 0.f;

    auto issue_stage = [&](int stg) {
        const int k0    = stg * 32;
        const int tap   = conv ? (k0 / Kin) : 0;
        const int kcol  = k0 - tap * Kin;
        const int shift = conv ? (tap - 1) : 0;
        const uint32_t aB = sbase + (stg % 3) * H_STAGE_BYTES;
        const uint32_t bB = aB + HA_HALVES * 2;
        // A: 128 rows x 4 chunks = 512 chunks (2/thread)
#pragma unroll
        for (int i = 0; i < 2; i++) {
            int flat = tid + i * 256;
            int row = flat >> 2, cq = flat & 3;
            int gm = bm + row;
            int b = gm >> sLog, l = gm & (S - 1);
            int src = l + shift;
            uint32_t sz = (src >= 0 && src < S) ? 16u : 0u;
            int srcc = (src >= 0 && src < S) ? src : 0;
            const __half* gp = A + (size_t)(((size_t)b << sLog) + srcc) * Kin + kcol + cq * 8;
            CP16(aB + (row * H_STRIDE + cq * 8) * 2, gp, sz);
        }
        // B: 128 rows x 4 chunks = 512 chunks (2/thread), guarded rows zfill
#pragma unroll
        for (int i = 0; i < 2; i++) {
            int flat = tid + i * 256;
            int nr = flat >> 2, cq = flat & 3;
            int gn = bn + nr;
            uint32_t sz = (gn < N) ? 16u : 0u;
            int gnc = (gn < N) ? gn : (N - 1);
            const __half* gp = WT + (size_t)gnc * Ktot + k0 + cq * 8;
            CP16(bB + (nr * H_STRIDE + cq * 8) * 2, gp, sz);
        }
    };

    auto compute = [&](int stg) {
        const uint32_t aB = sbase + (stg % 3) * H_STAGE_BYTES;
        const uint32_t bB = aB + HA_HALVES * 2;
#pragma unroll
        for (int c = 0; c < 2; c++) {
            uint32_t af[4][4];
#pragma unroll
            for (int mi = 0; mi < 4; mi++) {
                uint32_t ap = aB + ((wm * 64 + mi * 16 + lrow + rowOffA) * H_STRIDE
                                    + c * 16 + colOffA) * 2;
                LDM_X4(af[mi][0], af[mi][1], af[mi][2], af[mi][3], ap);
            }
            uint32_t bf[4][2];
#pragma unroll
            for (int njp = 0; njp < 2; njp++) {
                uint32_t bp = bB + ((wn * 32 + njp * 16 + lrow + rowOffB) * H_STRIDE
                                    + c * 16 + colOffB) * 2;
                uint32_t r0, r1, r2, r3;
                LDM_X4(r0, r1, r2, r3, bp);
                bf[njp * 2][0]     = r0;
                bf[njp * 2][1]     = r1;
                bf[njp * 2 + 1][0] = r2;
                bf[njp * 2 + 1][1] = r3;
            }
#pragma unroll
            for (int mi = 0; mi < 4; mi++)
#pragma unroll
                for (int nj = 0; nj < 4; nj++)
                    MMA_F16(acc[mi][nj], af[mi][0], af[mi][1], af[mi][2], af[mi][3],
                            bf[nj][0], bf[nj][1]);
        }
    };

    issue_stage(0); CP_COMMIT();
    issue_stage(1); CP_COMMIT();
    for (int s = 0; s < nst; s++) {
        CP_WAIT1();
        __syncthreads();
        if (s + 2 < nst) issue_stage(s + 2);
        CP_COMMIT();
        compute(s);
    }

#pragma unroll
    for (int mi = 0; mi < 4; mi++) {
        int gm0 = bm + wm * 64 + mi * 16 + gid;
#pragma unroll
        for (int nj = 0; nj < 4; nj++) {
            int gn = bn + wn * 32 + nj * 8 + tid4 * 2;
            float b0 = (gn < N) ? bias[gn] : 0.f;
            float b1 = (gn + 1 < N) ? bias[gn + 1] : 0.f;
            float v00 = acc[mi][nj][0] + b0;
            float v01 = acc[mi][nj][1] + b1;
            float v10 = acc[mi][nj][2] + b0;
            float v11 = acc[mi][nj][3] + b1;
            if (relu) {
                v00 = fmaxf(v00, 0.f); v01 = fmaxf(v01, 0.f);
                v10 = fmaxf(v10, 0.f); v11 = fmaxf(v11, 0.f);
            }
            if (transOut) {
                // write (b, n, f): C32[((gm>>sLog)*N + gn)*S + (gm&(S-1))]
                int b0i = gm0 >> sLog, f0 = gm0 & (S - 1);
                int b1i = (gm0 + 8) >> sLog, f1 = (gm0 + 8) & (S - 1);
                if (gn < N) {
                    C32[((size_t)b0i * N + gn) * S + f0] = v00;
                    C32[((size_t)b1i * N + gn) * S + f1] = v10;
                }
                if (gn + 1 < N) {
                    C32[((size_t)b0i * N + gn + 1) * S + f0] = v01;
                    C32[((size_t)b1i * N + gn + 1) * S + f1] = v11;
                }
            } else if (halfOut) {
                *(__half2*)&C16[(size_t)gm0 * N + gn]       = __floats2half2_rn(v00, v01);
                *(__half2*)&C16[(size_t)(gm0 + 8) * N + gn] = __floats2half2_rn(v10, v11);
            } else {
                C32[(size_t)gm0 * N + gn]           = v00;
                C32[(size_t)gm0 * N + gn + 1]       = v01;
                C32[(size_t)(gm0 + 8) * N + gn]     = v10;
                C32[(size_t)(gm0 + 8) * N + gn + 1] = v11;
            }
        }
    }
}

// ============== fused flash attention (fp16 in/out, tf32 mma) ==============
#define FA_PAD 68
#define FA_SMEM_FLOATS (128*FA_PAD + 64*FA_PAD + 64*FA_PAD + 128*FA_PAD + 3*128)

__device__ __forceinline__ void h8_to_f8(const __half* src, float* dst) {
    uint4 u = *(const uint4*)src;
    float2 f0 = __half22float2(*(__half2*)&u.x);
    float2 f1 = __half22float2(*(__half2*)&u.y);
    float2 f2 = __half22float2(*(__half2*)&u.z);
    float2 f3 = __half22float2(*(__half2*)&u.w);
    *(float4*)dst       = make_float4(f0.x, f0.y, f1.x, f1.y);
    *(float4*)(dst + 4) = make_float4(f2.x, f2.y, f3.x, f3.y);
}

__global__ __launch_bounds__(256) void flash_attn(const __half* __restrict__ qkv,
                                                  const float* __restrict__ am,
                                                  __half* __restrict__ ctx, int S)
{
    extern __shared__ float smf[];
    float* Qs   = smf;
    float* Ks   = Qs + 128*FA_PAD;
    float* Vs   = Ks + 64*FA_PAD;
    float* Ss   = Vs + 64*FA_PAD;
    float* mrow = Ss + 128*FA_PAD;
    float* lrow = mrow + 128;
    float* arow = lrow + 128;

    const int tid  = threadIdx.x;
    const int warp = tid >> 5, lane = tid & 31;
    const int gid  = lane >> 2, tid4 = lane & 3;
    const int wm   = warp & 3, wn = warp >> 2;
    const int bh   = blockIdx.y;
    const int b    = bh >> 3, h = bh & 7;
    const int q0   = blockIdx.x * 128;
    const float* amb = am + b * S;
    const __half* qb = qkv + (size_t)(b * S) * 1536 + h * 64;

#pragma unroll
    for (int i = 0; i < 4; i++) {
        int idx = tid + i * 256;
        int r = idx >> 3, c8 = idx & 7;
        h8_to_f8(&qb[(size_t)(q0 + r) * 1536 + c8 * 8], &Qs[r * FA_PAD + c8 * 8]);
    }
    if (tid < 128) { mrow[tid] = -INFINITY; lrow[tid] = 0.f; }

    float oacc[2][4][4];
#pragma unroll
    for (int mi = 0; mi < 2; mi++)
#pragma unroll
        for (int nj = 0; nj < 4; nj++)
#pragma unroll
            for (int r = 0; r < 4; r++) oacc[mi][nj][r] = 0.f;

    const int nkt = S >> 6;
    for (int kt = 0; kt < nkt; kt++) {
        const int k0 = kt * 64;
        __syncthreads();
#pragma unroll
        for (int i = 0; i < 2; i++) {
            int idx = tid + i * 256;
            int r = idx >> 3, c8 = idx & 7;
            const __half* src = &qb[(size_t)(k0 + r) * 1536];
            h8_to_f8(&src[512 + c8 * 8],  &Ks[r * FA_PAD + c8 * 8]);
            h8_to_f8(&src[1024 + c8 * 8], &Vs[r * FA_PAD + c8 * 8]);
        }
        __syncthreads();

        float sacc[2][4][4];
#pragma unroll
        for (int mi = 0; mi < 2; mi++)
#pragma unroll
            for (int nj = 0; nj < 4; nj++)
#pragma unroll
                for (int r = 0; r < 4; r++) sacc[mi][nj][r] = 0.f;
#pragma unroll
        for (int kc = 0; kc < 8; kc++) {
            uint32_t af[2][4];
#pragma unroll
            for (int mi = 0; mi < 2; mi++) {
                const float* ap = &Qs[(wm * 32 + mi * 16 + gid) * FA_PAD + kc * 8 + tid4];
                af[mi][0] = __float_as_uint(ap[0]);
                af[mi][1] = __float_as_uint(ap[8 * FA_PAD]);
                af[mi][2] = __float_as_uint(ap[4]);
                af[mi][3] = __float_as_uint(ap[8 * FA_PAD + 4]);
            }
            uint32_t bf[4][2];
#pragma unroll
            for (int nj = 0; nj < 4; nj++) {
                const float* bp = &Ks[(wn * 32 + nj * 8 + gid) * FA_PAD + kc * 8 + tid4];
                bf[nj][0] = __float_as_uint(bp[0]);
                bf[nj][1] = __float_as_uint(bp[4]);
            }
#pragma unroll
            for (int mi = 0; mi < 2; mi++)
#pragma unroll
                for (int nj = 0; nj < 4; nj++)
                    MMA_TF32(sacc[mi][nj], af[mi][0], af[mi][1], af[mi][2], af[mi][3],
                             bf[nj][0], bf[nj][1]);
        }
#pragma unroll
        for (int mi = 0; mi < 2; mi++) {
            int r = wm * 32 + mi * 16 + gid;
#pragma unroll
            for (int nj = 0; nj < 4; nj++) {
                int c = wn * 32 + nj * 8 + tid4 * 2;
                float am0 = amb[k0 + c], am1 = amb[k0 + c + 1];
                Ss[r * FA_PAD + c]           = sacc[mi][nj][0] * 0.125f + am0;
                Ss[r * FA_PAD + c + 1]       = sacc[mi][nj][1] * 0.125f + am1;
                Ss[(r + 8) * FA_PAD + c]     = sacc[mi][nj][2] * 0.125f + am0;
                Ss[(r + 8) * FA_PAD + c + 1] = sacc[mi][nj][3] * 0.125f + am1;
            }
        }
        __syncthreads();
        {
            int r = tid >> 1, hf = tid & 1;
            float* srow = Ss + r * FA_PAD + hf * 32;
            float mx = -INFINITY;
#pragma unroll 8
            for (int j = 0; j < 32; j++) mx = fmaxf(mx, srow[j]);
            mx = fmaxf(mx, __shfl_xor_sync(0xffffffffu, mx, 1));
            float mold = mrow[r];
            float mnew = fmaxf(mold, mx);
            float sum = 0.f;
#pragma unroll 8
            for (int j = 0; j < 32; j++) {
                float pv = __expf(srow[j] - mnew);
                srow[j] = __uint_as_float(f2tf32(pv));
                sum += pv;
            }
            sum += __shfl_xor_sync(0xffffffffu, sum, 1);
            if (hf == 0) {
                float alpha = __expf(mold - mnew);
                lrow[r] = lrow[r] * alpha + sum;
                mrow[r] = mnew;
                arow[r] = alpha;
            }
        }
        __syncthreads();

        float al[2][2];
#pragma unroll
        for (int mi = 0; mi < 2; mi++) {
            int r = wm * 32 + mi * 16 + gid;
            al[mi][0] = arow[r];
            al[mi][1] = arow[r + 8];
        }
#pragma unroll
        for (int mi = 0; mi < 2; mi++)
#pragma unroll
            for (int nj = 0; nj < 4; nj++) {
                oacc[mi][nj][0] *= al[mi][0];
                oacc[mi][nj][1] *= al[mi][0];
                oacc[mi][nj][2] *= al[mi][1];
                oacc[mi][nj][3] *= al[mi][1];
            }
#pragma unroll
        for (int kc = 0; kc < 8; kc++) {
            uint32_t af[2][4];
#pragma unroll
            for (int mi = 0; mi < 2; mi++) {
                const float* ap = &Ss[(wm * 32 + mi * 16 + gid) * FA_PAD + kc * 8 + tid4];
                af[mi][0] = __float_as_uint(ap[0]);
                af[mi][1] = __float_as_uint(ap[8 * FA_PAD]);
                af[mi][2] = __float_as_uint(ap[4]);
                af[mi][3] = __float_as_uint(ap[8 * FA_PAD + 4]);
            }
            uint32_t bf[4][2];
#pragma unroll
            for (int nj = 0; nj < 4; nj++) {
                const float* bp = &Vs[(kc * 8 + tid4) * FA_PAD + wn * 32 + nj * 8 + gid];
                bf[nj][0] = __float_as_uint(bp[0]);
                bf[nj][1] = __float_as_uint(bp[4 * FA_PAD]);
            }
#pragma unroll
            for (int mi = 0; mi < 2; mi++)
#pragma unroll
                for (int nj = 0; nj < 4; nj++)
                    MMA_TF32(oacc[mi][nj], af[mi][0], af[mi][1], af[mi][2], af[mi][3],
                             bf[nj][0], bf[nj][1]);
        }
    }
#pragma unroll
    for (int mi = 0; mi < 2; mi++) {
        int r = wm * 32 + mi * 16 + gid;
        float inv0 = 1.f / lrow[r];
        float inv1 = 1.f / lrow[r + 8];
#pragma unroll
        for (int nj = 0; nj < 4; nj++) {
            int c = wn * 32 + nj * 8 + tid4 * 2;
            __half2* o0 = (__half2*)&ctx[(size_t)(b * S + q0 + r) * DD + h * 64 + c];
            __half2* o1 = (__half2*)&ctx[(size_t)(b * S + q0 + r + 8) * DD + h * 64 + c];
            *o0 = __floats2half2_rn(oacc[mi][nj][0] * inv0, oacc[mi][nj][1] * inv0);
            *o1 = __floats2half2_rn(oacc[mi][nj][2] * inv1, oacc[mi][nj][3] * inv1);
        }
    }
}

// ---------------- embed + positional (reference adds pos[b], not pos[t]) ----
__global__ __launch_bounds__(256) void embed_kernel(const int* __restrict__ tokens,
                                                    const float* __restrict__ emb,
                                                    float* __restrict__ x,
                                                    __half* __restrict__ xh)
{
    int i = blockIdx.x * 256 + threadIdx.x;
    if (i >= BB*TT*DD) return;
    int d  = i & (DD-1);
    int bt = i / DD;
    int b  = bt / TT;
    int tok = tokens[bt];
    int half = d >> 1;
    float den = __expf(-(float)(2*half) * (logf(10000.f) / (float)DD));
    float ang = (float)b * den;
    float posv = (d & 1) ? cosf(ang) : sinf(ang);
    float v = 2.f * emb[(size_t)tok*DD + d] + posv;
    x[i] = v;
    xh[i] = __float2half_rn(v);
}

__global__ __launch_bounds__(256) void mask_kernel(const int* __restrict__ lens,
                                                   float* __restrict__ am, int S)
{
    int i = blockIdx.x*256 + threadIdx.x;
    if (i >= BB*S) return;
    int b = i / S, t = i % S;
    am[i] = (t > lens[b]) ? -INFINITY : 0.f;
}

__global__ __launch_bounds__(256) void add_ln_kernel(const float* __restrict__ resid,
                                                     const float* __restrict__ delta,
                                                     const float* __restrict__ g,
                                                     const float* __restrict__ bb,
                                                     float* __restrict__ out,
                                                     __half* __restrict__ outh)
{
    size_t row = blockIdx.x;
    int t = threadIdx.x;
    __shared__ float red[256];
    float v0 = resid[row*DD + t]       + delta[row*DD + t];
    float v1 = resid[row*DD + t + 256] + delta[row*DD + t + 256];
    red[t] = v0 + v1; __syncthreads();
    for (int s = 128; s > 0; s >>= 1) { if (t < s) red[t] += red[t+s]; __syncthreads(); }
    float mean = red[0] * (1.f/DD);
    __syncthreads();
    float d0 = v0 - mean, d1 = v1 - mean;
    red[t] = d0*d0 + d1*d1; __syncthreads();
    for (int s = 128; s > 0; s >>= 1) { if (t < s) red[t] += red[t+s]; __syncthreads(); }
    float var = red[0] * (1.f/DD);
    float sc = rsqrtf(var + 1e-5f);
    float o0 = d0*sc*g[t]     + bb[t];
    float o1 = d1*sc*g[t+256] + bb[t+256];
    out[row*DD + t]        = o0;
    out[row*DD + t + 256]  = o1;
    outh[row*DD + t]       = __float2half_rn(o0);
    outh[row*DD + t + 256] = __float2half_rn(o1);
}

__global__ void cumsum_kernel(const int* __restrict__ dur, int* __restrict__ cums)
{
    int b = blockIdx.x;
    if (threadIdx.x == 0) {
        int s = 0;
        for (int t = 0; t < TT; t++) { s += dur[b*TT + t]; cums[b*TT + t] = s; }
    }
}

__global__ __launch_bounds__(256) void regulate_kernel(const float* __restrict__ enc,
                                                       const int* __restrict__ cums,
                                                       const int* __restrict__ mellen,
                                                       float* __restrict__ dec_in,
                                                       __half* __restrict__ dec_inh)
{
    int bf = blockIdx.x;
    int b = bf / MELN, f = bf % MELN;
    const int* c = cums + b*TT;
    int lo = 0, hi = TT;
    while (lo < hi) { int mid = (lo + hi) >> 1; if (c[mid] <= f) lo = mid + 1; else hi = mid; }
    int idx = lo; if (idx > TT-1) idx = TT-1;
    float keep = (f <= mellen[b]) ? 1.f : 0.f;
    for (int d = threadIdx.x; d < DD; d += 256) {
        float v = enc[(size_t)(b*TT + idx)*DD + d] * keep;
        dec_in[(size_t)bf*DD + d]  = v;
        dec_inh[(size_t)bf*DD + d] = __float2half_rn(v);
    }
}

// =============================== host side ===============================
struct Ptrs {
    float *x, *ctx, *t1, *h2, *enc, *am, *am2;
    __half *xh, *qkvh, *ctxh, *hh, *wh, *whOut;
    int *cums;
};

static void get_ptrs(Ptrs& p)
{
    cudaGetSymbolAddress((void**)&p.x,     g_x);
    cudaGetSymbolAddress((void**)&p.xh,    g_xh);
    cudaGetSymbolAddress((void**)&p.qkvh,  g_qkvh);
    cudaGetSymbolAddress((void**)&p.ctx,   g_ctx);
    cudaGetSymbolAddress((void**)&p.ctxh,  g_ctxh);
    cudaGetSymbolAddress((void**)&p.t1,    g_t1);
    cudaGetSymbolAddress((void**)&p.hh,    g_hh);
    cudaGetSymbolAddress((void**)&p.h2,    g_h2);
    cudaGetSymbolAddress((void**)&p.enc,   g_enc);
    cudaGetSymbolAddress((void**)&p.am,    g_am);
    cudaGetSymbolAddress((void**)&p.am2,   g_am2);
    cudaGetSymbolAddress((void**)&p.wh,    g_wh);
    cudaGetSymbolAddress((void**)&p.whOut, g_whOut);
    cudaGetSymbolAddress((void**)&p.cums,  g_cums);
}

static const size_t FA_SMEM_BYTES = (size_t)FA_SMEM_FLOATS * sizeof(float);

static inline dim3 g_grid(int M, int N) { return dim3((N + 127)/128, M/128); }

static void run_layer(Ptrs& p, int S, int sLog, const float* am, const __half* whl,
                      const float* bqkv, const float* bo,
                      const float* ln1g, const float* ln1b,
                      const float* c1b,  const float* c2b,
                      const float* ln2g, const float* ln2b)
{
    const int M = BB * S;

    gemm_h<<<g_grid(M, 3*DD), 256, H_SMEM_BYTES>>>(p.xh, whl + WT_QKV, bqkv,
                                                   nullptr, p.qkvh,
                                                   M, 3*DD, DD, DD, sLog, 0, 0, 1, 0);
    flash_attn<<<dim3(S/128, BB*HH), 256, FA_SMEM_BYTES>>>(p.qkvh, am, p.ctxh, S);
    gemm_h<<<g_grid(M, DD), 256, H_SMEM_BYTES>>>(p.ctxh, whl + WT_WO, bo,
                                                 p.t1, nullptr,
                                                 M, DD, DD, DD, sLog, 0, 0, 0, 0);
    add_ln_kernel<<<M, 256>>>(p.x, p.t1, ln1g, ln1b, p.ctx, p.xh);
    gemm_h<<<g_grid(M, INTERN), 256, H_SMEM_BYTES>>>(p.xh, whl + WT_C1, c1b,
                                                     nullptr, p.hh,
                                                     M, INTERN, 3*DD, DD, sLog, 1, 1, 1, 0);
    gemm_h<<<g_grid(M, DD), 256, H_SMEM_BYTES>>>(p.hh, whl + WT_C2, c2b,
                                                 p.h2, nullptr,
                                                 M, DD, 3*INTERN, INTERN, sLog, 1, 0, 0, 0);
    add_ln_kernel<<<M, 256>>>(p.ctx, p.h2, ln2g, ln2b, p.x, p.xh);
}

extern "C" void kernel_launch(void* const* d_in, const int* in_sizes, int n_in,
                              void* d_out, int out_size)
{
    const int*   tokens        = (const int*)  d_in[0];
    const int*   token_lengths = (const int*)  d_in[1];
    const int*   melspec_len   = (const int*)  d_in[2];
    const int*   durations     = (const int*)  d_in[3];
    const float* emb           = (const float*)d_in[5];
    const float* ew[12]; for (int i = 0; i < 12; i++) ew[i] = (const float*)d_in[6 + i];
    const float* dw[12]; for (int i = 0; i < 12; i++) dw[i] = (const float*)d_in[18 + i];
    const float* out_w         = (const float*)d_in[30];
    const float* out_b         = (const float*)d_in[31];

    cudaFuncSetAttribute(flash_attn, cudaFuncAttributeMaxDynamicSharedMemorySize,
                         (int)FA_SMEM_BYTES);
    cudaFuncSetAttribute(gemm_h, cudaFuncAttributeMaxDynamicSharedMemorySize,
                         H_SMEM_BYTES);

    Ptrs p; get_ptrs(p);

    // ---- weight transpose + fp16 convert (batched: blockIdx.z = layer) ----
    for (int half = 0; half < 2; half++) {
        const float* const* w = (half == 0) ? ew : dw;
        __half* whb = p.wh + (size_t)half * LLAY * WT_LAYER;
        transpose_wh<<<dim3(16, 48, LLAY), 256>>>(w[0], whb + WT_QKV, DD, 3*DD,
                                                  (size_t)DD*3*DD, WT_LAYER);
        transpose_wh<<<dim3(16, 16, LLAY), 256>>>(w[2], whb + WT_WO, DD, DD,
                                                  (size_t)DD*DD, WT_LAYER);
        transpose_wh<<<dim3(48, 64, LLAY), 256>>>(w[6], whb + WT_C1, 3*DD, INTERN,
                                                  (size_t)3*DD*INTERN, WT_LAYER);
        transpose_wh<<<dim3(192, 16, LLAY), 256>>>(w[8], whb + WT_C2, 3*INTERN, DD,
                                                   (size_t)3*INTERN*DD, WT_LAYER);
    }
    // out_w (512, 80) -> (80, 512) fp16, N-guarded
    transpose_wh<<<dim3(16, 3, 1), 256>>>(out_w, p.whOut, DD, OUTC, 0, 0);

    // ---- embed + positional + encoder mask ----
    embed_kernel<<<(BB*TT*DD + 255)/256, 256>>>(tokens, emb, p.x, p.xh);
    mask_kernel<<<(BB*TT + 255)/256, 256>>>(token_lengths, p.am, TT);

    // ---- encoder stack (S = TT) ----
    for (int l = 0; l < LLAY; l++) {
        run_layer(p, TT, 8, p.am, p.wh + (size_t)l * WT_LAYER,
                  ew[1] + (size_t)l*3*DD,  ew[3] + (size_t)l*DD,
                  ew[4] + (size_t)l*DD,    ew[5] + (size_t)l*DD,
                  ew[7] + (size_t)l*INTERN, ew[9] + (size_t)l*DD,
                  ew[10] + (size_t)l*DD,   ew[11] + (size_t)l*DD);
    }

    // ---- length regulator ----
    cudaMemcpyAsync(p.enc, p.x, (size_t)BB*TT*DD*sizeof(float), cudaMemcpyDeviceToDevice);
    cumsum_kernel<<<BB, 32>>>(durations, p.cums);
    regulate_kernel<<<BB*MELN, 256>>>(p.enc, p.cums, melspec_len, p.x, p.xh);
    mask_kernel<<<(BB*MELN + 255)/256, 256>>>(melspec_len, p.am2, MELN);

    // ---- decoder stack (S = MELN) ----
    for (int l = 0; l < LLAY; l++) {
        run_layer(p, MELN, 10, p.am2, p.wh + (size_t)(LLAY + l) * WT_LAYER,
                  dw[1] + (size_t)l*3*DD,  dw[3] + (size_t)l*DD,
                  dw[4] + (size_t)l*DD,    dw[5] + (size_t)l*DD,
                  dw[7] + (size_t)l*INTERN, dw[9] + (size_t)l*DD,
                  dw[10] + (size_t)l*DD,   dw[11] + (size_t)l*DD);
    }

    // ---- output projection fused with transpose: writes (b, o, f) ----
    gemm_h<<<dim3(1, BB*MELN/128), 256, H_SMEM_BYTES>>>(p.xh, p.whOut, out_b,
                                                        (float*)d_out, nullptr,
                                                        BB*MELN, OUTC, DD, DD, 10,
                                                        0, 0, 0, 1);
}

// round 13
// speedup vs baseline: 10.2585x; 1.0148x over previous
#include <cuda_runtime.h>
#include <cuda_fp16.h>
#include <math.h>
#include <stdint.h>

// ---------------- problem constants ----------------
#define BB    16
#define TT    256
#define MELN  1024
#define DD    512
#define HH    8
#define DHD   64
#define LLAY  4
#define INTERN 2048
#define OUTC  80

// ---------------- scratch (device globals; no allocation allowed) ----------
__device__ float  g_x   [(size_t)BB*MELN*DD];
__device__ __half g_xh  [(size_t)BB*MELN*DD];
__device__ __half g_qkvh[(size_t)BB*MELN*3*DD];
__device__ float  g_ctx [(size_t)BB*MELN*DD];
__device__ __half g_ctxh[(size_t)BB*MELN*DD];
__device__ float  g_t1  [(size_t)BB*MELN*DD];
__device__ __half g_hh  [(size_t)BB*MELN*INTERN];
__device__ float  g_h2  [(size_t)BB*MELN*DD];
__device__ float  g_enc [(size_t)BB*TT*DD];
__device__ float  g_am  [BB*TT];
__device__ float  g_am2 [BB*MELN];
__device__ int    g_cums[BB*TT];
#define WT_QKV   0
#define WT_WO    786432
#define WT_C1    1048576
#define WT_C2    4194304
#define WT_LAYER 7340032
__device__ __half g_wh   [(size_t)WT_LAYER * 8];
__device__ __half g_whOut[OUTC * DD];

// ---------------- small helpers ----------------
__device__ __forceinline__ uint32_t smem_u32(const void* p) {
    uint32_t a;
    asm("{ .reg .u64 t; cvta.to.shared.u64 t, %1; cvt.u32.u64 %0, t; }" : "=r"(a) : "l"(p));
    return a;
}

#define MMA_F16(acc, a0,a1,a2,a3, b0,b1)                                      \
    asm volatile("mma.sync.aligned.m16n8k16.row.col.f32.f16.f16.f32 "         \
                 "{%0,%1,%2,%3},{%4,%5,%6,%7},{%8,%9},{%0,%1,%2,%3};"         \
                 : "+f"(acc[0]), "+f"(acc[1]), "+f"(acc[2]), "+f"(acc[3])     \
                 : "r"(a0), "r"(a1), "r"(a2), "r"(a3), "r"(b0), "r"(b1))

#define LDM_X4(r0,r1,r2,r3, addr)                                             \
    asm volatile("ldmatrix.sync.aligned.m8n8.x4.shared.b16 {%0,%1,%2,%3}, [%4];" \
                 : "=r"(r0), "=r"(r1), "=r"(r2), "=r"(r3) : "r"(addr))

#define CP16(dst, src, sz)                                                    \
    asm volatile("cp.async.cg.shared.global [%0], [%1], 16, %2;"              \
                 :: "r"(dst), "l"(src), "r"(sz) : "memory")
#define CP_COMMIT()  asm volatile("cp.async.commit_group;" ::: "memory")
#define CP_WAIT1()   asm volatile("cp.async.wait_group 1;" ::: "memory")

// ========= weight transpose + fp16 convert (batched over layers via z) =====
__global__ __launch_bounds__(256) void transpose_wh(const float* __restrict__ W,
                                                    __half* __restrict__ WH,
                                                    int K, int N,
                                                    size_t wStride, size_t whStride)
{
    const float* Wl = W + (size_t)blockIdx.z * wStride;
    __half* WHl = WH + (size_t)blockIdx.z * whStride;
    __shared__ float t[32][33];
    int k0 = blockIdx.x * 32, n0 = blockIdx.y * 32;
    int tx = threadIdx.x & 31, ty = threadIdx.x >> 5;
#pragma unroll
    for (int i = 0; i < 4; i++) {
        int r = ty + i * 8;
        t[r][tx] = (n0 + tx < N) ? Wl[(size_t)(k0 + r) * N + n0 + tx] : 0.f;
    }
    __syncthreads();
#pragma unroll
    for (int i = 0; i < 4; i++) {
        int r = ty + i * 8;
        if (n0 + r < N)
            WHl[(size_t)(n0 + r) * K + k0 + tx] = __float2half_rn(t[tx][r]);
    }
}

// ========== cp.async pipelined fp16 GEMM (m16n8k16 + ldmatrix) =============
// Template MI: warp m-tile = MI*16 rows, CTA tile = (MI*32) x 128.
// MI=4 -> 128x128 (default), MI=2 -> 64x128 (small-M / wave-quant relief).
// 256 thr = 8 warps (2m x 4n), 3-stage cp.async, 2 CTAs/SM.
#define H_STRIDE 40
#define HB_HALVES (128*H_STRIDE)

template<int MI>
__global__ __launch_bounds__(256, 2) void gemm_h(
    const __half* __restrict__ A, const __half* __restrict__ WT,
    const float* __restrict__ bias, float* __restrict__ C32,
    __half* __restrict__ C16,
    int M, int N, int Ktot, int Kin, int sLog, int conv, int relu,
    int halfOut, int transOut)
{
    constexpr int BM = MI * 32;
    constexpr int HA_HALVES = BM * H_STRIDE;
    constexpr int STAGE_BYTES = (HA_HALVES + HB_HALVES) * 2;

    extern __shared__ char sm[];
    const uint32_t sbase = smem_u32(sm);

    const int tid  = threadIdx.x;
    const int warp = tid >> 5, lane = tid & 31;
    const int gid  = lane >> 2, tid4 = lane & 3;
    const int wm   = warp & 1,  wn   = warp >> 1;
    const int bm   = blockIdx.y * BM;
    const int bn   = blockIdx.x * 128;
    const int S    = 1 << sLog;
    const int nst  = Ktot / 32;

    const int lrow = lane & 7;
    const int lsel = lane >> 3;
    const int rowOffA = (lsel & 1) * 8;
    const int colOffA = (lsel >> 1) * 8;
    const int rowOffB = (lsel >> 1) * 8;
    const int colOffB = (lsel & 1) * 8;

    float acc[MI][4][4];
#pragma unroll
    for (int i = 0; i < MI; i++)
#pragma unroll
        for (int j = 0; j < 4; j++)
#pragma unroll
            for (int r = 0; r < 4; r++) acc[i][j][r] = 0.f;

    auto issue_stage = [&](int stg) {
        const int k0    = stg * 32;
        const int tap   = conv ? (k0 / Kin) : 0;
        const int kcol  = k0 - tap * Kin;
        const int shift = conv ? (tap - 1) : 0;
        const uint32_t aB = sbase + (stg % 3) * STAGE_BYTES;
        const uint32_t bB = aB + HA_HALVES * 2;
#pragma unroll
        for (int i = 0; i < BM / 64; i++) {
            int flat = tid + i * 256;
            int row = flat >> 2, cq = flat & 3;
            int gm = bm + row;
            int b = gm >> sLog, l = gm & (S - 1);
            int src = l + shift;
            uint32_t sz = (src >= 0 && src < S) ? 16u : 0u;
            int srcc = (src >= 0 && src < S) ? src : 0;
            const __half* gp = A + (size_t)(((size_t)b << sLog) + srcc) * Kin + kcol + cq * 8;
            CP16(aB + (row * H_STRIDE + cq * 8) * 2, gp, sz);
        }
#pragma unroll
        for (int i = 0; i < 2; i++) {
            int flat = tid + i * 256;
            int nr = flat >> 2, cq = flat & 3;
            int gn = bn + nr;
            uint32_t sz = (gn < N) ? 16u : 0u;
            int gnc = (gn < N) ? gn : (N - 1);
            const __half* gp = WT + (size_t)gnc * Ktot + k0 + cq * 8;
            CP16(bB + (nr * H_STRIDE + cq * 8) * 2, gp, sz);
        }
    };

    auto compute = [&](int stg) {
        const uint32_t aB = sbase + (stg % 3) * STAGE_BYTES;
        const uint32_t bB = aB + HA_HALVES * 2;
#pragma unroll
        for (int c = 0; c < 2; c++) {
            uint32_t af[MI][4];
#pragma unroll
            for (int mi = 0; mi < MI; mi++) {
                uint32_t ap = aB + ((wm * (MI*16) + mi * 16 + lrow + rowOffA) * H_STRIDE
                                    + c * 16 + colOffA) * 2;
                LDM_X4(af[mi][0], af[mi][1], af[mi][2], af[mi][3], ap);
            }
            uint32_t bf[4][2];
#pragma unroll
            for (int njp = 0; njp < 2; njp++) {
                uint32_t bp = bB + ((wn * 32 + njp * 16 + lrow + rowOffB) * H_STRIDE
                                    + c * 16 + colOffB) * 2;
                uint32_t r0, r1, r2, r3;
                LDM_X4(r0, r1, r2, r3, bp);
                bf[njp * 2][0]     = r0;
                bf[njp * 2][1]     = r1;
                bf[njp * 2 + 1][0] = r2;
                bf[njp * 2 + 1][1] = r3;
            }
#pragma unroll
            for (int mi = 0; mi < MI; mi++)
#pragma unroll
                for (int nj = 0; nj < 4; nj++)
                    MMA_F16(acc[mi][nj], af[mi][0], af[mi][1], af[mi][2], af[mi][3],
                            bf[nj][0], bf[nj][1]);
        }
    };

    issue_stage(0); CP_COMMIT();
    issue_stage(1); CP_COMMIT();
    for (int s = 0; s < nst; s++) {
        CP_WAIT1();
        __syncthreads();
        if (s + 2 < nst) issue_stage(s + 2);
        CP_COMMIT();
        compute(s);
    }

#pragma unroll
    for (int mi = 0; mi < MI; mi++) {
        int gm0 = bm + wm * (MI*16) + mi * 16 + gid;
#pragma unroll
        for (int nj = 0; nj < 4; nj++) {
            int gn = bn + wn * 32 + nj * 8 + tid4 * 2;
            float b0 = (gn < N) ? bias[gn] : 0.f;
            float b1 = (gn + 1 < N) ? bias[gn + 1] : 0.f;
            float v00 = acc[mi][nj][0] + b0;
            float v01 = acc[mi][nj][1] + b1;
            float v10 = acc[mi][nj][2] + b0;
            float v11 = acc[mi][nj][3] + b1;
            if (relu) {
                v00 = fmaxf(v00, 0.f); v01 = fmaxf(v01, 0.f);
                v10 = fmaxf(v10, 0.f); v11 = fmaxf(v11, 0.f);
            }
            if (transOut) {
                int b0i = gm0 >> sLog, f0 = gm0 & (S - 1);
                int b1i = (gm0 + 8) >> sLog, f1 = (gm0 + 8) & (S - 1);
                if (gn < N) {
                    C32[((size_t)b0i * N + gn) * S + f0] = v00;
                    C32[((size_t)b1i * N + gn) * S + f1] = v10;
                }
                if (gn + 1 < N) {
                    C32[((size_t)b0i * N + gn + 1) * S + f0] = v01;
                    C32[((size_t)b1i * N + gn + 1) * S + f1] = v11;
                }
            } else if (halfOut) {
                *(__half2*)&C16[(size_t)gm0 * N + gn]       = __floats2half2_rn(v00, v01);
                *(__half2*)&C16[(size_t)(gm0 + 8) * N + gn] = __floats2half2_rn(v10, v11);
            } else {
                C32[(size_t)gm0 * N + gn]           = v00;
                C32[(size_t)gm0 * N + gn + 1]       = v01;
                C32[(size_t)(gm0 + 8) * N + gn]     = v10;
                C32[(size_t)(gm0 + 8) * N + gn + 1] = v11;
            }
        }
    }
}

#define H_SMEM_128 (((128*H_STRIDE) + HB_HALVES) * 2 * 3)   // 61440
#define H_SMEM_64  ((( 64*H_STRIDE) + HB_HALVES) * 2 * 3)   // 46080

// ============== fused flash attention (full fp16 mma path) ==============
// smem: Ss fp32 128x68 (softmax scratch), mrow/lrow/arow, then fp16 tiles:
// Qh 128x72, Kh 64x72, Vt (dim-major) 64x72, Ph 128x72.
#define FA_SPAD 68
#define FA_HPAD 72
#define FA_F32_FLOATS (128*FA_SPAD + 3*128)                  // 9088
#define FA_SMEM_BYTES (FA_F32_FLOATS*4 + (128+64+64+128)*FA_HPAD*2)  // 91648

__global__ __launch_bounds__(256) void flash_attn(const __half* __restrict__ qkv,
                                                  const float* __restrict__ am,
                                                  __half* __restrict__ ctx, int S)
{
    extern __shared__ float smf[];
    float* Ss   = smf;
    float* mrow = Ss + 128*FA_SPAD;
    float* lrow = mrow + 128;
    float* arow = lrow + 128;
    __half* Qh = (__half*)(arow + 128);
    __half* Kh = Qh + 128*FA_HPAD;
    __half* Vt = Kh + 64*FA_HPAD;
    __half* Ph = Vt + 64*FA_HPAD;

    const uint32_t qhA = smem_u32(Qh);
    const uint32_t khA = smem_u32(Kh);
    const uint32_t vtA = smem_u32(Vt);
    const uint32_t phA = smem_u32(Ph);

    const int tid  = threadIdx.x;
    const int warp = tid >> 5, lane = tid & 31;
    const int gid  = lane >> 2, tid4 = lane & 3;
    const int wm   = warp & 3, wn = warp >> 2;   // 4 m-warps x 2 n-warps
    const int bh   = blockIdx.y;
    const int b    = bh >> 3, h = bh & 7;
    const int q0   = blockIdx.x * 128;
    const float* amb = am + b * S;
    const __half* qb = qkv + (size_t)(b * S) * 1536 + h * 64;

    const int lrw  = lane & 7;
    const int lsel = lane >> 3;
    const int rowOffA = (lsel & 1) * 8;
    const int colOffA = (lsel >> 1) * 8;
    const int rowOffB = (lsel >> 1) * 8;
    const int colOffB = (lsel & 1) * 8;

    // Q tile: plain fp16 copy, 128 rows x 8 chunks
#pragma unroll
    for (int i = 0; i < 4; i++) {
        int idx = tid + i * 256;
        int r = idx >> 3, c8 = idx & 7;
        *(uint4*)&Qh[r * FA_HPAD + c8 * 8] =
            *(const uint4*)&qb[(size_t)(q0 + r) * 1536 + c8 * 8];
    }
    if (tid < 128) { mrow[tid] = -INFINITY; lrow[tid] = 0.f; }

    float oacc[2][4][4];
#pragma unroll
    for (int mi = 0; mi < 2; mi++)
#pragma unroll
        for (int nj = 0; nj < 4; nj++)
#pragma unroll
            for (int r = 0; r < 4; r++) oacc[mi][nj][r] = 0.f;

    const int nkt = S >> 6;
    for (int kt = 0; kt < nkt; kt++) {
        const int k0 = kt * 64;
        __syncthreads();
        // K tile copy + V transposed store (dim-major)
#pragma unroll
        for (int i = 0; i < 2; i++) {
            int idx = tid + i * 256;
            int r = idx >> 3, c8 = idx & 7;
            const __half* src = &qb[(size_t)(k0 + r) * 1536];
            *(uint4*)&Kh[r * FA_HPAD + c8 * 8] = *(const uint4*)&src[512 + c8 * 8];
            uint4 v = *(const uint4*)&src[1024 + c8 * 8];
            const __half* vh = (const __half*)&v;
#pragma unroll
            for (int j = 0; j < 8; j++)
                Vt[(c8 * 8 + j) * FA_HPAD + r] = vh[j];
        }
        __syncthreads();

        // ---- S = Q @ K^T (fp16 mma) ----
        float sacc[2][4][4];
#pragma unroll
        for (int mi = 0; mi < 2; mi++)
#pragma unroll
            for (int nj = 0; nj < 4; nj++)
#pragma unroll
                for (int r = 0; r < 4; r++) sacc[mi][nj][r] = 0.f;
#pragma unroll
        for (int kc = 0; kc < 4; kc++) {
            uint32_t af[2][4];
#pragma unroll
            for (int mi = 0; mi < 2; mi++) {
                uint32_t ap = qhA + ((wm * 32 + mi * 16 + lrw + rowOffA) * FA_HPAD
                                     + kc * 16 + colOffA) * 2;
                LDM_X4(af[mi][0], af[mi][1], af[mi][2], af[mi][3], ap);
            }
            uint32_t bf[4][2];
#pragma unroll
            for (int njp = 0; njp < 2; njp++) {
                uint32_t bp = khA + ((wn * 32 + njp * 16 + lrw + rowOffB) * FA_HPAD
                                     + kc * 16 + colOffB) * 2;
                uint32_t r0, r1, r2, r3;
                LDM_X4(r0, r1, r2, r3, bp);
                bf[njp * 2][0]     = r0;
                bf[njp * 2][1]     = r1;
                bf[njp * 2 + 1][0] = r2;
                bf[njp * 2 + 1][1] = r3;
            }
#pragma unroll
            for (int mi = 0; mi < 2; mi++)
#pragma unroll
                for (int nj = 0; nj < 4; nj++)
                    MMA_F16(sacc[mi][nj], af[mi][0], af[mi][1], af[mi][2], af[mi][3],
                            bf[nj][0], bf[nj][1]);
        }
        // scores -> Ss (fp32, scale + mask)
#pragma unroll
        for (int mi = 0; mi < 2; mi++) {
            int r = wm * 32 + mi * 16 + gid;
#pragma unroll
            for (int nj = 0; nj < 4; nj++) {
                int c = wn * 32 + nj * 8 + tid4 * 2;
                float am0 = amb[k0 + c], am1 = amb[k0 + c + 1];
                Ss[r * FA_SPAD + c]           = sacc[mi][nj][0] * 0.125f + am0;
                Ss[r * FA_SPAD + c + 1]       = sacc[mi][nj][1] * 0.125f + am1;
                Ss[(r + 8) * FA_SPAD + c]     = sacc[mi][nj][2] * 0.125f + am0;
                Ss[(r + 8) * FA_SPAD + c + 1] = sacc[mi][nj][3] * 0.125f + am1;
            }
        }
        __syncthreads();
        // online softmax (2 threads per row), write P in fp16
        {
            int r = tid >> 1, hf = tid & 1;
            float* srow = Ss + r * FA_SPAD + hf * 32;
            __half* prow = Ph + r * FA_HPAD + hf * 32;
            float mx = -INFINITY;
#pragma unroll 8
            for (int j = 0; j < 32; j++) mx = fmaxf(mx, srow[j]);
            mx = fmaxf(mx, __shfl_xor_sync(0xffffffffu, mx, 1));
            float mold = mrow[r];
            float mnew = fmaxf(mold, mx);
            float sum = 0.f;
#pragma unroll 8
            for (int j = 0; j < 32; j++) {
                float pv = __expf(srow[j] - mnew);
                prow[j] = __float2half_rn(pv);
                sum += pv;
            }
            sum += __shfl_xor_sync(0xffffffffu, sum, 1);
            if (hf == 0) {
                float alpha = __expf(mold - mnew);
                lrow[r] = lrow[r] * alpha + sum;
                mrow[r] = mnew;
                arow[r] = alpha;
            }
        }
        __syncthreads();

        // rescale O, then O += P @ V (fp16 mma; B from Vt dim-major)
        float al[2][2];
#pragma unroll
        for (int mi = 0; mi < 2; mi++) {
            int r = wm * 32 + mi * 16 + gid;
            al[mi][0] = arow[r];
            al[mi][1] = arow[r + 8];
        }
#pragma unroll
        for (int mi = 0; mi < 2; mi++)
#pragma unroll
            for (int nj = 0; nj < 4; nj++) {
                oacc[mi][nj][0] *= al[mi][0];
                oacc[mi][nj][1] *= al[mi][0];
                oacc[mi][nj][2] *= al[mi][1];
                oacc[mi][nj][3] *= al[mi][1];
            }
#pragma unroll
        for (int kc = 0; kc < 4; kc++) {
            uint32_t af[2][4];
#pragma unroll
            for (int mi = 0; mi < 2; mi++) {
                uint32_t ap = phA + ((wm * 32 + mi * 16 + lrw + rowOffA) * FA_HPAD
                                     + kc * 16 + colOffA) * 2;
                LDM_X4(af[mi][0], af[mi][1], af[mi][2], af[mi][3], ap);
            }
            uint32_t bf[4][2];
#pragma unroll
            for (int njp = 0; njp < 2; njp++) {
                uint32_t bp = vtA + ((wn * 32 + njp * 16 + lrw + rowOffB) * FA_HPAD
                                     + kc * 16 + colOffB) * 2;
                uint32_t r0, r1, r2, r3;
                LDM_X4(r0, r1, r2, r3, bp);
                bf[njp * 2][0]     = r0;
                bf[njp * 2][1]     = r1;
                bf[njp * 2 + 1][0] = r2;
                bf[njp * 2 + 1][1] = r3;
            }
#pragma unroll
            for (int mi = 0; mi < 2; mi++)
#pragma unroll
                for (int nj = 0; nj < 4; nj++)
                    MMA_F16(oacc[mi][nj], af[mi][0], af[mi][1], af[mi][2], af[mi][3],
                            bf[nj][0], bf[nj][1]);
        }
    }
#pragma unroll
    for (int mi = 0; mi < 2; mi++) {
        int r = wm * 32 + mi * 16 + gid;
        float inv0 = 1.f / lrow[r];
        float inv1 = 1.f / lrow[r + 8];
#pragma unroll
        for (int nj = 0; nj < 4; nj++) {
            int c = wn * 32 + nj * 8 + tid4 * 2;
            __half2* o0 = (__half2*)&ctx[(size_t)(b * S + q0 + r) * DD + h * 64 + c];
            __half2* o1 = (__half2*)&ctx[(size_t)(b * S + q0 + r + 8) * DD + h * 64 + c];
            *o0 = __floats2half2_rn(oacc[mi][nj][0] * inv0, oacc[mi][nj][1] * inv0);
            *o1 = __floats2half2_rn(oacc[mi][nj][2] * inv1, oacc[mi][nj][3] * inv1);
        }
    }
}

// ---------------- embed + positional (reference adds pos[b], not pos[t]) ----
__global__ __launch_bounds__(256) void embed_kernel(const int* __restrict__ tokens,
                                                    const float* __restrict__ emb,
                                                    float* __restrict__ x,
                                                    __half* __restrict__ xh)
{
    int i = blockIdx.x * 256 + threadIdx.x;
    if (i >= BB*TT*DD) return;
    int d  = i & (DD-1);
    int bt = i / DD;
    int b  = bt / TT;
    int tok = tokens[bt];
    int half = d >> 1;
    float den = __expf(-(float)(2*half) * (logf(10000.f) / (float)DD));
    float ang = (float)b * den;
    float posv = (d & 1) ? cosf(ang) : sinf(ang);
    float v = 2.f * emb[(size_t)tok*DD + d] + posv;
    x[i] = v;
    xh[i] = __float2half_rn(v);
}

__global__ __launch_bounds__(256) void mask_kernel(const int* __restrict__ lens,
                                                   float* __restrict__ am, int S)
{
    int i = blockIdx.x*256 + threadIdx.x;
    if (i >= BB*S) return;
    int b = i / S, t = i % S;
    am[i] = (t > lens[b]) ? -INFINITY : 0.f;
}

__global__ __launch_bounds__(256) void add_ln_kernel(const float* __restrict__ resid,
                                                     const float* __restrict__ delta,
                                                     const float* __restrict__ g,
                                                     const float* __restrict__ bb,
                                                     float* __restrict__ out,
                                                     __half* __restrict__ outh)
{
    size_t row = blockIdx.x;
    int t = threadIdx.x;
    __shared__ float red[256];
    float v0 = resid[row*DD + t]       + delta[row*DD + t];
    float v1 = resid[row*DD + t + 256] + delta[row*DD + t + 256];
    red[t] = v0 + v1; __syncthreads();
    for (int s = 128; s > 0; s >>= 1) { if (t < s) red[t] += red[t+s]; __syncthreads(); }
    float mean = red[0] * (1.f/DD);
    __syncthreads();
    float d0 = v0 - mean, d1 = v1 - mean;
    red[t] = d0*d0 + d1*d1; __syncthreads();
    for (int s = 128; s > 0; s >>= 1) { if (t < s) red[t] += red[t+s]; __syncthreads(); }
    float var = red[0] * (1.f/DD);
    float sc = rsqrtf(var + 1e-5f);
    float o0 = d0*sc*g[t]     + bb[t];
    float o1 = d1*sc*g[t+256] + bb[t+256];
    out[row*DD + t]        = o0;
    out[row*DD + t + 256]  = o1;
    outh[row*DD + t]       = __float2half_rn(o0);
    outh[row*DD + t + 256] = __float2half_rn(o1);
}

__global__ void cumsum_kernel(const int* __restrict__ dur, int* __restrict__ cums)
{
    int b = blockIdx.x;
    if (threadIdx.x == 0) {
        int s = 0;
        for (int t = 0; t < TT; t++) { s += dur[b*TT + t]; cums[b*TT + t] = s; }
    }
}

__global__ __launch_bounds__(256) void regulate_kernel(const float* __restrict__ enc,
                                                       const int* __restrict__ cums,
                                                       const int* __restrict__ mellen,
                                                       float* __restrict__ dec_in,
                                                       __half* __restrict__ dec_inh)
{
    int bf = blockIdx.x;
    int b = bf / MELN, f = bf % MELN;
    const int* c = cums + b*TT;
    int lo = 0, hi = TT;
    while (lo < hi) { int mid = (lo + hi) >> 1; if (c[mid] <= f) lo = mid + 1; else hi = mid; }
    int idx = lo; if (idx > TT-1) idx = TT-1;
    float keep = (f <= mellen[b]) ? 1.f : 0.f;
    for (int d = threadIdx.x; d < DD; d += 256) {
        float v = enc[(size_t)(b*TT + idx)*DD + d] * keep;
        dec_in[(size_t)bf*DD + d]  = v;
        dec_inh[(size_t)bf*DD + d] = __float2half_rn(v);
    }
}

// =============================== host side ===============================
struct Ptrs {
    float *x, *ctx, *t1, *h2, *enc, *am, *am2;
    __half *xh, *qkvh, *ctxh, *hh, *wh, *whOut;
    int *cums;
};

static void get_ptrs(Ptrs& p)
{
    cudaGetSymbolAddress((void**)&p.x,     g_x);
    cudaGetSymbolAddress((void**)&p.xh,    g_xh);
    cudaGetSymbolAddress((void**)&p.qkvh,  g_qkvh);
    cudaGetSymbolAddress((void**)&p.ctx,   g_ctx);
    cudaGetSymbolAddress((void**)&p.ctxh,  g_ctxh);
    cudaGetSymbolAddress((void**)&p.t1,    g_t1);
    cudaGetSymbolAddress((void**)&p.hh,    g_hh);
    cudaGetSymbolAddress((void**)&p.h2,    g_h2);
    cudaGetSymbolAddress((void**)&p.enc,   g_enc);
    cudaGetSymbolAddress((void**)&p.am,    g_am);
    cudaGetSymbolAddress((void**)&p.am2,   g_am2);
    cudaGetSymbolAddress((void**)&p.wh,    g_wh);
    cudaGetSymbolAddress((void**)&p.whOut, g_whOut);
    cudaGetSymbolAddress((void**)&p.cums,  g_cums);
}

static void run_layer(Ptrs& p, int S, int sLog, const float* am, const __half* whl,
                      const float* bqkv, const float* bo,
                      const float* ln1g, const float* ln1b,
                      const float* c1b,  const float* c2b,
                      const float* ln2g, const float* ln2b)
{
    const int M = BB * S;
    const bool small = (S == TT);   // encoder: use 64-row tiles for narrow GEMMs

    if (small)
        gemm_h<2><<<dim3(12, M/64), 256, H_SMEM_64>>>(p.xh, whl + WT_QKV, bqkv,
                                                      nullptr, p.qkvh,
                                                      M, 3*DD, DD, DD, sLog, 0, 0, 1, 0);
    else
        gemm_h<4><<<dim3(12, M/128), 256, H_SMEM_128>>>(p.xh, whl + WT_QKV, bqkv,
                                                        nullptr, p.qkvh,
                                                        M, 3*DD, DD, DD, sLog, 0, 0, 1, 0);

    flash_attn<<<dim3(S/128, BB*HH), 256, FA_SMEM_BYTES>>>(p.qkvh, am, p.ctxh, S);

    if (small)
        gemm_h<2><<<dim3(4, M/64), 256, H_SMEM_64>>>(p.ctxh, whl + WT_WO, bo,
                                                     p.t1, nullptr,
                                                     M, DD, DD, DD, sLog, 0, 0, 0, 0);
    else
        gemm_h<4><<<dim3(4, M/128), 256, H_SMEM_128>>>(p.ctxh, whl + WT_WO, bo,
                                                       p.t1, nullptr,
                                                       M, DD, DD, DD, sLog, 0, 0, 0, 0);

    add_ln_kernel<<<M, 256>>>(p.x, p.t1, ln1g, ln1b, p.ctx, p.xh);

    gemm_h<4><<<dim3(16, M/128), 256, H_SMEM_128>>>(p.xh, whl + WT_C1, c1b,
                                                    nullptr, p.hh,
                                                    M, INTERN, 3*DD, DD, sLog, 1, 1, 1, 0);
    if (small)
        gemm_h<2><<<dim3(4, M/64), 256, H_SMEM_64>>>(p.hh, whl + WT_C2, c2b,
                                                     p.h2, nullptr,
                                                     M, DD, 3*INTERN, INTERN, sLog, 1, 0, 0, 0);
    else
        gemm_h<4><<<dim3(4, M/128), 256, H_SMEM_128>>>(p.hh, whl + WT_C2, c2b,
                                                       p.h2, nullptr,
                                                       M, DD, 3*INTERN, INTERN, sLog, 1, 0, 0, 0);

    add_ln_kernel<<<M, 256>>>(p.ctx, p.h2, ln2g, ln2b, p.x, p.xh);
}

extern "C" void kernel_launch(void* const* d_in, const int* in_sizes, int n_in,
                              void* d_out, int out_size)
{
    const int*   tokens        = (const int*)  d_in[0];
    const int*   token_lengths = (const int*)  d_in[1];
    const int*   melspec_len   = (const int*)  d_in[2];
    const int*   durations     = (const int*)  d_in[3];
    const float* emb           = (const float*)d_in[5];
    const float* ew[12]; for (int i = 0; i < 12; i++) ew[i] = (const float*)d_in[6 + i];
    const float* dw[12]; for (int i = 0; i < 12; i++) dw[i] = (const float*)d_in[18 + i];
    const float* out_w         = (const float*)d_in[30];
    const float* out_b         = (const float*)d_in[31];

    cudaFuncSetAttribute(flash_attn, cudaFuncAttributeMaxDynamicSharedMemorySize,
                         FA_SMEM_BYTES);
    cudaFuncSetAttribute(gemm_h<4>, cudaFuncAttributeMaxDynamicSharedMemorySize,
                         H_SMEM_128);
    cudaFuncSetAttribute(gemm_h<2>, cudaFuncAttributeMaxDynamicSharedMemorySize,
                         H_SMEM_64);

    Ptrs p; get_ptrs(p);

    // ---- weight transpose + fp16 convert (batched: blockIdx.z = layer) ----
    for (int half = 0; half < 2; half++) {
        const float* const* w = (half == 0) ? ew : dw;
        __half* whb = p.wh + (size_t)half * LLAY * WT_LAYER;
        transpose_wh<<<dim3(16, 48, LLAY), 256>>>(w[0], whb + WT_QKV, DD, 3*DD,
                                                  (size_t)DD*3*DD, WT_LAYER);
        transpose_wh<<<dim3(16, 16, LLAY), 256>>>(w[2], whb + WT_WO, DD, DD,
                                                  (size_t)DD*DD, WT_LAYER);
        transpose_wh<<<dim3(48, 64, LLAY), 256>>>(w[6], whb + WT_C1, 3*DD, INTERN,
                                                  (size_t)3*DD*INTERN, WT_LAYER);
        transpose_wh<<<dim3(192, 16, LLAY), 256>>>(w[8], whb + WT_C2, 3*INTERN, DD,
                                                   (size_t)3*INTERN*DD, WT_LAYER);
    }
    transpose_wh<<<dim3(16, 3, 1), 256>>>(out_w, p.whOut, DD, OUTC, 0, 0);

    // ---- embed + positional + encoder mask ----
    embed_kernel<<<(BB*TT*DD + 255)/256, 256>>>(tokens, emb, p.x, p.xh);
    mask_kernel<<<(BB*TT + 255)/256, 256>>>(token_lengths, p.am, TT);

    // ---- encoder stack (S = TT) ----
    for (int l = 0; l < LLAY; l++) {
        run_layer(p, TT, 8, p.am, p.wh + (size_t)l * WT_LAYER,
                  ew[1] + (size_t)l*3*DD,  ew[3] + (size_t)l*DD,
                  ew[4] + (size_t)l*DD,    ew[5] + (size_t)l*DD,
                  ew[7] + (size_t)l*INTERN, ew[9] + (size_t)l*DD,
                  ew[10] + (size_t)l*DD,   ew[11] + (size_t)l*DD);
    }

    // ---- length regulator ----
    cudaMemcpyAsync(p.enc, p.x, (size_t)BB*TT*DD*sizeof(float), cudaMemcpyDeviceToDevice);
    cumsum_kernel<<<BB, 32>>>(durations, p.cums);
    regulate_kernel<<<BB*MELN, 256>>>(p.enc, p.cums, melspec_len, p.x, p.xh);
    mask_kernel<<<(BB*MELN + 255)/256, 256>>>(melspec_len, p.am2, MELN);

    // ---- decoder stack (S = MELN) ----
    for (int l = 0; l < LLAY; l++) {
        run_layer(p, MELN, 10, p.am2, p.wh + (size_t)(LLAY + l) * WT_LAYER,
                  dw[1] + (size_t)l*3*DD,  dw[3] + (size_t)l*DD,
                  dw[4] + (size_t)l*DD,    dw[5] + (size_t)l*DD,
                  dw[7] + (size_t)l*INTERN, dw[9] + (size_t)l*DD,
                  dw[10] + (size_t)l*DD,   dw[11] + (size_t)l*DD);
    }

    // ---- output projection fused with transpose: writes (b, o, f) ----
    gemm_h<2><<<dim3(1, BB*MELN/64), 256, H_SMEM_64>>>(p.xh, p.whOut, out_b,
                                                       (float*)d_out, nullptr,
                                                       BB*MELN, OUTC, DD, DD, 10,
                                                       0, 0, 0, 1);
}